// round 12
// baseline (speedup 1.0000x reference)
#include <cuda_runtime.h>
#include <cuda_bf16.h>
#include <math.h>
#include <stdint.h>

// Problem constants
#define NLAYER 6
#define NHEAD  16
#define DMODEL 1024
#define DHEAD  64
#define DFF    4096
#define BATCH  4
#define SEQ    1024
#define MROWS  (BATCH*SEQ)
#define NEG_INF_F (-100000000.0f)

// ---------------------------------------------------------------------------
// Scratch (static device globals; no allocation anywhere)
// ---------------------------------------------------------------------------
__device__ float g_x[MROWS*DMODEL];
__device__ float g_y[MROWS*DMODEL];
__device__ __nv_bfloat16 g_xhi[MROWS*DMODEL], g_xlo[MROWS*DMODEL];
__device__ __nv_bfloat16 g_qhi[MROWS*DMODEL], g_qlo[MROWS*DMODEL];
__device__ __nv_bfloat16 g_khi[MROWS*DMODEL], g_klo[MROWS*DMODEL];
__device__ __nv_bfloat16 g_vhi[MROWS*DMODEL], g_vlo[MROWS*DMODEL];
__device__ __nv_bfloat16 g_ohi[MROWS*DMODEL], g_olo[MROWS*DMODEL];
__device__ __nv_bfloat16 g_hhi[MROWS*DFF],    g_hlo[MROWS*DFF];
__device__ __nv_bfloat16 g_wqkv_hi[3*DMODEL*DMODEL], g_wqkv_lo[3*DMODEL*DMODEL];
__device__ __nv_bfloat16 g_wo_hi[DMODEL*DMODEL],     g_wo_lo[DMODEL*DMODEL];
__device__ __nv_bfloat16 g_w1_hi[DMODEL*DFF],        g_w1_lo[DMODEL*DFF];
__device__ __nv_bfloat16 g_w2_hi[DFF*DMODEL],        g_w2_lo[DFF*DMODEL];

// ---------------------------------------------------------------------------
// PTX helpers
// ---------------------------------------------------------------------------
__device__ __forceinline__ uint32_t smem_u32(const void* p) {
    uint32_t a;
    asm("{ .reg .u64 t; cvta.to.shared.u64 t, %1; cvt.u32.u64 %0, t; }" : "=r"(a) : "l"(p));
    return a;
}
__device__ __forceinline__ void cp_async16(uint32_t dst, const void* src) {
    asm volatile("cp.async.cg.shared.global [%0], [%1], 16;" :: "r"(dst), "l"(src) : "memory");
}
#define CP_COMMIT() asm volatile("cp.async.commit_group;" ::: "memory")

__device__ __forceinline__ void ldsm_x4(uint32_t& r0, uint32_t& r1, uint32_t& r2,
                                        uint32_t& r3, uint32_t addr) {
    asm volatile("ldmatrix.sync.aligned.m8n8.x4.shared.b16 {%0,%1,%2,%3}, [%4];"
                 : "=r"(r0), "=r"(r1), "=r"(r2), "=r"(r3) : "r"(addr));
}
__device__ __forceinline__ void ldsm_x4_t(uint32_t& r0, uint32_t& r1, uint32_t& r2,
                                          uint32_t& r3, uint32_t addr) {
    asm volatile("ldmatrix.sync.aligned.m8n8.x4.trans.shared.b16 {%0,%1,%2,%3}, [%4];"
                 : "=r"(r0), "=r"(r1), "=r"(r2), "=r"(r3) : "r"(addr));
}
__device__ __forceinline__ void mma_bf16(float* c, const uint32_t* a, const uint32_t* b) {
    asm volatile(
        "mma.sync.aligned.m16n8k16.row.col.f32.bf16.bf16.f32 "
        "{%0,%1,%2,%3}, {%4,%5,%6,%7}, {%8,%9}, {%0,%1,%2,%3};"
        : "+f"(c[0]), "+f"(c[1]), "+f"(c[2]), "+f"(c[3])
        : "r"(a[0]), "r"(a[1]), "r"(a[2]), "r"(a[3]), "r"(b[0]), "r"(b[1]));
}
__device__ __forceinline__ void pack_split(float x, float y, uint32_t& hi, uint32_t& lo) {
    __nv_bfloat16 hx = __float2bfloat16(x), hy = __float2bfloat16(y);
    __nv_bfloat162 H; H.x = hx; H.y = hy;
    __nv_bfloat162 L;
    L.x = __float2bfloat16(x - __bfloat162float(hx));
    L.y = __float2bfloat16(y - __bfloat162float(hy));
    hi = *(uint32_t*)&H; lo = *(uint32_t*)&L;
}

// Swizzle for 64B-row tiles (GEMM: 32 bf16/row)
__device__ __forceinline__ uint32_t swz(int row, int c) {
    return (uint32_t)(((row >> 1) << 7) |
                      ((((((row & 1) << 2) | c)) ^ ((row >> 1) & 7)) << 4));
}
// Swizzle for 128B-row tiles (attention: 64 bf16/row)
__device__ __forceinline__ uint32_t swz128(int row, int c) {
    return (uint32_t)((row << 7) | (((c ^ (row & 7))) << 4));
}

// GEMM smem geometry: 128x128 tile, BK=32, TRIPLE buffered, 2 CTAs/SM
#define T_TILE 8192
#define STAGEB (4*T_TILE)
#define GSMEM  (3*STAGEB)            // 98304 (x2 CTAs = 192KB/SM)

// Attention smem
#define AQ_TILE 16384
#define AKV_STAGE 32768
#define ATTN_SMEM (2*AQ_TILE + 2*AKV_STAGE + 512)

// ---------------------------------------------------------------------------
// Positional encoding (fp64) + fused bf16 split of the result
// ---------------------------------------------------------------------------
__global__ void posenc_kernel(const float* __restrict__ x, float* __restrict__ out,
                              __nv_bfloat16* __restrict__ ohi,
                              __nv_bfloat16* __restrict__ olo)
{
    int idx = blockIdx.x * blockDim.x + threadIdx.x;
    if (idx >= SEQ * DMODEL) return;
    int d = idx & (DMODEL - 1);
    int s = idx >> 10;
    int t = (d < DMODEL/2) ? d : d - DMODEL/2;
    const double log_inc = log(10000.0) / (double)(DMODEL/2 - 1);
    double arg = (double)s * exp(-(double)t * log_inc);
    float sig = (float)((d < DMODEL/2) ? sin(arg) : cos(arg));
#pragma unroll
    for (int b = 0; b < BATCH; ++b) {
        size_t off = (size_t)b * SEQ * DMODEL + idx;
        float v = x[off] + sig;
        out[off] = v;
        __nv_bfloat16 h = __float2bfloat16(v);
        ohi[off] = h;
        olo[off] = __float2bfloat16(v - __bfloat162float(h));
    }
}

// ---------------------------------------------------------------------------
// W [K,N] fp32 -> transposed bf16 split: hiT, loT [N,K]
// ---------------------------------------------------------------------------
__global__ __launch_bounds__(256) void split_wT_kernel(
    const float* __restrict__ W, __nv_bfloat16* __restrict__ hiT,
    __nv_bfloat16* __restrict__ loT, int K, int N)
{
    __shared__ float t[32][33];
    int nx = blockIdx.x * 32;
    int ky = blockIdx.y * 32;
    int tx = threadIdx.x, ty = threadIdx.y;   // (32, 8)
#pragma unroll
    for (int i = 0; i < 4; ++i)
        t[ty + 8*i][tx] = W[(size_t)(ky + ty + 8*i) * N + nx + tx];
    __syncthreads();
#pragma unroll
    for (int i = 0; i < 4; ++i) {
        float v = t[tx][ty + 8*i];
        __nv_bfloat16 h = __float2bfloat16(v);
        size_t o = (size_t)(nx + ty + 8*i) * K + ky + tx;
        hiT[o] = h;
        loT[o] = __float2bfloat16(v - __bfloat162float(h));
    }
}

// --- chunk loader: 4 tiles (Ahi,Alo,Bhi,Blo) x 512 16B chunks / 256 thr = 8 ---
#define LOAD_CHUNK(k0, buf)                                                     \
    {                                                                           \
        _Pragma("unroll")                                                       \
        for (int i = 0; i < 8; ++i) {                                           \
            int t = tid + i * 256;                                              \
            int tile = t >> 9;                                                  \
            int w = t & 511;                                                    \
            int row = w >> 2;                                                   \
            int c = w & 3;                                                      \
            const __nv_bfloat16* src =                                          \
                (tile == 0) ? Ahi : (tile == 1) ? Alo : (tile == 2) ? Bhi : Blo;\
            int gr = ((tile < 2) ? m0 : n0) + row;                              \
            cp_async16((buf) + (uint32_t)tile * T_TILE + swz(row, c),           \
                       src + (size_t)gr * KDIM + (k0) + c * 8);                 \
        }                                                                       \
        CP_COMMIT();                                                            \
    }

// --- MMA body (3-pass, pass-major), 8 warps each 32x64 ---
#define MMA_BODY(buf)                                                            \
    {                                                                            \
        const uint32_t Ah = buf;                                                 \
        const uint32_t Al = buf + T_TILE;                                        \
        const uint32_t Bh = buf + 2 * T_TILE;                                    \
        const uint32_t Bl = buf + 3 * T_TILE;                                    \
        _Pragma("unroll")                                                        \
        for (int kk = 0; kk < 2; ++kk) {                                         \
            uint32_t ahi_f[2][4], alo_f[2][4];                                   \
            _Pragma("unroll")                                                    \
            for (int mi = 0; mi < 2; ++mi) {                                     \
                int r = a_r + mi * 16;                                           \
                uint32_t off = swz(r, kk * 2 + a_h);                             \
                ldsm_x4(ahi_f[mi][0], ahi_f[mi][1], ahi_f[mi][2], ahi_f[mi][3], Ah + off); \
                ldsm_x4(alo_f[mi][0], alo_f[mi][1], alo_f[mi][2], alo_f[mi][3], Al + off); \
            }                                                                    \
            uint32_t bf[8][2];                                                   \
            _Pragma("unroll")                                                    \
            for (int nt = 0; nt < 4; ++nt) {                                     \
                int r = b_r + nt * 16;                                           \
                uint32_t off = swz(r, kk * 2 + b_h);                             \
                uint32_t q0, q1, q2, q3;                                         \
                ldsm_x4(q0, q1, q2, q3, Bh + off);                               \
                bf[nt*2][0] = q0; bf[nt*2][1] = q1;                              \
                bf[nt*2+1][0] = q2; bf[nt*2+1][1] = q3;                          \
            }                                                                    \
            _Pragma("unroll")                                                    \
            for (int mi = 0; mi < 2; ++mi)                                       \
                _Pragma("unroll")                                                \
                for (int ni = 0; ni < 8; ++ni)                                   \
                    mma_bf16(acc[mi][ni], ahi_f[mi], bf[ni]);                    \
            _Pragma("unroll")                                                    \
            for (int mi = 0; mi < 2; ++mi)                                       \
                _Pragma("unroll")                                                \
                for (int ni = 0; ni < 8; ++ni)                                   \
                    mma_bf16(acc[mi][ni], alo_f[mi], bf[ni]);                    \
            _Pragma("unroll")                                                    \
            for (int nt = 0; nt < 4; ++nt) {                                     \
                int r = b_r + nt * 16;                                           \
                uint32_t off = swz(r, kk * 2 + b_h);                             \
                uint32_t q0, q1, q2, q3;                                         \
                ldsm_x4(q0, q1, q2, q3, Bl + off);                               \
                bf[nt*2][0] = q0; bf[nt*2][1] = q1;                              \
                bf[nt*2+1][0] = q2; bf[nt*2+1][1] = q3;                          \
            }                                                                    \
            _Pragma("unroll")                                                    \
            for (int mi = 0; mi < 2; ++mi)                                       \
                _Pragma("unroll")                                                \
                for (int ni = 0; ni < 8; ++ni)                                   \
                    mma_bf16(acc[mi][ni], ahi_f[mi], bf[ni]);                    \
        }                                                                        \
    }

// --- 3-stage K-loop: single barrier per iteration, compile-time nch,
//     unroll-3 so the %3 stage rotation is static in the unrolled bulk ---
#define K_LOOP()                                                                 \
    LOAD_CHUNK(0, sb);                                                           \
    LOAD_CHUNK(32, sb + STAGEB);                                                 \
    _Pragma("unroll 3")                                                          \
    for (int ch = 0; ch < nch; ++ch) {                                           \
        if (ch + 1 < nch) {                                                      \
            asm volatile("cp.async.wait_group 1;" ::: "memory");                 \
        } else {                                                                 \
            asm volatile("cp.async.wait_group 0;" ::: "memory");                 \
        }                                                                        \
        __syncthreads();                                                         \
        if (ch + 2 < nch) {                                                      \
            LOAD_CHUNK((ch + 2) * 32, sb + (uint32_t)((ch + 2) % 3) * STAGEB);   \
        }                                                                        \
        MMA_BODY(sb + (uint32_t)(ch % 3) * STAGEB)                               \
    }

// ---------------------------------------------------------------------------
// General HMMA bf16-split GEMM (Wo / FF1 / FF2): 128x128 tile, 256 thr, 2 CTA/SM
// KDIM is compile-time (1024 or 4096).
// ---------------------------------------------------------------------------
template<int KDIM>
__global__ __launch_bounds__(256, 2) void mma_gemm_kernel(
    const __nv_bfloat16* __restrict__ Ahi, const __nv_bfloat16* __restrict__ Alo,
    const __nv_bfloat16* __restrict__ Bhi, const __nv_bfloat16* __restrict__ Blo,
    const float* __restrict__ bias, float* __restrict__ C,
    __nv_bfloat16* __restrict__ Chi, __nv_bfloat16* __restrict__ Clo,
    int N, float alpha, int relu, int outmode)
{
    extern __shared__ char smem[];
    const uint32_t sb = smem_u32(smem);
    const int tid = threadIdx.x;
    const int wid = tid >> 5, lane = tid & 31;
    const int m0 = blockIdx.y * 128, n0 = blockIdx.x * 128;
    const int wm = (wid & 3) * 32;
    const int wn = (wid >> 2) * 64;

    float acc[2][8][4];
#pragma unroll
    for (int mi = 0; mi < 2; ++mi)
#pragma unroll
        for (int ni = 0; ni < 8; ++ni)
#pragma unroll
            for (int r = 0; r < 4; ++r) acc[mi][ni][r] = 0.0f;

    constexpr int nch = KDIM >> 5;
    const int a_r = wm + (lane & 15);
    const int a_h = lane >> 4;
    const int b_r = wn + ((lane >> 4) << 3) + (lane & 7);
    const int b_h = (lane >> 3) & 1;

    K_LOOP()

    const int grp = lane >> 2, qid = lane & 3;
#pragma unroll
    for (int mi = 0; mi < 2; ++mi) {
        const int row0 = m0 + wm + mi * 16 + grp;
#pragma unroll
        for (int ni = 0; ni < 8; ++ni) {
            const int col = n0 + wn + ni * 8 + qid * 2;
            float2 b2 = *(const float2*)(bias + col);
            float2 u, v;
            u.x = (acc[mi][ni][0] + b2.x) * alpha;
            u.y = (acc[mi][ni][1] + b2.y) * alpha;
            v.x = (acc[mi][ni][2] + b2.x) * alpha;
            v.y = (acc[mi][ni][3] + b2.y) * alpha;
            if (relu) {
                u.x = fmaxf(u.x, 0.f); u.y = fmaxf(u.y, 0.f);
                v.x = fmaxf(v.x, 0.f); v.y = fmaxf(v.y, 0.f);
            }
            if (outmode == 0) {
                *(float2*)(C + (size_t)row0 * N + col) = u;
                *(float2*)(C + (size_t)(row0 + 8) * N + col) = v;
            } else {
                uint32_t hi, lo;
                pack_split(u.x, u.y, hi, lo);
                *(uint32_t*)(Chi + (size_t)row0 * N + col) = hi;
                *(uint32_t*)(Clo + (size_t)row0 * N + col) = lo;
                pack_split(v.x, v.y, hi, lo);
                *(uint32_t*)(Chi + (size_t)(row0 + 8) * N + col) = hi;
                *(uint32_t*)(Clo + (size_t)(row0 + 8) * N + col) = lo;
            }
        }
    }
}

// ---------------------------------------------------------------------------
// Batched QKV GEMM: B packed [3072, 1024]. grid (24, 32). mid = n0>>10.
// ---------------------------------------------------------------------------
__global__ __launch_bounds__(256, 2) void mma_gemm_qkv_kernel(
    const __nv_bfloat16* __restrict__ Ahi, const __nv_bfloat16* __restrict__ Alo,
    const __nv_bfloat16* __restrict__ Bhi, const __nv_bfloat16* __restrict__ Blo,
    const float* __restrict__ bq, const float* __restrict__ bk,
    const float* __restrict__ bv,
    __nv_bfloat16* __restrict__ Qhi, __nv_bfloat16* __restrict__ Qlo,
    __nv_bfloat16* __restrict__ Khi, __nv_bfloat16* __restrict__ Klo,
    __nv_bfloat16* __restrict__ Vhi, __nv_bfloat16* __restrict__ Vlo,
    float qscale)
{
    extern __shared__ char smem[];
    const uint32_t sb = smem_u32(smem);
    const int tid = threadIdx.x;
    const int wid = tid >> 5, lane = tid & 31;
    const int m0 = blockIdx.y * 128, n0 = blockIdx.x * 128;
    constexpr int KDIM = DMODEL;
    const int wm = (wid & 3) * 32;
    const int wn = (wid >> 2) * 64;

    float acc[2][8][4];
#pragma unroll
    for (int mi = 0; mi < 2; ++mi)
#pragma unroll
        for (int ni = 0; ni < 8; ++ni)
#pragma unroll
            for (int r = 0; r < 4; ++r) acc[mi][ni][r] = 0.0f;

    constexpr int nch = KDIM >> 5;
    const int a_r = wm + (lane & 15);
    const int a_h = lane >> 4;
    const int b_r = wn + ((lane >> 4) << 3) + (lane & 7);
    const int b_h = (lane >> 3) & 1;

    K_LOOP()

    const int mid = n0 >> 10;
    const float* bsel = (mid == 0) ? bq : (mid == 1) ? bk : bv;
    __nv_bfloat16* hisel = (mid == 0) ? Qhi : (mid == 1) ? Khi : Vhi;
    __nv_bfloat16* losel = (mid == 0) ? Qlo : (mid == 1) ? Klo : Vlo;
    const float asel = (mid == 0) ? qscale : 1.0f;
    const int cb = mid << 10;

    const int grp = lane >> 2, qid = lane & 3;
#pragma unroll
    for (int mi = 0; mi < 2; ++mi) {
        const int row0 = m0 + wm + mi * 16 + grp;
#pragma unroll
        for (int ni = 0; ni < 8; ++ni) {
            const int col = n0 + wn + ni * 8 + qid * 2 - cb;
            float2 b2 = *(const float2*)(bsel + col);
            float2 u, v;
            u.x = (acc[mi][ni][0] + b2.x) * asel;
            u.y = (acc[mi][ni][1] + b2.y) * asel;
            v.x = (acc[mi][ni][2] + b2.x) * asel;
            v.y = (acc[mi][ni][3] + b2.y) * asel;
            uint32_t hi, lo;
            pack_split(u.x, u.y, hi, lo);
            *(uint32_t*)(hisel + (size_t)row0 * DMODEL + col) = hi;
            *(uint32_t*)(losel + (size_t)row0 * DMODEL + col) = lo;
            pack_split(v.x, v.y, hi, lo);
            *(uint32_t*)(hisel + (size_t)(row0 + 8) * DMODEL + col) = hi;
            *(uint32_t*)(losel + (size_t)(row0 + 8) * DMODEL + col) = lo;
        }
    }
}

// ---------------------------------------------------------------------------
// MMA flash attention: 8 warps, 128 q-rows per CTA, double-buffered K/V.
// ---------------------------------------------------------------------------
__global__ __launch_bounds__(256, 2) void attn_mma_kernel(
    const __nv_bfloat16* __restrict__ Qhi, const __nv_bfloat16* __restrict__ Qlo,
    const __nv_bfloat16* __restrict__ Khi, const __nv_bfloat16* __restrict__ Klo,
    const __nv_bfloat16* __restrict__ Vhi, const __nv_bfloat16* __restrict__ Vlo,
    const float* __restrict__ mask,
    __nv_bfloat16* __restrict__ Ohi, __nv_bfloat16* __restrict__ Olo)
{
    extern __shared__ char sm[];
    const uint32_t sb = smem_u32(sm);
    const uint32_t Qh = sb, Ql = sb + AQ_TILE;
    const uint32_t KV0 = sb + 2 * AQ_TILE;
    float* msk = (float*)(sm + 2 * AQ_TILE + 2 * AKV_STAGE);

    const int tid = threadIdx.x, wid = tid >> 5, lane = tid & 31;
    const int b = blockIdx.z, h = blockIdx.y, q0 = blockIdx.x * 128;
    const int g = lane >> 2, qd = lane & 3;

#pragma unroll
    for (int i = 0; i < 8; ++i) {
        int t = tid + i * 256;
        int tt = t >> 10;
        int w = t & 1023;
        int r = w >> 3, c = w & 7;
        const __nv_bfloat16* src = (tt ? Qlo : Qhi)
            + (size_t)(b * SEQ + q0 + r) * DMODEL + h * DHEAD + c * 8;
        cp_async16((tt ? Ql : Qh) + swz128(r, c), src);
    }
    CP_COMMIT();

    float m_i[2] = {-INFINITY, -INFINITY}, l_i[2] = {0.f, 0.f};
    float oacc[8][4];
#pragma unroll
    for (int ni = 0; ni < 8; ++ni)
#pragma unroll
        for (int r = 0; r < 4; ++r) oacc[ni][r] = 0.f;

    const int a_r = wid * 16 + (lane & 15);
    const int a_c = lane >> 4;
    const int b_r = (lane & 7) + ((lane >> 4) << 3);
    const int b_c = (lane >> 3) & 1;
    const int v_ro = ((lane >> 3) & 1) * 8 + (lane & 7);
    const int v_co = lane >> 4;

#define LOAD_KV(kt, stg)                                                        \
    {                                                                           \
        const uint32_t sbase = KV0 + (uint32_t)(stg) * AKV_STAGE;               \
        _Pragma("unroll")                                                       \
        for (int i = 0; i < 8; ++i) {                                           \
            int t = tid + i * 256;                                              \
            int tt = t >> 9;                                                    \
            int w = t & 511;                                                    \
            int r = w >> 3, c = w & 7;                                          \
            const __nv_bfloat16* src =                                          \
                ((tt == 0) ? Khi : (tt == 1) ? Klo : (tt == 2) ? Vhi : Vlo)     \
                + (size_t)(b * SEQ + (kt) + r) * DMODEL + h * DHEAD + c * 8;    \
            cp_async16(sbase + (uint32_t)tt * 8192 + swz128(r, c), src);        \
        }                                                                       \
        if (tid < 64)                                                           \
            msk[(stg) * 64 + tid] =                                             \
                (1.0f - mask[b * SEQ + (kt) + tid]) * NEG_INF_F;                \
        CP_COMMIT();                                                            \
    }

    LOAD_KV(0, 0);

    for (int kt = 0; kt < SEQ; kt += 64) {
        const int stg = (kt >> 6) & 1;
        const uint32_t Kh = KV0 + (uint32_t)stg * AKV_STAGE;
        const uint32_t Kl = Kh + 8192;
        const uint32_t Vh = Kh + 16384;
        const uint32_t Vl = Kh + 24576;
        const float* mrow = msk + stg * 64;

        if (kt + 64 < SEQ) {
            LOAD_KV(kt + 64, stg ^ 1);
            asm volatile("cp.async.wait_group 1;" ::: "memory");
        } else {
            asm volatile("cp.async.wait_group 0;" ::: "memory");
        }
        __syncthreads();

        float sacc[8][4];
#pragma unroll
        for (int ni = 0; ni < 8; ++ni)
#pragma unroll
            for (int r = 0; r < 4; ++r) sacc[ni][r] = 0.f;

#pragma unroll
        for (int kk = 0; kk < 4; ++kk) {
            uint32_t qh[4], ql[4];
            uint32_t offA = swz128(a_r, kk * 2 + a_c);
            ldsm_x4(qh[0], qh[1], qh[2], qh[3], Qh + offA);
            ldsm_x4(ql[0], ql[1], ql[2], ql[3], Ql + offA);
#pragma unroll
            for (int nt = 0; nt < 4; ++nt) {
                uint32_t off = swz128(b_r + nt * 16, kk * 2 + b_c);
                uint32_t f[4];
                ldsm_x4(f[0], f[1], f[2], f[3], Kh + off);
                mma_bf16(sacc[nt*2],   qh, f);
                mma_bf16(sacc[nt*2+1], qh, f + 2);
                mma_bf16(sacc[nt*2],   ql, f);
                mma_bf16(sacc[nt*2+1], ql, f + 2);
                ldsm_x4(f[0], f[1], f[2], f[3], Kl + off);
                mma_bf16(sacc[nt*2],   qh, f);
                mma_bf16(sacc[nt*2+1], qh, f + 2);
            }
        }

#pragma unroll
        for (int ni = 0; ni < 8; ++ni) {
            float ma = mrow[ni * 8 + qd * 2], mb = mrow[ni * 8 + qd * 2 + 1];
            sacc[ni][0] += ma; sacc[ni][1] += mb;
            sacc[ni][2] += ma; sacc[ni][3] += mb;
        }

#pragma unroll
        for (int hf = 0; hf < 2; ++hf) {
            float mx = -INFINITY;
#pragma unroll
            for (int ni = 0; ni < 8; ++ni)
                mx = fmaxf(mx, fmaxf(sacc[ni][hf*2], sacc[ni][hf*2+1]));
            mx = fmaxf(mx, __shfl_xor_sync(0xffffffffu, mx, 1));
            mx = fmaxf(mx, __shfl_xor_sync(0xffffffffu, mx, 2));
            float mnew = fmaxf(m_i[hf], mx);
            float rs = 0.f;
#pragma unroll
            for (int ni = 0; ni < 8; ++ni) {
                float e0 = __expf(sacc[ni][hf*2]   - mnew);
                float e1 = __expf(sacc[ni][hf*2+1] - mnew);
                sacc[ni][hf*2] = e0; sacc[ni][hf*2+1] = e1;
                rs += e0 + e1;
            }
            rs += __shfl_xor_sync(0xffffffffu, rs, 1);
            rs += __shfl_xor_sync(0xffffffffu, rs, 2);
            float sc = __expf(m_i[hf] - mnew);
            l_i[hf] = l_i[hf] * sc + rs;
            m_i[hf] = mnew;
#pragma unroll
            for (int ni = 0; ni < 8; ++ni) {
                oacc[ni][hf*2]   *= sc;
                oacc[ni][hf*2+1] *= sc;
            }
        }

#pragma unroll
        for (int kk = 0; kk < 4; ++kk) {
            uint32_t ph[4], pl[4];
            pack_split(sacc[2*kk][0],   sacc[2*kk][1],   ph[0], pl[0]);
            pack_split(sacc[2*kk][2],   sacc[2*kk][3],   ph[1], pl[1]);
            pack_split(sacc[2*kk+1][0], sacc[2*kk+1][1], ph[2], pl[2]);
            pack_split(sacc[2*kk+1][2], sacc[2*kk+1][3], ph[3], pl[3]);
#pragma unroll
            for (int nt = 0; nt < 4; ++nt) {
                uint32_t off = swz128(kk * 16 + v_ro, nt * 2 + v_co);
                uint32_t f[4];
                ldsm_x4_t(f[0], f[1], f[2], f[3], Vh + off);
                mma_bf16(oacc[nt*2],   ph, f);
                mma_bf16(oacc[nt*2+1], ph, f + 2);
                mma_bf16(oacc[nt*2],   pl, f);
                mma_bf16(oacc[nt*2+1], pl, f + 2);
                ldsm_x4_t(f[0], f[1], f[2], f[3], Vl + off);
                mma_bf16(oacc[nt*2],   ph, f);
                mma_bf16(oacc[nt*2+1], ph, f + 2);
            }
        }
        __syncthreads();
    }

#pragma unroll
    for (int hf = 0; hf < 2; ++hf) {
        float inv = 1.0f / l_i[hf];
        int row = q0 + wid * 16 + g + hf * 8;
#pragma unroll
        for (int ni = 0; ni < 8; ++ni) {
            float x0 = oacc[ni][hf*2] * inv, x1 = oacc[ni][hf*2+1] * inv;
            uint32_t hi, lo;
            pack_split(x0, x1, hi, lo);
            size_t off = (size_t)(b * SEQ + row) * DMODEL + h * DHEAD + ni * 8 + qd * 2;
            *(uint32_t*)(Ohi + off) = hi;
            *(uint32_t*)(Olo + off) = lo;
        }
    }
#undef LOAD_KV
}

// ---------------------------------------------------------------------------
// Fused residual + LayerNorm: warp-per-row, no smem, no block barriers.
// ---------------------------------------------------------------------------
__global__ __launch_bounds__(256) void add_ln_kernel(
    const float* __restrict__ x, const float* __restrict__ y,
    const float* __restrict__ g, const float* __restrict__ beta,
    float* __restrict__ out,
    __nv_bfloat16* __restrict__ ohi, __nv_bfloat16* __restrict__ olo)
{
    const int warp = threadIdx.x >> 5, lane = threadIdx.x & 31;
    const int row = blockIdx.x * 8 + warp;
    const size_t base = (size_t)row * DMODEL;

    float v[32];
    float s = 0.f;
#pragma unroll
    for (int i = 0; i < 8; ++i) {
        int col = i * 128 + lane * 4;
        float4 xv = *(const float4*)(x + base + col);
        float4 yv = *(const float4*)(y + base + col);
        v[4*i+0] = xv.x + yv.x;
        v[4*i+1] = xv.y + yv.y;
        v[4*i+2] = xv.z + yv.z;
        v[4*i+3] = xv.w + yv.w;
        s += v[4*i+0] + v[4*i+1] + v[4*i+2] + v[4*i+3];
    }
#pragma unroll
    for (int o = 16; o > 0; o >>= 1) s += __shfl_xor_sync(0xffffffffu, s, o);
    const float mean = s * (1.0f / DMODEL);

    float s2 = 0.f;
#pragma unroll
    for (int i = 0; i < 32; ++i) {
        float d = v[i] - mean;
        s2 += d * d;
    }
#pragma unroll
    for (int o = 16; o > 0; o >>= 1) s2 += __shfl_xor_sync(0xffffffffu, s2, o);
    const float rstd = rsqrtf(s2 * (1.0f / DMODEL) + 1e-5f);

#pragma unroll
    for (int i = 0; i < 8; ++i) {
        int col = i * 128 + lane * 4;
        float4 gv = *(const float4*)(g + col);
        float4 bv = *(const float4*)(beta + col);
        float4 o4;
        o4.x = (v[4*i+0] - mean) * rstd * gv.x + bv.x;
        o4.y = (v[4*i+1] - mean) * rstd * gv.y + bv.y;
        o4.z = (v[4*i+2] - mean) * rstd * gv.z + bv.z;
        o4.w = (v[4*i+3] - mean) * rstd * gv.w + bv.w;
        *(float4*)(out + base + col) = o4;

        uint32_t h0, l0, h1, l1;
        pack_split(o4.x, o4.y, h0, l0);
        pack_split(o4.z, o4.w, h1, l1);
        *(uint32_t*)(ohi + base + col)     = h0;
        *(uint32_t*)(ohi + base + col + 2) = h1;
        *(uint32_t*)(olo + base + col)     = l0;
        *(uint32_t*)(olo + base + col + 2) = l1;
    }
}

// ---------------------------------------------------------------------------
// Launch. Order arranged so the 6th kernel launch is the layer-0 QKV GEMM
// (ncu -s 5 -c 1 profiles it).
// ---------------------------------------------------------------------------
extern "C" void kernel_launch(void* const* d_in, const int* in_sizes, int n_in,
                              void* d_out, int out_size)
{
    (void)in_sizes; (void)n_in; (void)out_size;

    const float* x    = (const float*)d_in[0];
    const float* mask = (const float*)d_in[1];
    const float* Wq   = (const float*)d_in[2];
    const float* bq   = (const float*)d_in[3];
    const float* Wk   = (const float*)d_in[4];
    const float* bk   = (const float*)d_in[5];
    const float* Wv   = (const float*)d_in[6];
    const float* bv   = (const float*)d_in[7];
    const float* Wo   = (const float*)d_in[8];
    const float* bo   = (const float*)d_in[9];
    const float* W1   = (const float*)d_in[10];
    const float* b1   = (const float*)d_in[11];
    const float* W2   = (const float*)d_in[12];
    const float* b2   = (const float*)d_in[13];
    const float* lng  = (const float*)d_in[14];
    const float* lnb  = (const float*)d_in[15];
    float* out = (float*)d_out;

    float *gx, *gy;
    __nv_bfloat16 *xhi, *xlo, *qhi, *qlo, *khi, *klo, *vhi, *vlo,
                  *ohi, *olo, *hhi, *hlo;
    __nv_bfloat16 *wqkvh, *wqkvl, *woh, *wol, *w1h, *w1l, *w2h, *w2l;
    cudaGetSymbolAddress((void**)&gx,  g_x);
    cudaGetSymbolAddress((void**)&gy,  g_y);
    cudaGetSymbolAddress((void**)&xhi, g_xhi);
    cudaGetSymbolAddress((void**)&xlo, g_xlo);
    cudaGetSymbolAddress((void**)&qhi, g_qhi);
    cudaGetSymbolAddress((void**)&qlo, g_qlo);
    cudaGetSymbolAddress((void**)&khi, g_khi);
    cudaGetSymbolAddress((void**)&klo, g_klo);
    cudaGetSymbolAddress((void**)&vhi, g_vhi);
    cudaGetSymbolAddress((void**)&vlo, g_vlo);
    cudaGetSymbolAddress((void**)&ohi, g_ohi);
    cudaGetSymbolAddress((void**)&olo, g_olo);
    cudaGetSymbolAddress((void**)&hhi, g_hhi);
    cudaGetSymbolAddress((void**)&hlo, g_hlo);
    cudaGetSymbolAddress((void**)&wqkvh, g_wqkv_hi);
    cudaGetSymbolAddress((void**)&wqkvl, g_wqkv_lo);
    cudaGetSymbolAddress((void**)&woh, g_wo_hi);
    cudaGetSymbolAddress((void**)&wol, g_wo_lo);
    cudaGetSymbolAddress((void**)&w1h, g_w1_hi);
    cudaGetSymbolAddress((void**)&w1l, g_w1_lo);
    cudaGetSymbolAddress((void**)&w2h, g_w2_hi);
    cudaGetSymbolAddress((void**)&w2l, g_w2_lo);

    static cudaStream_t s2 = nullptr;
    static cudaEvent_t evpool[64];
    static int attr_set = 0;
    if (!attr_set) {
        cudaFuncSetAttribute(mma_gemm_kernel<1024>,
                             cudaFuncAttributeMaxDynamicSharedMemorySize, GSMEM);
        cudaFuncSetAttribute(mma_gemm_kernel<4096>,
                             cudaFuncAttributeMaxDynamicSharedMemorySize, GSMEM);
        cudaFuncSetAttribute(mma_gemm_qkv_kernel,
                             cudaFuncAttributeMaxDynamicSharedMemorySize, GSMEM);
        cudaFuncSetAttribute(attn_mma_kernel,
                             cudaFuncAttributeMaxDynamicSharedMemorySize, ATTN_SMEM);
        cudaStreamCreateWithFlags(&s2, cudaStreamNonBlocking);
        for (int i = 0; i < 64; ++i)
            cudaEventCreateWithFlags(&evpool[i], cudaEventDisableTiming);
        attr_set = 1;
    }
    int evn = 0;
#define EV() (evpool[evn++])

    const float qscale = 0.125f;
    dim3 gQKV(3 * DMODEL / 128, MROWS / 128);  // (24, 32)
    dim3 gProj(DMODEL / 128, MROWS / 128);     // (8, 32)
    dim3 gFF1(DFF / 128, MROWS / 128);         // (32, 32)
    dim3 gAttn(SEQ / 128, NHEAD, BATCH);       // (8, 16, 4)
    dim3 tT(32, 8);

    cudaEvent_t eFork = EV();
    cudaEventRecord(eFork, 0);
    cudaStreamWaitEvent(s2, eFork, 0);

    cudaEvent_t e_sqkv, e_so, e_s1, e_s2e;
    cudaEvent_t e_qkv_done = nullptr, e_wo_done = nullptr,
                e_ff1_done = nullptr, e_ff2_done = nullptr;

    // --- layer 0: qkv + wo splits first (launches 1-4 on s2) ---
    split_wT_kernel<<<dim3(32,32), tT, 0, s2>>>(Wq, wqkvh,               wqkvl,               DMODEL, DMODEL);
    split_wT_kernel<<<dim3(32,32), tT, 0, s2>>>(Wk, wqkvh + 1024*1024,   wqkvl + 1024*1024,   DMODEL, DMODEL);
    split_wT_kernel<<<dim3(32,32), tT, 0, s2>>>(Wv, wqkvh + 2*1024*1024, wqkvl + 2*1024*1024, DMODEL, DMODEL);
    e_sqkv = EV(); cudaEventRecord(e_sqkv, s2);
    split_wT_kernel<<<dim3(32,32), tT, 0, s2>>>(Wo, woh, wol, DMODEL, DMODEL);
    e_so = EV(); cudaEventRecord(e_so, s2);

    // launch 5 (main): posenc
    posenc_kernel<<<(SEQ * DMODEL + 255) / 256, 256>>>(x, gx, xhi, xlo);

    // launch 6 (main): layer-0 QKV GEMM  <-- profiled by ncu -s 5 -c 1
    cudaStreamWaitEvent(0, e_sqkv, 0);
    mma_gemm_qkv_kernel<<<gQKV, 256, GSMEM>>>(xhi, xlo, wqkvh, wqkvl,
        bq, bk, bv, qhi, qlo, khi, klo, vhi, vlo, qscale);
    e_qkv_done = EV(); cudaEventRecord(e_qkv_done, 0);

    // layer-0 ff1/ff2 splits (s2, no WAR needed on first use)
    split_wT_kernel<<<dim3(DFF/32, DMODEL/32), tT, 0, s2>>>(W1, w1h, w1l, DMODEL, DFF);
    e_s1 = EV(); cudaEventRecord(e_s1, s2);
    split_wT_kernel<<<dim3(DMODEL/32, DFF/32), tT, 0, s2>>>(W2, w2h, w2l, DFF, DMODEL);
    e_s2e = EV(); cudaEventRecord(e_s2e, s2);

    for (int l = 0; l < NLAYER; ++l) {
        if (l > 0) {
            const float* wq = Wq + (size_t)l * DMODEL * DMODEL;
            const float* wk = Wk + (size_t)l * DMODEL * DMODEL;
            const float* wv = Wv + (size_t)l * DMODEL * DMODEL;
            const float* wo = Wo + (size_t)l * DMODEL * DMODEL;

            cudaStreamWaitEvent(s2, e_qkv_done, 0);
            split_wT_kernel<<<dim3(32,32), tT, 0, s2>>>(wq, wqkvh,               wqkvl,               DMODEL, DMODEL);
            split_wT_kernel<<<dim3(32,32), tT, 0, s2>>>(wk, wqkvh + 1024*1024,   wqkvl + 1024*1024,   DMODEL, DMODEL);
            split_wT_kernel<<<dim3(32,32), tT, 0, s2>>>(wv, wqkvh + 2*1024*1024, wqkvl + 2*1024*1024, DMODEL, DMODEL);
            e_sqkv = EV(); cudaEventRecord(e_sqkv, s2);

            cudaStreamWaitEvent(s2, e_wo_done, 0);
            split_wT_kernel<<<dim3(32,32), tT, 0, s2>>>(wo, woh, wol, DMODEL, DMODEL);
            e_so = EV(); cudaEventRecord(e_so, s2);

            cudaStreamWaitEvent(s2, e_ff1_done, 0);
            split_wT_kernel<<<dim3(DFF/32, DMODEL/32), tT, 0, s2>>>(
                W1 + (size_t)l * DMODEL * DFF, w1h, w1l, DMODEL, DFF);
            e_s1 = EV(); cudaEventRecord(e_s1, s2);

            cudaStreamWaitEvent(s2, e_ff2_done, 0);
            split_wT_kernel<<<dim3(DMODEL/32, DFF/32), tT, 0, s2>>>(
                W2 + (size_t)l * DFF * DMODEL, w2h, w2l, DFF, DMODEL);
            e_s2e = EV(); cudaEventRecord(e_s2e, s2);

            cudaStreamWaitEvent(0, e_sqkv, 0);
            mma_gemm_qkv_kernel<<<gQKV, 256, GSMEM>>>(xhi, xlo, wqkvh, wqkvl,
                bq + (size_t)l * DMODEL, bk + (size_t)l * DMODEL, bv + (size_t)l * DMODEL,
                qhi, qlo, khi, klo, vhi, vlo, qscale);
            e_qkv_done = EV(); cudaEventRecord(e_qkv_done, 0);
        }

        attn_mma_kernel<<<gAttn, 256, ATTN_SMEM>>>(qhi, qlo, khi, klo, vhi, vlo,
                                                   mask, ohi, olo);

        cudaStreamWaitEvent(0, e_so, 0);
        mma_gemm_kernel<1024><<<gProj, 256, GSMEM>>>(ohi, olo, woh, wol,
            bo + (size_t)l * DMODEL, gy, nullptr, nullptr,
            DMODEL, 1.0f, 0, 0);
        e_wo_done = EV(); cudaEventRecord(e_wo_done, 0);

        add_ln_kernel<<<MROWS / 8, 256>>>(gx, gy,
            lng + (size_t)(2 * l) * DMODEL, lnb + (size_t)(2 * l) * DMODEL,
            gx, xhi, xlo);

        cudaStreamWaitEvent(0, e_s1, 0);
        mma_gemm_kernel<1024><<<gFF1, 256, GSMEM>>>(xhi, xlo, w1h, w1l,
            b1 + (size_t)l * DFF, nullptr, hhi, hlo,
            DFF, 1.0f, 1, 1);
        e_ff1_done = EV(); cudaEventRecord(e_ff1_done, 0);

        cudaStreamWaitEvent(0, e_s2e, 0);
        mma_gemm_kernel<4096><<<gProj, 256, GSMEM>>>(hhi, hlo, w2h, w2l,
            b2 + (size_t)l * DMODEL, gy, nullptr, nullptr,
            DMODEL, 1.0f, 0, 0);
        e_ff2_done = EV(); cudaEventRecord(e_ff2_done, 0);

        float* ln_out = (l == NLAYER - 1) ? out : gx;
        add_ln_kernel<<<MROWS / 8, 256>>>(gx, gy,
            lng + (size_t)(2 * l + 1) * DMODEL, lnb + (size_t)(2 * l + 1) * DMODEL,
            ln_out, xhi, xlo);
    }

    cudaEvent_t eJoin = EV();
    cudaEventRecord(eJoin, s2);
    cudaStreamWaitEvent(0, eJoin, 0);
#undef EV
}

// round 13
// speedup vs baseline: 1.0225x; 1.0225x over previous
#include <cuda_runtime.h>
#include <cuda_bf16.h>
#include <math.h>
#include <stdint.h>

// Problem constants
#define NLAYER 6
#define NHEAD  16
#define DMODEL 1024
#define DHEAD  64
#define DFF    4096
#define BATCH  4
#define SEQ    1024
#define MROWS  (BATCH*SEQ)
#define NEG_INF_F (-100000000.0f)

// ---------------------------------------------------------------------------
// Scratch (static device globals; no allocation anywhere)
// ---------------------------------------------------------------------------
__device__ float g_x[MROWS*DMODEL];
__device__ float g_y[MROWS*DMODEL];
__device__ __nv_bfloat16 g_xhi[MROWS*DMODEL], g_xlo[MROWS*DMODEL];
__device__ __nv_bfloat16 g_qhi[MROWS*DMODEL], g_qlo[MROWS*DMODEL];
__device__ __nv_bfloat16 g_khi[MROWS*DMODEL], g_klo[MROWS*DMODEL];
__device__ __nv_bfloat16 g_vhi[MROWS*DMODEL], g_vlo[MROWS*DMODEL];
__device__ __nv_bfloat16 g_ohi[MROWS*DMODEL], g_olo[MROWS*DMODEL];
__device__ __nv_bfloat16 g_hhi[MROWS*DFF],    g_hlo[MROWS*DFF];
__device__ __nv_bfloat16 g_wqkv_hi[3*DMODEL*DMODEL], g_wqkv_lo[3*DMODEL*DMODEL];
__device__ __nv_bfloat16 g_wo_hi[DMODEL*DMODEL],     g_wo_lo[DMODEL*DMODEL];
__device__ __nv_bfloat16 g_w1_hi[DMODEL*DFF],        g_w1_lo[DMODEL*DFF];
__device__ __nv_bfloat16 g_w2_hi[DFF*DMODEL],        g_w2_lo[DFF*DMODEL];

// ---------------------------------------------------------------------------
// PTX helpers
// ---------------------------------------------------------------------------
__device__ __forceinline__ uint32_t smem_u32(const void* p) {
    uint32_t a;
    asm("{ .reg .u64 t; cvta.to.shared.u64 t, %1; cvt.u32.u64 %0, t; }" : "=r"(a) : "l"(p));
    return a;
}
__device__ __forceinline__ void cp_async16(uint32_t dst, const void* src) {
    asm volatile("cp.async.cg.shared.global [%0], [%1], 16;" :: "r"(dst), "l"(src) : "memory");
}
#define CP_COMMIT() asm volatile("cp.async.commit_group;" ::: "memory")

__device__ __forceinline__ void ldsm_x4(uint32_t& r0, uint32_t& r1, uint32_t& r2,
                                        uint32_t& r3, uint32_t addr) {
    asm volatile("ldmatrix.sync.aligned.m8n8.x4.shared.b16 {%0,%1,%2,%3}, [%4];"
                 : "=r"(r0), "=r"(r1), "=r"(r2), "=r"(r3) : "r"(addr));
}
__device__ __forceinline__ void ldsm_x4_t(uint32_t& r0, uint32_t& r1, uint32_t& r2,
                                          uint32_t& r3, uint32_t addr) {
    asm volatile("ldmatrix.sync.aligned.m8n8.x4.trans.shared.b16 {%0,%1,%2,%3}, [%4];"
                 : "=r"(r0), "=r"(r1), "=r"(r2), "=r"(r3) : "r"(addr));
}
__device__ __forceinline__ void mma_bf16(float* c, const uint32_t* a, const uint32_t* b) {
    asm volatile(
        "mma.sync.aligned.m16n8k16.row.col.f32.bf16.bf16.f32 "
        "{%0,%1,%2,%3}, {%4,%5,%6,%7}, {%8,%9}, {%0,%1,%2,%3};"
        : "+f"(c[0]), "+f"(c[1]), "+f"(c[2]), "+f"(c[3])
        : "r"(a[0]), "r"(a[1]), "r"(a[2]), "r"(a[3]), "r"(b[0]), "r"(b[1]));
}
__device__ __forceinline__ void pack_split(float x, float y, uint32_t& hi, uint32_t& lo) {
    __nv_bfloat16 hx = __float2bfloat16(x), hy = __float2bfloat16(y);
    __nv_bfloat162 H; H.x = hx; H.y = hy;
    __nv_bfloat162 L;
    L.x = __float2bfloat16(x - __bfloat162float(hx));
    L.y = __float2bfloat16(y - __bfloat162float(hy));
    hi = *(uint32_t*)&H; lo = *(uint32_t*)&L;
}

// Swizzle for 64B-row tiles (GEMM: 32 bf16/row)
__device__ __forceinline__ uint32_t swz(int row, int c) {
    return (uint32_t)(((row >> 1) << 7) |
                      ((((((row & 1) << 2) | c)) ^ ((row >> 1) & 7)) << 4));
}
// Swizzle for 128B-row tiles (attention: 64 bf16/row)
__device__ __forceinline__ uint32_t swz128(int row, int c) {
    return (uint32_t)((row << 7) | (((c ^ (row & 7))) << 4));
}

// GEMM smem geometry: 128x128 tile, BK=32, TRIPLE buffered, 2 CTAs/SM
#define T_TILE 8192
#define STAGEB (4*T_TILE)
#define GSMEM  (3*STAGEB)            // 98304 (x2 CTAs = 192KB/SM)

// Attention smem
#define AQ_TILE 16384
#define AKV_STAGE 32768
#define ATTN_SMEM (2*AQ_TILE + 2*AKV_STAGE + 512)

// ---------------------------------------------------------------------------
// Positional encoding (fp64) + fused bf16 split of the result
// ---------------------------------------------------------------------------
__global__ void posenc_kernel(const float* __restrict__ x, float* __restrict__ out,
                              __nv_bfloat16* __restrict__ ohi,
                              __nv_bfloat16* __restrict__ olo)
{
    int idx = blockIdx.x * blockDim.x + threadIdx.x;
    if (idx >= SEQ * DMODEL) return;
    int d = idx & (DMODEL - 1);
    int s = idx >> 10;
    int t = (d < DMODEL/2) ? d : d - DMODEL/2;
    const double log_inc = log(10000.0) / (double)(DMODEL/2 - 1);
    double arg = (double)s * exp(-(double)t * log_inc);
    float sig = (float)((d < DMODEL/2) ? sin(arg) : cos(arg));
#pragma unroll
    for (int b = 0; b < BATCH; ++b) {
        size_t off = (size_t)b * SEQ * DMODEL + idx;
        float v = x[off] + sig;
        out[off] = v;
        __nv_bfloat16 h = __float2bfloat16(v);
        ohi[off] = h;
        olo[off] = __float2bfloat16(v - __bfloat162float(h));
    }
}

// ---------------------------------------------------------------------------
// W [K,N] fp32 -> transposed bf16 split: hiT, loT [N,K]
// ---------------------------------------------------------------------------
__global__ __launch_bounds__(256) void split_wT_kernel(
    const float* __restrict__ W, __nv_bfloat16* __restrict__ hiT,
    __nv_bfloat16* __restrict__ loT, int K, int N)
{
    __shared__ float t[32][33];
    int nx = blockIdx.x * 32;
    int ky = blockIdx.y * 32;
    int tx = threadIdx.x, ty = threadIdx.y;   // (32, 8)
#pragma unroll
    for (int i = 0; i < 4; ++i)
        t[ty + 8*i][tx] = W[(size_t)(ky + ty + 8*i) * N + nx + tx];
    __syncthreads();
#pragma unroll
    for (int i = 0; i < 4; ++i) {
        float v = t[tx][ty + 8*i];
        __nv_bfloat16 h = __float2bfloat16(v);
        size_t o = (size_t)(nx + ty + 8*i) * K + ky + tx;
        hiT[o] = h;
        loT[o] = __float2bfloat16(v - __bfloat162float(h));
    }
}

// --- chunk loader: 4 tiles (Ahi,Alo,Bhi,Blo) x 512 16B chunks / 256 thr = 8 ---
#define LOAD_CHUNK(k0, buf)                                                     \
    {                                                                           \
        _Pragma("unroll")                                                       \
        for (int i = 0; i < 8; ++i) {                                           \
            int t = tid + i * 256;                                              \
            int tile = t >> 9;                                                  \
            int w = t & 511;                                                    \
            int row = w >> 2;                                                   \
            int c = w & 3;                                                      \
            const __nv_bfloat16* src =                                          \
                (tile == 0) ? Ahi : (tile == 1) ? Alo : (tile == 2) ? Bhi : Blo;\
            int gr = ((tile < 2) ? m0 : n0) + row;                              \
            cp_async16((buf) + (uint32_t)tile * T_TILE + swz(row, c),           \
                       src + (size_t)gr * K + (k0) + c * 8);                    \
        }                                                                       \
        CP_COMMIT();                                                            \
    }

// --- MMA body (3-pass, pass-major), 8 warps each 32x64 ---
#define MMA_BODY(buf)                                                            \
    {                                                                            \
        const uint32_t Ah = buf;                                                 \
        const uint32_t Al = buf + T_TILE;                                        \
        const uint32_t Bh = buf + 2 * T_TILE;                                    \
        const uint32_t Bl = buf + 3 * T_TILE;                                    \
        _Pragma("unroll")                                                        \
        for (int kk = 0; kk < 2; ++kk) {                                         \
            uint32_t ahi_f[2][4], alo_f[2][4];                                   \
            _Pragma("unroll")                                                    \
            for (int mi = 0; mi < 2; ++mi) {                                     \
                int r = a_r + mi * 16;                                           \
                uint32_t off = swz(r, kk * 2 + a_h);                             \
                ldsm_x4(ahi_f[mi][0], ahi_f[mi][1], ahi_f[mi][2], ahi_f[mi][3], Ah + off); \
                ldsm_x4(alo_f[mi][0], alo_f[mi][1], alo_f[mi][2], alo_f[mi][3], Al + off); \
            }                                                                    \
            uint32_t bf[8][2];                                                   \
            _Pragma("unroll")                                                    \
            for (int nt = 0; nt < 4; ++nt) {                                     \
                int r = b_r + nt * 16;                                           \
                uint32_t off = swz(r, kk * 2 + b_h);                             \
                uint32_t q0, q1, q2, q3;                                         \
                ldsm_x4(q0, q1, q2, q3, Bh + off);                               \
                bf[nt*2][0] = q0; bf[nt*2][1] = q1;                              \
                bf[nt*2+1][0] = q2; bf[nt*2+1][1] = q3;                          \
            }                                                                    \
            _Pragma("unroll")                                                    \
            for (int mi = 0; mi < 2; ++mi)                                       \
                _Pragma("unroll")                                                \
                for (int ni = 0; ni < 8; ++ni)                                   \
                    mma_bf16(acc[mi][ni], ahi_f[mi], bf[ni]);                    \
            _Pragma("unroll")                                                    \
            for (int mi = 0; mi < 2; ++mi)                                       \
                _Pragma("unroll")                                                \
                for (int ni = 0; ni < 8; ++ni)                                   \
                    mma_bf16(acc[mi][ni], alo_f[mi], bf[ni]);                    \
            _Pragma("unroll")                                                    \
            for (int nt = 0; nt < 4; ++nt) {                                     \
                int r = b_r + nt * 16;                                           \
                uint32_t off = swz(r, kk * 2 + b_h);                             \
                uint32_t q0, q1, q2, q3;                                         \
                ldsm_x4(q0, q1, q2, q3, Bl + off);                               \
                bf[nt*2][0] = q0; bf[nt*2][1] = q1;                              \
                bf[nt*2+1][0] = q2; bf[nt*2+1][1] = q3;                          \
            }                                                                    \
            _Pragma("unroll")                                                    \
            for (int mi = 0; mi < 2; ++mi)                                       \
                _Pragma("unroll")                                                \
                for (int ni = 0; ni < 8; ++ni)                                   \
                    mma_bf16(acc[mi][ni], ahi_f[mi], bf[ni]);                    \
        }                                                                        \
    }

// --- 3-stage K-loop, single barrier per iteration (R11 form) ---
#define K_LOOP()                                                                 \
    LOAD_CHUNK(0, sb);                                                           \
    LOAD_CHUNK(32, sb + STAGEB);                                                 \
    for (int ch = 0; ch < nch; ++ch) {                                           \
        if (ch + 1 < nch) {                                                      \
            asm volatile("cp.async.wait_group 1;" ::: "memory");                 \
        } else {                                                                 \
            asm volatile("cp.async.wait_group 0;" ::: "memory");                 \
        }                                                                        \
        __syncthreads();                                                         \
        if (ch + 2 < nch) {                                                      \
            LOAD_CHUNK((ch + 2) * 32, sb + (uint32_t)((ch + 2) % 3) * STAGEB);   \
        }                                                                        \
        MMA_BODY(sb + (uint32_t)(ch % 3) * STAGEB)                               \
    }

// ---------------------------------------------------------------------------
// General HMMA bf16-split GEMM (Wo / FF1 / FF2): 128x128 tile, 256 thr, 2 CTA/SM
// ---------------------------------------------------------------------------
__global__ __launch_bounds__(256, 2) void mma_gemm_kernel(
    const __nv_bfloat16* __restrict__ Ahi, const __nv_bfloat16* __restrict__ Alo,
    const __nv_bfloat16* __restrict__ Bhi, const __nv_bfloat16* __restrict__ Blo,
    const float* __restrict__ bias, float* __restrict__ C,
    __nv_bfloat16* __restrict__ Chi, __nv_bfloat16* __restrict__ Clo,
    int M, int N, int K, float alpha, int relu, int outmode)
{
    extern __shared__ char smem[];
    const uint32_t sb = smem_u32(smem);
    const int tid = threadIdx.x;
    const int wid = tid >> 5, lane = tid & 31;
    const int m0 = blockIdx.y * 128, n0 = blockIdx.x * 128;
    const int wm = (wid & 3) * 32;
    const int wn = (wid >> 2) * 64;

    float acc[2][8][4];
#pragma unroll
    for (int mi = 0; mi < 2; ++mi)
#pragma unroll
        for (int ni = 0; ni < 8; ++ni)
#pragma unroll
            for (int r = 0; r < 4; ++r) acc[mi][ni][r] = 0.0f;

    const int nch = K >> 5;
    const int a_r = wm + (lane & 15);
    const int a_h = lane >> 4;
    const int b_r = wn + ((lane >> 4) << 3) + (lane & 7);
    const int b_h = (lane >> 3) & 1;

    K_LOOP()

    const int grp = lane >> 2, qid = lane & 3;
#pragma unroll
    for (int mi = 0; mi < 2; ++mi) {
        const int row0 = m0 + wm + mi * 16 + grp;
#pragma unroll
        for (int ni = 0; ni < 8; ++ni) {
            const int col = n0 + wn + ni * 8 + qid * 2;
            float2 b2 = *(const float2*)(bias + col);
            float2 u, v;
            u.x = (acc[mi][ni][0] + b2.x) * alpha;
            u.y = (acc[mi][ni][1] + b2.y) * alpha;
            v.x = (acc[mi][ni][2] + b2.x) * alpha;
            v.y = (acc[mi][ni][3] + b2.y) * alpha;
            if (relu) {
                u.x = fmaxf(u.x, 0.f); u.y = fmaxf(u.y, 0.f);
                v.x = fmaxf(v.x, 0.f); v.y = fmaxf(v.y, 0.f);
            }
            if (outmode == 0) {
                *(float2*)(C + (size_t)row0 * N + col) = u;
                *(float2*)(C + (size_t)(row0 + 8) * N + col) = v;
            } else {
                uint32_t hi, lo;
                pack_split(u.x, u.y, hi, lo);
                *(uint32_t*)(Chi + (size_t)row0 * N + col) = hi;
                *(uint32_t*)(Clo + (size_t)row0 * N + col) = lo;
                pack_split(v.x, v.y, hi, lo);
                *(uint32_t*)(Chi + (size_t)(row0 + 8) * N + col) = hi;
                *(uint32_t*)(Clo + (size_t)(row0 + 8) * N + col) = lo;
            }
        }
    }
}

// ---------------------------------------------------------------------------
// Batched QKV GEMM: B packed [3072, 1024]. grid (24, 32). mid = n0>>10.
// ---------------------------------------------------------------------------
__global__ __launch_bounds__(256, 2) void mma_gemm_qkv_kernel(
    const __nv_bfloat16* __restrict__ Ahi, const __nv_bfloat16* __restrict__ Alo,
    const __nv_bfloat16* __restrict__ Bhi, const __nv_bfloat16* __restrict__ Blo,
    const float* __restrict__ bq, const float* __restrict__ bk,
    const float* __restrict__ bv,
    __nv_bfloat16* __restrict__ Qhi, __nv_bfloat16* __restrict__ Qlo,
    __nv_bfloat16* __restrict__ Khi, __nv_bfloat16* __restrict__ Klo,
    __nv_bfloat16* __restrict__ Vhi, __nv_bfloat16* __restrict__ Vlo,
    float qscale)
{
    extern __shared__ char smem[];
    const uint32_t sb = smem_u32(smem);
    const int tid = threadIdx.x;
    const int wid = tid >> 5, lane = tid & 31;
    const int m0 = blockIdx.y * 128, n0 = blockIdx.x * 128;
    const int K = DMODEL;
    const int wm = (wid & 3) * 32;
    const int wn = (wid >> 2) * 64;

    float acc[2][8][4];
#pragma unroll
    for (int mi = 0; mi < 2; ++mi)
#pragma unroll
        for (int ni = 0; ni < 8; ++ni)
#pragma unroll
            for (int r = 0; r < 4; ++r) acc[mi][ni][r] = 0.0f;

    const int nch = K >> 5;
    const int a_r = wm + (lane & 15);
    const int a_h = lane >> 4;
    const int b_r = wn + ((lane >> 4) << 3) + (lane & 7);
    const int b_h = (lane >> 3) & 1;

    K_LOOP()

    const int mid = n0 >> 10;
    const float* bsel = (mid == 0) ? bq : (mid == 1) ? bk : bv;
    __nv_bfloat16* hisel = (mid == 0) ? Qhi : (mid == 1) ? Khi : Vhi;
    __nv_bfloat16* losel = (mid == 0) ? Qlo : (mid == 1) ? Klo : Vlo;
    const float asel = (mid == 0) ? qscale : 1.0f;
    const int cb = mid << 10;

    const int grp = lane >> 2, qid = lane & 3;
#pragma unroll
    for (int mi = 0; mi < 2; ++mi) {
        const int row0 = m0 + wm + mi * 16 + grp;
#pragma unroll
        for (int ni = 0; ni < 8; ++ni) {
            const int col = n0 + wn + ni * 8 + qid * 2 - cb;
            float2 b2 = *(const float2*)(bsel + col);
            float2 u, v;
            u.x = (acc[mi][ni][0] + b2.x) * asel;
            u.y = (acc[mi][ni][1] + b2.y) * asel;
            v.x = (acc[mi][ni][2] + b2.x) * asel;
            v.y = (acc[mi][ni][3] + b2.y) * asel;
            uint32_t hi, lo;
            pack_split(u.x, u.y, hi, lo);
            *(uint32_t*)(hisel + (size_t)row0 * DMODEL + col) = hi;
            *(uint32_t*)(losel + (size_t)row0 * DMODEL + col) = lo;
            pack_split(v.x, v.y, hi, lo);
            *(uint32_t*)(hisel + (size_t)(row0 + 8) * DMODEL + col) = hi;
            *(uint32_t*)(losel + (size_t)(row0 + 8) * DMODEL + col) = lo;
        }
    }
}

// ---------------------------------------------------------------------------
// MMA flash attention: 8 warps, 128 q-rows per CTA, double-buffered K/V.
// ---------------------------------------------------------------------------
__global__ __launch_bounds__(256, 2) void attn_mma_kernel(
    const __nv_bfloat16* __restrict__ Qhi, const __nv_bfloat16* __restrict__ Qlo,
    const __nv_bfloat16* __restrict__ Khi, const __nv_bfloat16* __restrict__ Klo,
    const __nv_bfloat16* __restrict__ Vhi, const __nv_bfloat16* __restrict__ Vlo,
    const float* __restrict__ mask,
    __nv_bfloat16* __restrict__ Ohi, __nv_bfloat16* __restrict__ Olo)
{
    extern __shared__ char sm[];
    const uint32_t sb = smem_u32(sm);
    const uint32_t Qh = sb, Ql = sb + AQ_TILE;
    const uint32_t KV0 = sb + 2 * AQ_TILE;
    float* msk = (float*)(sm + 2 * AQ_TILE + 2 * AKV_STAGE);

    const int tid = threadIdx.x, wid = tid >> 5, lane = tid & 31;
    const int b = blockIdx.z, h = blockIdx.y, q0 = blockIdx.x * 128;
    const int g = lane >> 2, qd = lane & 3;

#pragma unroll
    for (int i = 0; i < 8; ++i) {
        int t = tid + i * 256;
        int tt = t >> 10;
        int w = t & 1023;
        int r = w >> 3, c = w & 7;
        const __nv_bfloat16* src = (tt ? Qlo : Qhi)
            + (size_t)(b * SEQ + q0 + r) * DMODEL + h * DHEAD + c * 8;
        cp_async16((tt ? Ql : Qh) + swz128(r, c), src);
    }
    CP_COMMIT();

    float m_i[2] = {-INFINITY, -INFINITY}, l_i[2] = {0.f, 0.f};
    float oacc[8][4];
#pragma unroll
    for (int ni = 0; ni < 8; ++ni)
#pragma unroll
        for (int r = 0; r < 4; ++r) oacc[ni][r] = 0.f;

    const int a_r = wid * 16 + (lane & 15);
    const int a_c = lane >> 4;
    const int b_r = (lane & 7) + ((lane >> 4) << 3);
    const int b_c = (lane >> 3) & 1;
    const int v_ro = ((lane >> 3) & 1) * 8 + (lane & 7);
    const int v_co = lane >> 4;

#define LOAD_KV(kt, stg)                                                        \
    {                                                                           \
        const uint32_t sbase = KV0 + (uint32_t)(stg) * AKV_STAGE;               \
        _Pragma("unroll")                                                       \
        for (int i = 0; i < 8; ++i) {                                           \
            int t = tid + i * 256;                                              \
            int tt = t >> 9;                                                    \
            int w = t & 511;                                                    \
            int r = w >> 3, c = w & 7;                                          \
            const __nv_bfloat16* src =                                          \
                ((tt == 0) ? Khi : (tt == 1) ? Klo : (tt == 2) ? Vhi : Vlo)     \
                + (size_t)(b * SEQ + (kt) + r) * DMODEL + h * DHEAD + c * 8;    \
            cp_async16(sbase + (uint32_t)tt * 8192 + swz128(r, c), src);        \
        }                                                                       \
        if (tid < 64)                                                           \
            msk[(stg) * 64 + tid] =                                             \
                (1.0f - mask[b * SEQ + (kt) + tid]) * NEG_INF_F;                \
        CP_COMMIT();                                                            \
    }

    LOAD_KV(0, 0);

    for (int kt = 0; kt < SEQ; kt += 64) {
        const int stg = (kt >> 6) & 1;
        const uint32_t Kh = KV0 + (uint32_t)stg * AKV_STAGE;
        const uint32_t Kl = Kh + 8192;
        const uint32_t Vh = Kh + 16384;
        const uint32_t Vl = Kh + 24576;
        const float* mrow = msk + stg * 64;

        if (kt + 64 < SEQ) {
            LOAD_KV(kt + 64, stg ^ 1);
            asm volatile("cp.async.wait_group 1;" ::: "memory");
        } else {
            asm volatile("cp.async.wait_group 0;" ::: "memory");
        }
        __syncthreads();

        // ---- S = Q K^T (3-pass), per-nt fragment consumption ----
        float sacc[8][4];
#pragma unroll
        for (int ni = 0; ni < 8; ++ni)
#pragma unroll
            for (int r = 0; r < 4; ++r) sacc[ni][r] = 0.f;

#pragma unroll
        for (int kk = 0; kk < 4; ++kk) {
            uint32_t qh[4], ql[4];
            uint32_t offA = swz128(a_r, kk * 2 + a_c);
            ldsm_x4(qh[0], qh[1], qh[2], qh[3], Qh + offA);
            ldsm_x4(ql[0], ql[1], ql[2], ql[3], Ql + offA);
#pragma unroll
            for (int nt = 0; nt < 4; ++nt) {
                uint32_t off = swz128(b_r + nt * 16, kk * 2 + b_c);
                uint32_t f[4];
                ldsm_x4(f[0], f[1], f[2], f[3], Kh + off);
                mma_bf16(sacc[nt*2],   qh, f);
                mma_bf16(sacc[nt*2+1], qh, f + 2);
                mma_bf16(sacc[nt*2],   ql, f);
                mma_bf16(sacc[nt*2+1], ql, f + 2);
                ldsm_x4(f[0], f[1], f[2], f[3], Kl + off);
                mma_bf16(sacc[nt*2],   qh, f);
                mma_bf16(sacc[nt*2+1], qh, f + 2);
            }
        }

        // additive mask
#pragma unroll
        for (int ni = 0; ni < 8; ++ni) {
            float ma = mrow[ni * 8 + qd * 2], mb = mrow[ni * 8 + qd * 2 + 1];
            sacc[ni][0] += ma; sacc[ni][1] += mb;
            sacc[ni][2] += ma; sacc[ni][3] += mb;
        }

        // ---- streaming softmax ----
#pragma unroll
        for (int hf = 0; hf < 2; ++hf) {
            float mx = -INFINITY;
#pragma unroll
            for (int ni = 0; ni < 8; ++ni)
                mx = fmaxf(mx, fmaxf(sacc[ni][hf*2], sacc[ni][hf*2+1]));
            mx = fmaxf(mx, __shfl_xor_sync(0xffffffffu, mx, 1));
            mx = fmaxf(mx, __shfl_xor_sync(0xffffffffu, mx, 2));
            float mnew = fmaxf(m_i[hf], mx);
            float rs = 0.f;
#pragma unroll
            for (int ni = 0; ni < 8; ++ni) {
                float e0 = __expf(sacc[ni][hf*2]   - mnew);
                float e1 = __expf(sacc[ni][hf*2+1] - mnew);
                sacc[ni][hf*2] = e0; sacc[ni][hf*2+1] = e1;
                rs += e0 + e1;
            }
            rs += __shfl_xor_sync(0xffffffffu, rs, 1);
            rs += __shfl_xor_sync(0xffffffffu, rs, 2);
            float sc = __expf(m_i[hf] - mnew);
            l_i[hf] = l_i[hf] * sc + rs;
            m_i[hf] = mnew;
#pragma unroll
            for (int ni = 0; ni < 8; ++ni) {
                oacc[ni][hf*2]   *= sc;
                oacc[ni][hf*2+1] *= sc;
            }
        }

        // ---- O += P V (3-pass), per-nt fragment consumption ----
#pragma unroll
        for (int kk = 0; kk < 4; ++kk) {
            uint32_t ph[4], pl[4];
            pack_split(sacc[2*kk][0],   sacc[2*kk][1],   ph[0], pl[0]);
            pack_split(sacc[2*kk][2],   sacc[2*kk][3],   ph[1], pl[1]);
            pack_split(sacc[2*kk+1][0], sacc[2*kk+1][1], ph[2], pl[2]);
            pack_split(sacc[2*kk+1][2], sacc[2*kk+1][3], ph[3], pl[3]);
#pragma unroll
            for (int nt = 0; nt < 4; ++nt) {
                uint32_t off = swz128(kk * 16 + v_ro, nt * 2 + v_co);
                uint32_t f[4];
                ldsm_x4_t(f[0], f[1], f[2], f[3], Vh + off);
                mma_bf16(oacc[nt*2],   ph, f);
                mma_bf16(oacc[nt*2+1], ph, f + 2);
                mma_bf16(oacc[nt*2],   pl, f);
                mma_bf16(oacc[nt*2+1], pl, f + 2);
                ldsm_x4_t(f[0], f[1], f[2], f[3], Vl + off);
                mma_bf16(oacc[nt*2],   ph, f);
                mma_bf16(oacc[nt*2+1], ph, f + 2);
            }
        }
        __syncthreads();
    }

    // ---- O /= l; write bf16 hi/lo ----
#pragma unroll
    for (int hf = 0; hf < 2; ++hf) {
        float inv = 1.0f / l_i[hf];
        int row = q0 + wid * 16 + g + hf * 8;
#pragma unroll
        for (int ni = 0; ni < 8; ++ni) {
            float x0 = oacc[ni][hf*2] * inv, x1 = oacc[ni][hf*2+1] * inv;
            uint32_t hi, lo;
            pack_split(x0, x1, hi, lo);
            size_t off = (size_t)(b * SEQ + row) * DMODEL + h * DHEAD + ni * 8 + qd * 2;
            *(uint32_t*)(Ohi + off) = hi;
            *(uint32_t*)(Olo + off) = lo;
        }
    }
#undef LOAD_KV
}

// ---------------------------------------------------------------------------
// Fused residual + LayerNorm: warp-per-row, no smem, no block barriers.
// ---------------------------------------------------------------------------
__global__ __launch_bounds__(256) void add_ln_kernel(
    const float* __restrict__ x, const float* __restrict__ y,
    const float* __restrict__ g, const float* __restrict__ beta,
    float* __restrict__ out,
    __nv_bfloat16* __restrict__ ohi, __nv_bfloat16* __restrict__ olo)
{
    const int warp = threadIdx.x >> 5, lane = threadIdx.x & 31;
    const int row = blockIdx.x * 8 + warp;
    const size_t base = (size_t)row * DMODEL;

    float v[32];
    float s = 0.f;
#pragma unroll
    for (int i = 0; i < 8; ++i) {
        int col = i * 128 + lane * 4;
        float4 xv = *(const float4*)(x + base + col);
        float4 yv = *(const float4*)(y + base + col);
        v[4*i+0] = xv.x + yv.x;
        v[4*i+1] = xv.y + yv.y;
        v[4*i+2] = xv.z + yv.z;
        v[4*i+3] = xv.w + yv.w;
        s += v[4*i+0] + v[4*i+1] + v[4*i+2] + v[4*i+3];
    }
#pragma unroll
    for (int o = 16; o > 0; o >>= 1) s += __shfl_xor_sync(0xffffffffu, s, o);
    const float mean = s * (1.0f / DMODEL);

    float s2 = 0.f;
#pragma unroll
    for (int i = 0; i < 32; ++i) {
        float d = v[i] - mean;
        s2 += d * d;
    }
#pragma unroll
    for (int o = 16; o > 0; o >>= 1) s2 += __shfl_xor_sync(0xffffffffu, s2, o);
    const float rstd = rsqrtf(s2 * (1.0f / DMODEL) + 1e-5f);

#pragma unroll
    for (int i = 0; i < 8; ++i) {
        int col = i * 128 + lane * 4;
        float4 gv = *(const float4*)(g + col);
        float4 bv = *(const float4*)(beta + col);
        float4 o4;
        o4.x = (v[4*i+0] - mean) * rstd * gv.x + bv.x;
        o4.y = (v[4*i+1] - mean) * rstd * gv.y + bv.y;
        o4.z = (v[4*i+2] - mean) * rstd * gv.z + bv.z;
        o4.w = (v[4*i+3] - mean) * rstd * gv.w + bv.w;
        *(float4*)(out + base + col) = o4;

        uint32_t h0, l0, h1, l1;
        pack_split(o4.x, o4.y, h0, l0);
        pack_split(o4.z, o4.w, h1, l1);
        *(uint32_t*)(ohi + base + col)     = h0;
        *(uint32_t*)(ohi + base + col + 2) = h1;
        *(uint32_t*)(olo + base + col)     = l0;
        *(uint32_t*)(olo + base + col + 2) = l1;
    }
}

// ---------------------------------------------------------------------------
// Launch (dual-stream: main = stream 0, s2 = weight splits) — R11 orchestration
// ---------------------------------------------------------------------------
extern "C" void kernel_launch(void* const* d_in, const int* in_sizes, int n_in,
                              void* d_out, int out_size)
{
    (void)in_sizes; (void)n_in; (void)out_size;

    const float* x    = (const float*)d_in[0];
    const float* mask = (const float*)d_in[1];
    const float* Wq   = (const float*)d_in[2];
    const float* bq   = (const float*)d_in[3];
    const float* Wk   = (const float*)d_in[4];
    const float* bk   = (const float*)d_in[5];
    const float* Wv   = (const float*)d_in[6];
    const float* bv   = (const float*)d_in[7];
    const float* Wo   = (const float*)d_in[8];
    const float* bo   = (const float*)d_in[9];
    const float* W1   = (const float*)d_in[10];
    const float* b1   = (const float*)d_in[11];
    const float* W2   = (const float*)d_in[12];
    const float* b2   = (const float*)d_in[13];
    const float* lng  = (const float*)d_in[14];
    const float* lnb  = (const float*)d_in[15];
    float* out = (float*)d_out;

    float *gx, *gy;
    __nv_bfloat16 *xhi, *xlo, *qhi, *qlo, *khi, *klo, *vhi, *vlo,
                  *ohi, *olo, *hhi, *hlo;
    __nv_bfloat16 *wqkvh, *wqkvl, *woh, *wol, *w1h, *w1l, *w2h, *w2l;
    cudaGetSymbolAddress((void**)&gx,  g_x);
    cudaGetSymbolAddress((void**)&gy,  g_y);
    cudaGetSymbolAddress((void**)&xhi, g_xhi);
    cudaGetSymbolAddress((void**)&xlo, g_xlo);
    cudaGetSymbolAddress((void**)&qhi, g_qhi);
    cudaGetSymbolAddress((void**)&qlo, g_qlo);
    cudaGetSymbolAddress((void**)&khi, g_khi);
    cudaGetSymbolAddress((void**)&klo, g_klo);
    cudaGetSymbolAddress((void**)&vhi, g_vhi);
    cudaGetSymbolAddress((void**)&vlo, g_vlo);
    cudaGetSymbolAddress((void**)&ohi, g_ohi);
    cudaGetSymbolAddress((void**)&olo, g_olo);
    cudaGetSymbolAddress((void**)&hhi, g_hhi);
    cudaGetSymbolAddress((void**)&hlo, g_hlo);
    cudaGetSymbolAddress((void**)&wqkvh, g_wqkv_hi);
    cudaGetSymbolAddress((void**)&wqkvl, g_wqkv_lo);
    cudaGetSymbolAddress((void**)&woh, g_wo_hi);
    cudaGetSymbolAddress((void**)&wol, g_wo_lo);
    cudaGetSymbolAddress((void**)&w1h, g_w1_hi);
    cudaGetSymbolAddress((void**)&w1l, g_w1_lo);
    cudaGetSymbolAddress((void**)&w2h, g_w2_hi);
    cudaGetSymbolAddress((void**)&w2l, g_w2_lo);

    static cudaStream_t s2 = nullptr;
    static cudaEvent_t evpool[64];
    static int attr_set = 0;
    if (!attr_set) {
        cudaFuncSetAttribute(mma_gemm_kernel,
                             cudaFuncAttributeMaxDynamicSharedMemorySize, GSMEM);
        cudaFuncSetAttribute(mma_gemm_qkv_kernel,
                             cudaFuncAttributeMaxDynamicSharedMemorySize, GSMEM);
        cudaFuncSetAttribute(attn_mma_kernel,
                             cudaFuncAttributeMaxDynamicSharedMemorySize, ATTN_SMEM);
        cudaStreamCreateWithFlags(&s2, cudaStreamNonBlocking);
        for (int i = 0; i < 64; ++i)
            cudaEventCreateWithFlags(&evpool[i], cudaEventDisableTiming);
        attr_set = 1;
    }
    int evn = 0;
#define EV() (evpool[evn++])

    const float qscale = 0.125f;
    dim3 gQKV(3 * DMODEL / 128, MROWS / 128);  // (24, 32)
    dim3 gProj(DMODEL / 128, MROWS / 128);     // (8, 32)
    dim3 gFF1(DFF / 128, MROWS / 128);         // (32, 32)
    dim3 gAttn(SEQ / 128, NHEAD, BATCH);       // (8, 16, 4)
    dim3 tT(32, 8);

    cudaEvent_t eFork = EV();
    cudaEventRecord(eFork, 0);
    cudaStreamWaitEvent(s2, eFork, 0);

    posenc_kernel<<<(SEQ * DMODEL + 255) / 256, 256>>>(x, gx, xhi, xlo);

    cudaEvent_t e_qkv_done = nullptr, e_wo_done = nullptr,
                e_ff1_done = nullptr, e_ff2_done = nullptr;

    for (int l = 0; l < NLAYER; ++l) {
        const float* wq = Wq + (size_t)l * DMODEL * DMODEL;
        const float* wk = Wk + (size_t)l * DMODEL * DMODEL;
        const float* wv = Wv + (size_t)l * DMODEL * DMODEL;
        const float* wo = Wo + (size_t)l * DMODEL * DMODEL;

        if (e_qkv_done) cudaStreamWaitEvent(s2, e_qkv_done, 0);
        split_wT_kernel<<<dim3(32,32), tT, 0, s2>>>(wq, wqkvh,               wqkvl,               DMODEL, DMODEL);
        split_wT_kernel<<<dim3(32,32), tT, 0, s2>>>(wk, wqkvh + 1024*1024,   wqkvl + 1024*1024,   DMODEL, DMODEL);
        split_wT_kernel<<<dim3(32,32), tT, 0, s2>>>(wv, wqkvh + 2*1024*1024, wqkvl + 2*1024*1024, DMODEL, DMODEL);
        cudaEvent_t e_sqkv = EV(); cudaEventRecord(e_sqkv, s2);

        if (e_wo_done) cudaStreamWaitEvent(s2, e_wo_done, 0);
        split_wT_kernel<<<dim3(32,32), tT, 0, s2>>>(wo, woh, wol, DMODEL, DMODEL);
        cudaEvent_t e_so = EV(); cudaEventRecord(e_so, s2);

        if (e_ff1_done) cudaStreamWaitEvent(s2, e_ff1_done, 0);
        split_wT_kernel<<<dim3(DFF/32, DMODEL/32), tT, 0, s2>>>(
            W1 + (size_t)l * DMODEL * DFF, w1h, w1l, DMODEL, DFF);
        cudaEvent_t e_s1 = EV(); cudaEventRecord(e_s1, s2);

        if (e_ff2_done) cudaStreamWaitEvent(s2, e_ff2_done, 0);
        split_wT_kernel<<<dim3(DMODEL/32, DFF/32), tT, 0, s2>>>(
            W2 + (size_t)l * DFF * DMODEL, w2h, w2l, DFF, DMODEL);
        cudaEvent_t e_s2e = EV(); cudaEventRecord(e_s2e, s2);

        cudaStreamWaitEvent(0, e_sqkv, 0);
        mma_gemm_qkv_kernel<<<gQKV, 256, GSMEM>>>(xhi, xlo, wqkvh, wqkvl,
            bq + (size_t)l * DMODEL, bk + (size_t)l * DMODEL, bv + (size_t)l * DMODEL,
            qhi, qlo, khi, klo, vhi, vlo, qscale);
        e_qkv_done = EV(); cudaEventRecord(e_qkv_done, 0);

        attn_mma_kernel<<<gAttn, 256, ATTN_SMEM>>>(qhi, qlo, khi, klo, vhi, vlo,
                                                   mask, ohi, olo);

        cudaStreamWaitEvent(0, e_so, 0);
        mma_gemm_kernel<<<gProj, 256, GSMEM>>>(ohi, olo, woh, wol,
            bo + (size_t)l * DMODEL, gy, nullptr, nullptr,
            MROWS, DMODEL, DMODEL, 1.0f, 0, 0);
        e_wo_done = EV(); cudaEventRecord(e_wo_done, 0);

        add_ln_kernel<<<MROWS / 8, 256>>>(gx, gy,
            lng + (size_t)(2 * l) * DMODEL, lnb + (size_t)(2 * l) * DMODEL,
            gx, xhi, xlo);

        cudaStreamWaitEvent(0, e_s1, 0);
        mma_gemm_kernel<<<gFF1, 256, GSMEM>>>(xhi, xlo, w1h, w1l,
            b1 + (size_t)l * DFF, nullptr, hhi, hlo,
            MROWS, DFF, DMODEL, 1.0f, 1, 1);
        e_ff1_done = EV(); cudaEventRecord(e_ff1_done, 0);

        cudaStreamWaitEvent(0, e_s2e, 0);
        mma_gemm_kernel<<<gProj, 256, GSMEM>>>(hhi, hlo, w2h, w2l,
            b2 + (size_t)l * DMODEL, gy, nullptr, nullptr,
            MROWS, DMODEL, DFF, 1.0f, 0, 0);
        e_ff2_done = EV(); cudaEventRecord(e_ff2_done, 0);

        float* ln_out = (l == NLAYER - 1) ? out : gx;
        add_ln_kernel<<<MROWS / 8, 256>>>(gx, gy,
            lng + (size_t)(2 * l + 1) * DMODEL, lnb + (size_t)(2 * l + 1) * DMODEL,
            ln_out, xhi, xlo);
    }

    cudaEvent_t eJoin = EV();
    cudaEventRecord(eJoin, s2);
    cudaStreamWaitEvent(0, eJoin, 0);
#undef EV
}

// round 14
// speedup vs baseline: 1.3828x; 1.3524x over previous
#include <cuda_runtime.h>
#include <cuda_bf16.h>
#include <cuda_fp16.h>
#include <math.h>
#include <stdint.h>

// Problem constants
#define NLAYER 6
#define NHEAD  16
#define DMODEL 1024
#define DHEAD  64
#define DFF    4096
#define BATCH  4
#define SEQ    1024
#define MROWS  (BATCH*SEQ)
#define NEG_INF_F (-100000000.0f)

// ---------------------------------------------------------------------------
// Scratch (static device globals; no allocation anywhere)
// ---------------------------------------------------------------------------
__device__ float g_x[MROWS*DMODEL];
__device__ float g_y[MROWS*DMODEL];
__device__ __half g_xh[MROWS*DMODEL];           // activation, single fp16
__device__ __half g_oh[MROWS*DMODEL];           // attention out, single fp16
__device__ __half g_hh[MROWS*DFF];              // ffn hidden, single fp16
// attention operands stay bf16 hi/lo (proven path)
__device__ __nv_bfloat16 g_qhi[MROWS*DMODEL], g_qlo[MROWS*DMODEL];
__device__ __nv_bfloat16 g_khi[MROWS*DMODEL], g_klo[MROWS*DMODEL];
__device__ __nv_bfloat16 g_vhi[MROWS*DMODEL], g_vlo[MROWS*DMODEL];
// weights: fp16 hi/lo split (~22 bits effective)
__device__ __half g_wqkv_hi[3*DMODEL*DMODEL], g_wqkv_lo[3*DMODEL*DMODEL];
__device__ __half g_wo_hi[DMODEL*DMODEL],     g_wo_lo[DMODEL*DMODEL];
__device__ __half g_w1_hi[DMODEL*DFF],        g_w1_lo[DMODEL*DFF];
__device__ __half g_w2_hi[DFF*DMODEL],        g_w2_lo[DFF*DMODEL];

// ---------------------------------------------------------------------------
// PTX helpers
// ---------------------------------------------------------------------------
__device__ __forceinline__ uint32_t smem_u32(const void* p) {
    uint32_t a;
    asm("{ .reg .u64 t; cvta.to.shared.u64 t, %1; cvt.u32.u64 %0, t; }" : "=r"(a) : "l"(p));
    return a;
}
__device__ __forceinline__ void cp_async16(uint32_t dst, const void* src) {
    asm volatile("cp.async.cg.shared.global [%0], [%1], 16;" :: "r"(dst), "l"(src) : "memory");
}
#define CP_COMMIT() asm volatile("cp.async.commit_group;" ::: "memory")

__device__ __forceinline__ void ldsm_x4(uint32_t& r0, uint32_t& r1, uint32_t& r2,
                                        uint32_t& r3, uint32_t addr) {
    asm volatile("ldmatrix.sync.aligned.m8n8.x4.shared.b16 {%0,%1,%2,%3}, [%4];"
                 : "=r"(r0), "=r"(r1), "=r"(r2), "=r"(r3) : "r"(addr));
}
__device__ __forceinline__ void ldsm_x4_t(uint32_t& r0, uint32_t& r1, uint32_t& r2,
                                          uint32_t& r3, uint32_t addr) {
    asm volatile("ldmatrix.sync.aligned.m8n8.x4.trans.shared.b16 {%0,%1,%2,%3}, [%4];"
                 : "=r"(r0), "=r"(r1), "=r"(r2), "=r"(r3) : "r"(addr));
}
__device__ __forceinline__ void mma_bf16(float* c, const uint32_t* a, const uint32_t* b) {
    asm volatile(
        "mma.sync.aligned.m16n8k16.row.col.f32.bf16.bf16.f32 "
        "{%0,%1,%2,%3}, {%4,%5,%6,%7}, {%8,%9}, {%0,%1,%2,%3};"
        : "+f"(c[0]), "+f"(c[1]), "+f"(c[2]), "+f"(c[3])
        : "r"(a[0]), "r"(a[1]), "r"(a[2]), "r"(a[3]), "r"(b[0]), "r"(b[1]));
}
__device__ __forceinline__ void mma_fp16(float* c, const uint32_t* a, const uint32_t* b) {
    asm volatile(
        "mma.sync.aligned.m16n8k16.row.col.f32.f16.f16.f32 "
        "{%0,%1,%2,%3}, {%4,%5,%6,%7}, {%8,%9}, {%0,%1,%2,%3};"
        : "+f"(c[0]), "+f"(c[1]), "+f"(c[2]), "+f"(c[3])
        : "r"(a[0]), "r"(a[1]), "r"(a[2]), "r"(a[3]), "r"(b[0]), "r"(b[1]));
}
// bf16 hi/lo pack (attention Q/K/V path)
__device__ __forceinline__ void pack_split(float x, float y, uint32_t& hi, uint32_t& lo) {
    __nv_bfloat16 hx = __float2bfloat16(x), hy = __float2bfloat16(y);
    __nv_bfloat162 H; H.x = hx; H.y = hy;
    __nv_bfloat162 L;
    L.x = __float2bfloat16(x - __bfloat162float(hx));
    L.y = __float2bfloat16(y - __bfloat162float(hy));
    hi = *(uint32_t*)&H; lo = *(uint32_t*)&L;
}
__device__ __forceinline__ uint32_t pack_h2(float x, float y) {
    __half2 h = __floats2half2_rn(x, y);
    return *(uint32_t*)&h;
}

// Swizzle for 64B-row tiles (GEMM: 32 x b16/row)
__device__ __forceinline__ uint32_t swz(int row, int c) {
    return (uint32_t)(((row >> 1) << 7) |
                      ((((((row & 1) << 2) | c)) ^ ((row >> 1) & 7)) << 4));
}
// Swizzle for 128B-row tiles (attention: 64 x b16/row)
__device__ __forceinline__ uint32_t swz128(int row, int c) {
    return (uint32_t)((row << 7) | (((c ^ (row & 7))) << 4));
}

// GEMM smem geometry: 128x128 tile, BK=32, 3 tiles (A, Bhi, Blo), TRIPLE buffered
#define T_TILE 8192
#define STAGEB (3*T_TILE)            // 24576
#define GSMEM  (3*STAGEB)            // 73728 (x2 CTAs = 144KB/SM)

// Attention smem (unchanged bf16 path)
#define AQ_TILE 16384
#define AKV_STAGE 32768
#define ATTN_SMEM (2*AQ_TILE + 2*AKV_STAGE + 512)

// ---------------------------------------------------------------------------
// Positional encoding (fp64) + fused fp16 round of the result
// ---------------------------------------------------------------------------
__global__ void posenc_kernel(const float* __restrict__ x, float* __restrict__ out,
                              __half* __restrict__ oh)
{
    int idx = blockIdx.x * blockDim.x + threadIdx.x;
    if (idx >= SEQ * DMODEL) return;
    int d = idx & (DMODEL - 1);
    int s = idx >> 10;
    int t = (d < DMODEL/2) ? d : d - DMODEL/2;
    const double log_inc = log(10000.0) / (double)(DMODEL/2 - 1);
    double arg = (double)s * exp(-(double)t * log_inc);
    float sig = (float)((d < DMODEL/2) ? sin(arg) : cos(arg));
#pragma unroll
    for (int b = 0; b < BATCH; ++b) {
        size_t off = (size_t)b * SEQ * DMODEL + idx;
        float v = x[off] + sig;
        out[off] = v;
        oh[off] = __float2half_rn(v);
    }
}

// ---------------------------------------------------------------------------
// W [K,N] fp32 -> transposed fp16 split: hiT, loT [N,K]
// ---------------------------------------------------------------------------
__global__ __launch_bounds__(256) void split_wT_kernel(
    const float* __restrict__ W, __half* __restrict__ hiT,
    __half* __restrict__ loT, int K, int N)
{
    __shared__ float t[32][33];
    int nx = blockIdx.x * 32;
    int ky = blockIdx.y * 32;
    int tx = threadIdx.x, ty = threadIdx.y;   // (32, 8)
#pragma unroll
    for (int i = 0; i < 4; ++i)
        t[ty + 8*i][tx] = W[(size_t)(ky + ty + 8*i) * N + nx + tx];
    __syncthreads();
#pragma unroll
    for (int i = 0; i < 4; ++i) {
        float v = t[tx][ty + 8*i];
        __half h = __float2half_rn(v);
        size_t o = (size_t)(nx + ty + 8*i) * K + ky + tx;
        hiT[o] = h;
        loT[o] = __float2half_rn(v - __half2float(h));
    }
}

// --- chunk loader: 3 tiles (A, Bhi, Blo) x 512 16B chunks / 256 thr = 6 ---
#define LOAD_CHUNK(k0, buf)                                                     \
    {                                                                           \
        _Pragma("unroll")                                                       \
        for (int i = 0; i < 6; ++i) {                                           \
            int t = tid + i * 256;                                              \
            int tile = t >> 9;                                                  \
            int w = t & 511;                                                    \
            int row = w >> 2;                                                   \
            int c = w & 3;                                                      \
            const __half* src =                                                 \
                (tile == 0) ? A : (tile == 1) ? Bhi : Blo;                      \
            int gr = ((tile == 0) ? m0 : n0) + row;                             \
            cp_async16((buf) + (uint32_t)tile * T_TILE + swz(row, c),           \
                       src + (size_t)gr * K + (k0) + c * 8);                    \
        }                                                                       \
        CP_COMMIT();                                                            \
    }

// --- MMA body (2-pass fp16: A*Bhi + A*Blo), 8 warps each 32x64 ---
#define MMA_BODY(buf)                                                            \
    {                                                                            \
        const uint32_t Aa = buf;                                                 \
        const uint32_t Bh = buf + T_TILE;                                        \
        const uint32_t Bl = buf + 2 * T_TILE;                                    \
        _Pragma("unroll")                                                        \
        for (int kk = 0; kk < 2; ++kk) {                                         \
            uint32_t a_f[2][4];                                                  \
            _Pragma("unroll")                                                    \
            for (int mi = 0; mi < 2; ++mi) {                                     \
                uint32_t off = swz(a_r + mi * 16, kk * 2 + a_h);                 \
                ldsm_x4(a_f[mi][0], a_f[mi][1], a_f[mi][2], a_f[mi][3], Aa + off); \
            }                                                                    \
            uint32_t bf[8][2];                                                   \
            _Pragma("unroll")                                                    \
            for (int nt = 0; nt < 4; ++nt) {                                     \
                uint32_t off = swz(b_r + nt * 16, kk * 2 + b_h);                 \
                uint32_t q0, q1, q2, q3;                                         \
                ldsm_x4(q0, q1, q2, q3, Bh + off);                               \
                bf[nt*2][0] = q0; bf[nt*2][1] = q1;                              \
                bf[nt*2+1][0] = q2; bf[nt*2+1][1] = q3;                          \
            }                                                                    \
            _Pragma("unroll")                                                    \
            for (int mi = 0; mi < 2; ++mi)                                       \
                _Pragma("unroll")                                                \
                for (int ni = 0; ni < 8; ++ni)                                   \
                    mma_fp16(acc[mi][ni], a_f[mi], bf[ni]);                      \
            _Pragma("unroll")                                                    \
            for (int nt = 0; nt < 4; ++nt) {                                     \
                uint32_t off = swz(b_r + nt * 16, kk * 2 + b_h);                 \
                uint32_t q0, q1, q2, q3;                                         \
                ldsm_x4(q0, q1, q2, q3, Bl + off);                               \
                bf[nt*2][0] = q0; bf[nt*2][1] = q1;                              \
                bf[nt*2+1][0] = q2; bf[nt*2+1][1] = q3;                          \
            }                                                                    \
            _Pragma("unroll")                                                    \
            for (int mi = 0; mi < 2; ++mi)                                       \
                _Pragma("unroll")                                                \
                for (int ni = 0; ni < 8; ++ni)                                   \
                    mma_fp16(acc[mi][ni], a_f[mi], bf[ni]);                      \
        }                                                                        \
    }

// --- 3-stage K-loop, single barrier per iteration ---
#define K_LOOP()                                                                 \
    LOAD_CHUNK(0, sb);                                                           \
    LOAD_CHUNK(32, sb + STAGEB);                                                 \
    for (int ch = 0; ch < nch; ++ch) {                                           \
        if (ch + 1 < nch) {                                                      \
            asm volatile("cp.async.wait_group 1;" ::: "memory");                 \
        } else {                                                                 \
            asm volatile("cp.async.wait_group 0;" ::: "memory");                 \
        }                                                                        \
        __syncthreads();                                                         \
        if (ch + 2 < nch) {                                                      \
            LOAD_CHUNK((ch + 2) * 32, sb + (uint32_t)((ch + 2) % 3) * STAGEB);   \
        }                                                                        \
        MMA_BODY(sb + (uint32_t)(ch % 3) * STAGEB)                               \
    }

// ---------------------------------------------------------------------------
// fp16 2-pass GEMM (Wo / FF1 / FF2): 128x128 tile, 256 thr, 2 CTA/SM.
// outmode 0: fp32 C. outmode 1: single fp16 Ch.
// ---------------------------------------------------------------------------
__global__ __launch_bounds__(256, 2) void mma_gemm_kernel(
    const __half* __restrict__ A,
    const __half* __restrict__ Bhi, const __half* __restrict__ Blo,
    const float* __restrict__ bias, float* __restrict__ C,
    __half* __restrict__ Ch,
    int M, int N, int K, float alpha, int relu, int outmode)
{
    extern __shared__ char smem[];
    const uint32_t sb = smem_u32(smem);
    const int tid = threadIdx.x;
    const int wid = tid >> 5, lane = tid & 31;
    const int m0 = blockIdx.y * 128, n0 = blockIdx.x * 128;
    const int wm = (wid & 3) * 32;
    const int wn = (wid >> 2) * 64;

    float acc[2][8][4];
#pragma unroll
    for (int mi = 0; mi < 2; ++mi)
#pragma unroll
        for (int ni = 0; ni < 8; ++ni)
#pragma unroll
            for (int r = 0; r < 4; ++r) acc[mi][ni][r] = 0.0f;

    const int nch = K >> 5;
    const int a_r = wm + (lane & 15);
    const int a_h = lane >> 4;
    const int b_r = wn + ((lane >> 4) << 3) + (lane & 7);
    const int b_h = (lane >> 3) & 1;

    K_LOOP()

    const int grp = lane >> 2, qid = lane & 3;
#pragma unroll
    for (int mi = 0; mi < 2; ++mi) {
        const int row0 = m0 + wm + mi * 16 + grp;
#pragma unroll
        for (int ni = 0; ni < 8; ++ni) {
            const int col = n0 + wn + ni * 8 + qid * 2;
            float2 b2 = *(const float2*)(bias + col);
            float2 u, v;
            u.x = (acc[mi][ni][0] + b2.x) * alpha;
            u.y = (acc[mi][ni][1] + b2.y) * alpha;
            v.x = (acc[mi][ni][2] + b2.x) * alpha;
            v.y = (acc[mi][ni][3] + b2.y) * alpha;
            if (relu) {
                u.x = fmaxf(u.x, 0.f); u.y = fmaxf(u.y, 0.f);
                v.x = fmaxf(v.x, 0.f); v.y = fmaxf(v.y, 0.f);
            }
            if (outmode == 0) {
                *(float2*)(C + (size_t)row0 * N + col) = u;
                *(float2*)(C + (size_t)(row0 + 8) * N + col) = v;
            } else {
                *(uint32_t*)(Ch + (size_t)row0 * N + col) = pack_h2(u.x, u.y);
                *(uint32_t*)(Ch + (size_t)(row0 + 8) * N + col) = pack_h2(v.x, v.y);
            }
        }
    }
}

// ---------------------------------------------------------------------------
// Batched QKV GEMM (fp16 2-pass): B packed [3072, 1024]. grid (24, 32).
// Epilogue packs bf16 hi/lo for the attention kernel.
// ---------------------------------------------------------------------------
__global__ __launch_bounds__(256, 2) void mma_gemm_qkv_kernel(
    const __half* __restrict__ A,
    const __half* __restrict__ Bhi, const __half* __restrict__ Blo,
    const float* __restrict__ bq, const float* __restrict__ bk,
    const float* __restrict__ bv,
    __nv_bfloat16* __restrict__ Qhi, __nv_bfloat16* __restrict__ Qlo,
    __nv_bfloat16* __restrict__ Khi, __nv_bfloat16* __restrict__ Klo,
    __nv_bfloat16* __restrict__ Vhi, __nv_bfloat16* __restrict__ Vlo,
    float qscale)
{
    extern __shared__ char smem[];
    const uint32_t sb = smem_u32(smem);
    const int tid = threadIdx.x;
    const int wid = tid >> 5, lane = tid & 31;
    const int m0 = blockIdx.y * 128, n0 = blockIdx.x * 128;
    const int K = DMODEL;
    const int wm = (wid & 3) * 32;
    const int wn = (wid >> 2) * 64;

    float acc[2][8][4];
#pragma unroll
    for (int mi = 0; mi < 2; ++mi)
#pragma unroll
        for (int ni = 0; ni < 8; ++ni)
#pragma unroll
            for (int r = 0; r < 4; ++r) acc[mi][ni][r] = 0.0f;

    const int nch = K >> 5;
    const int a_r = wm + (lane & 15);
    const int a_h = lane >> 4;
    const int b_r = wn + ((lane >> 4) << 3) + (lane & 7);
    const int b_h = (lane >> 3) & 1;

    K_LOOP()

    const int mid = n0 >> 10;
    const float* bsel = (mid == 0) ? bq : (mid == 1) ? bk : bv;
    __nv_bfloat16* hisel = (mid == 0) ? Qhi : (mid == 1) ? Khi : Vhi;
    __nv_bfloat16* losel = (mid == 0) ? Qlo : (mid == 1) ? Klo : Vlo;
    const float asel = (mid == 0) ? qscale : 1.0f;
    const int cb = mid << 10;

    const int grp = lane >> 2, qid = lane & 3;
#pragma unroll
    for (int mi = 0; mi < 2; ++mi) {
        const int row0 = m0 + wm + mi * 16 + grp;
#pragma unroll
        for (int ni = 0; ni < 8; ++ni) {
            const int col = n0 + wn + ni * 8 + qid * 2 - cb;
            float2 b2 = *(const float2*)(bsel + col);
            float2 u, v;
            u.x = (acc[mi][ni][0] + b2.x) * asel;
            u.y = (acc[mi][ni][1] + b2.y) * asel;
            v.x = (acc[mi][ni][2] + b2.x) * asel;
            v.y = (acc[mi][ni][3] + b2.y) * asel;
            uint32_t hi, lo;
            pack_split(u.x, u.y, hi, lo);
            *(uint32_t*)(hisel + (size_t)row0 * DMODEL + col) = hi;
            *(uint32_t*)(losel + (size_t)row0 * DMODEL + col) = lo;
            pack_split(v.x, v.y, hi, lo);
            *(uint32_t*)(hisel + (size_t)(row0 + 8) * DMODEL + col) = hi;
            *(uint32_t*)(losel + (size_t)(row0 + 8) * DMODEL + col) = lo;
        }
    }
}

// ---------------------------------------------------------------------------
// MMA flash attention (bf16 3-pass internals unchanged); O out = single fp16.
// ---------------------------------------------------------------------------
__global__ __launch_bounds__(256, 2) void attn_mma_kernel(
    const __nv_bfloat16* __restrict__ Qhi, const __nv_bfloat16* __restrict__ Qlo,
    const __nv_bfloat16* __restrict__ Khi, const __nv_bfloat16* __restrict__ Klo,
    const __nv_bfloat16* __restrict__ Vhi, const __nv_bfloat16* __restrict__ Vlo,
    const float* __restrict__ mask,
    __half* __restrict__ Oh)
{
    extern __shared__ char sm[];
    const uint32_t sb = smem_u32(sm);
    const uint32_t Qh = sb, Ql = sb + AQ_TILE;
    const uint32_t KV0 = sb + 2 * AQ_TILE;
    float* msk = (float*)(sm + 2 * AQ_TILE + 2 * AKV_STAGE);

    const int tid = threadIdx.x, wid = tid >> 5, lane = tid & 31;
    const int b = blockIdx.z, h = blockIdx.y, q0 = blockIdx.x * 128;
    const int g = lane >> 2, qd = lane & 3;

#pragma unroll
    for (int i = 0; i < 8; ++i) {
        int t = tid + i * 256;
        int tt = t >> 10;
        int w = t & 1023;
        int r = w >> 3, c = w & 7;
        const __nv_bfloat16* src = (tt ? Qlo : Qhi)
            + (size_t)(b * SEQ + q0 + r) * DMODEL + h * DHEAD + c * 8;
        cp_async16((tt ? Ql : Qh) + swz128(r, c), src);
    }
    CP_COMMIT();

    float m_i[2] = {-INFINITY, -INFINITY}, l_i[2] = {0.f, 0.f};
    float oacc[8][4];
#pragma unroll
    for (int ni = 0; ni < 8; ++ni)
#pragma unroll
        for (int r = 0; r < 4; ++r) oacc[ni][r] = 0.f;

    const int a_r = wid * 16 + (lane & 15);
    const int a_c = lane >> 4;
    const int b_r = (lane & 7) + ((lane >> 4) << 3);
    const int b_c = (lane >> 3) & 1;
    const int v_ro = ((lane >> 3) & 1) * 8 + (lane & 7);
    const int v_co = lane >> 4;

#define LOAD_KV(kt, stg)                                                        \
    {                                                                           \
        const uint32_t sbase = KV0 + (uint32_t)(stg) * AKV_STAGE;               \
        _Pragma("unroll")                                                       \
        for (int i = 0; i < 8; ++i) {                                           \
            int t = tid + i * 256;                                              \
            int tt = t >> 9;                                                    \
            int w = t & 511;                                                    \
            int r = w >> 3, c = w & 7;                                          \
            const __nv_bfloat16* src =                                          \
                ((tt == 0) ? Khi : (tt == 1) ? Klo : (tt == 2) ? Vhi : Vlo)     \
                + (size_t)(b * SEQ + (kt) + r) * DMODEL + h * DHEAD + c * 8;    \
            cp_async16(sbase + (uint32_t)tt * 8192 + swz128(r, c), src);        \
        }                                                                       \
        if (tid < 64)                                                           \
            msk[(stg) * 64 + tid] =                                             \
                (1.0f - mask[b * SEQ + (kt) + tid]) * NEG_INF_F;                \
        CP_COMMIT();                                                            \
    }

    LOAD_KV(0, 0);

    for (int kt = 0; kt < SEQ; kt += 64) {
        const int stg = (kt >> 6) & 1;
        const uint32_t Kh = KV0 + (uint32_t)stg * AKV_STAGE;
        const uint32_t Kl = Kh + 8192;
        const uint32_t Vh = Kh + 16384;
        const uint32_t Vl = Kh + 24576;
        const float* mrow = msk + stg * 64;

        if (kt + 64 < SEQ) {
            LOAD_KV(kt + 64, stg ^ 1);
            asm volatile("cp.async.wait_group 1;" ::: "memory");
        } else {
            asm volatile("cp.async.wait_group 0;" ::: "memory");
        }
        __syncthreads();

        float sacc[8][4];
#pragma unroll
        for (int ni = 0; ni < 8; ++ni)
#pragma unroll
            for (int r = 0; r < 4; ++r) sacc[ni][r] = 0.f;

#pragma unroll
        for (int kk = 0; kk < 4; ++kk) {
            uint32_t qh[4], ql[4];
            uint32_t offA = swz128(a_r, kk * 2 + a_c);
            ldsm_x4(qh[0], qh[1], qh[2], qh[3], Qh + offA);
            ldsm_x4(ql[0], ql[1], ql[2], ql[3], Ql + offA);
#pragma unroll
            for (int nt = 0; nt < 4; ++nt) {
                uint32_t off = swz128(b_r + nt * 16, kk * 2 + b_c);
                uint32_t f[4];
                ldsm_x4(f[0], f[1], f[2], f[3], Kh + off);
                mma_bf16(sacc[nt*2],   qh, f);
                mma_bf16(sacc[nt*2+1], qh, f + 2);
                mma_bf16(sacc[nt*2],   ql, f);
                mma_bf16(sacc[nt*2+1], ql, f + 2);
                ldsm_x4(f[0], f[1], f[2], f[3], Kl + off);
                mma_bf16(sacc[nt*2],   qh, f);
                mma_bf16(sacc[nt*2+1], qh, f + 2);
            }
        }

#pragma unroll
        for (int ni = 0; ni < 8; ++ni) {
            float ma = mrow[ni * 8 + qd * 2], mb = mrow[ni * 8 + qd * 2 + 1];
            sacc[ni][0] += ma; sacc[ni][1] += mb;
            sacc[ni][2] += ma; sacc[ni][3] += mb;
        }

#pragma unroll
        for (int hf = 0; hf < 2; ++hf) {
            float mx = -INFINITY;
#pragma unroll
            for (int ni = 0; ni < 8; ++ni)
                mx = fmaxf(mx, fmaxf(sacc[ni][hf*2], sacc[ni][hf*2+1]));
            mx = fmaxf(mx, __shfl_xor_sync(0xffffffffu, mx, 1));
            mx = fmaxf(mx, __shfl_xor_sync(0xffffffffu, mx, 2));
            float mnew = fmaxf(m_i[hf], mx);
            float rs = 0.f;
#pragma unroll
            for (int ni = 0; ni < 8; ++ni) {
                float e0 = __expf(sacc[ni][hf*2]   - mnew);
                float e1 = __expf(sacc[ni][hf*2+1] - mnew);
                sacc[ni][hf*2] = e0; sacc[ni][hf*2+1] = e1;
                rs += e0 + e1;
            }
            rs += __shfl_xor_sync(0xffffffffu, rs, 1);
            rs += __shfl_xor_sync(0xffffffffu, rs, 2);
            float sc = __expf(m_i[hf] - mnew);
            l_i[hf] = l_i[hf] * sc + rs;
            m_i[hf] = mnew;
#pragma unroll
            for (int ni = 0; ni < 8; ++ni) {
                oacc[ni][hf*2]   *= sc;
                oacc[ni][hf*2+1] *= sc;
            }
        }

#pragma unroll
        for (int kk = 0; kk < 4; ++kk) {
            uint32_t ph[4], pl[4];
            pack_split(sacc[2*kk][0],   sacc[2*kk][1],   ph[0], pl[0]);
            pack_split(sacc[2*kk][2],   sacc[2*kk][3],   ph[1], pl[1]);
            pack_split(sacc[2*kk+1][0], sacc[2*kk+1][1], ph[2], pl[2]);
            pack_split(sacc[2*kk+1][2], sacc[2*kk+1][3], ph[3], pl[3]);
#pragma unroll
            for (int nt = 0; nt < 4; ++nt) {
                uint32_t off = swz128(kk * 16 + v_ro, nt * 2 + v_co);
                uint32_t f[4];
                ldsm_x4_t(f[0], f[1], f[2], f[3], Vh + off);
                mma_bf16(oacc[nt*2],   ph, f);
                mma_bf16(oacc[nt*2+1], ph, f + 2);
                mma_bf16(oacc[nt*2],   pl, f);
                mma_bf16(oacc[nt*2+1], pl, f + 2);
                ldsm_x4_t(f[0], f[1], f[2], f[3], Vl + off);
                mma_bf16(oacc[nt*2],   ph, f);
                mma_bf16(oacc[nt*2+1], ph, f + 2);
            }
        }
        __syncthreads();
    }

    // ---- O /= l; write single fp16 ----
#pragma unroll
    for (int hf = 0; hf < 2; ++hf) {
        float inv = 1.0f / l_i[hf];
        int row = q0 + wid * 16 + g + hf * 8;
#pragma unroll
        for (int ni = 0; ni < 8; ++ni) {
            float x0 = oacc[ni][hf*2] * inv, x1 = oacc[ni][hf*2+1] * inv;
            size_t off = (size_t)(b * SEQ + row) * DMODEL + h * DHEAD + ni * 8 + qd * 2;
            *(uint32_t*)(Oh + off) = pack_h2(x0, x1);
        }
    }
#undef LOAD_KV
}

// ---------------------------------------------------------------------------
// Fused residual + LayerNorm: warp-per-row; writes fp32 out + single fp16 xh.
// ---------------------------------------------------------------------------
__global__ __launch_bounds__(256) void add_ln_kernel(
    const float* __restrict__ x, const float* __restrict__ y,
    const float* __restrict__ g, const float* __restrict__ beta,
    float* __restrict__ out, __half* __restrict__ oh)
{
    const int warp = threadIdx.x >> 5, lane = threadIdx.x & 31;
    const int row = blockIdx.x * 8 + warp;
    const size_t base = (size_t)row * DMODEL;

    float v[32];
    float s = 0.f;
#pragma unroll
    for (int i = 0; i < 8; ++i) {
        int col = i * 128 + lane * 4;
        float4 xv = *(const float4*)(x + base + col);
        float4 yv = *(const float4*)(y + base + col);
        v[4*i+0] = xv.x + yv.x;
        v[4*i+1] = xv.y + yv.y;
        v[4*i+2] = xv.z + yv.z;
        v[4*i+3] = xv.w + yv.w;
        s += v[4*i+0] + v[4*i+1] + v[4*i+2] + v[4*i+3];
    }
#pragma unroll
    for (int o = 16; o > 0; o >>= 1) s += __shfl_xor_sync(0xffffffffu, s, o);
    const float mean = s * (1.0f / DMODEL);

    float s2 = 0.f;
#pragma unroll
    for (int i = 0; i < 32; ++i) {
        float d = v[i] - mean;
        s2 += d * d;
    }
#pragma unroll
    for (int o = 16; o > 0; o >>= 1) s2 += __shfl_xor_sync(0xffffffffu, s2, o);
    const float rstd = rsqrtf(s2 * (1.0f / DMODEL) + 1e-5f);

#pragma unroll
    for (int i = 0; i < 8; ++i) {
        int col = i * 128 + lane * 4;
        float4 gv = *(const float4*)(g + col);
        float4 bv = *(const float4*)(beta + col);
        float4 o4;
        o4.x = (v[4*i+0] - mean) * rstd * gv.x + bv.x;
        o4.y = (v[4*i+1] - mean) * rstd * gv.y + bv.y;
        o4.z = (v[4*i+2] - mean) * rstd * gv.z + bv.z;
        o4.w = (v[4*i+3] - mean) * rstd * gv.w + bv.w;
        *(float4*)(out + base + col) = o4;
        *(uint32_t*)(oh + base + col)     = pack_h2(o4.x, o4.y);
        *(uint32_t*)(oh + base + col + 2) = pack_h2(o4.z, o4.w);
    }
}

// ---------------------------------------------------------------------------
// Launch (dual-stream: main = stream 0, s2 = weight splits) — R13 orchestration
// ---------------------------------------------------------------------------
extern "C" void kernel_launch(void* const* d_in, const int* in_sizes, int n_in,
                              void* d_out, int out_size)
{
    (void)in_sizes; (void)n_in; (void)out_size;

    const float* x    = (const float*)d_in[0];
    const float* mask = (const float*)d_in[1];
    const float* Wq   = (const float*)d_in[2];
    const float* bq   = (const float*)d_in[3];
    const float* Wk   = (const float*)d_in[4];
    const float* bk   = (const float*)d_in[5];
    const float* Wv   = (const float*)d_in[6];
    const float* bv   = (const float*)d_in[7];
    const float* Wo   = (const float*)d_in[8];
    const float* bo   = (const float*)d_in[9];
    const float* W1   = (const float*)d_in[10];
    const float* b1   = (const float*)d_in[11];
    const float* W2   = (const float*)d_in[12];
    const float* b2   = (const float*)d_in[13];
    const float* lng  = (const float*)d_in[14];
    const float* lnb  = (const float*)d_in[15];
    float* out = (float*)d_out;

    float *gx, *gy;
    __half *xh, *oh, *hh;
    __nv_bfloat16 *qhi, *qlo, *khi, *klo, *vhi, *vlo;
    __half *wqkvh, *wqkvl, *woh, *wol, *w1h, *w1l, *w2h, *w2l;
    cudaGetSymbolAddress((void**)&gx,  g_x);
    cudaGetSymbolAddress((void**)&gy,  g_y);
    cudaGetSymbolAddress((void**)&xh,  g_xh);
    cudaGetSymbolAddress((void**)&oh,  g_oh);
    cudaGetSymbolAddress((void**)&hh,  g_hh);
    cudaGetSymbolAddress((void**)&qhi, g_qhi);
    cudaGetSymbolAddress((void**)&qlo, g_qlo);
    cudaGetSymbolAddress((void**)&khi, g_khi);
    cudaGetSymbolAddress((void**)&klo, g_klo);
    cudaGetSymbolAddress((void**)&vhi, g_vhi);
    cudaGetSymbolAddress((void**)&vlo, g_vlo);
    cudaGetSymbolAddress((void**)&wqkvh, g_wqkv_hi);
    cudaGetSymbolAddress((void**)&wqkvl, g_wqkv_lo);
    cudaGetSymbolAddress((void**)&woh, g_wo_hi);
    cudaGetSymbolAddress((void**)&wol, g_wo_lo);
    cudaGetSymbolAddress((void**)&w1h, g_w1_hi);
    cudaGetSymbolAddress((void**)&w1l, g_w1_lo);
    cudaGetSymbolAddress((void**)&w2h, g_w2_hi);
    cudaGetSymbolAddress((void**)&w2l, g_w2_lo);

    static cudaStream_t s2 = nullptr;
    static cudaEvent_t evpool[64];
    static int attr_set = 0;
    if (!attr_set) {
        cudaFuncSetAttribute(mma_gemm_kernel,
                             cudaFuncAttributeMaxDynamicSharedMemorySize, GSMEM);
        cudaFuncSetAttribute(mma_gemm_qkv_kernel,
                             cudaFuncAttributeMaxDynamicSharedMemorySize, GSMEM);
        cudaFuncSetAttribute(attn_mma_kernel,
                             cudaFuncAttributeMaxDynamicSharedMemorySize, ATTN_SMEM);
        cudaStreamCreateWithFlags(&s2, cudaStreamNonBlocking);
        for (int i = 0; i < 64; ++i)
            cudaEventCreateWithFlags(&evpool[i], cudaEventDisableTiming);
        attr_set = 1;
    }
    int evn = 0;
#define EV() (evpool[evn++])

    const float qscale = 0.125f;
    dim3 gQKV(3 * DMODEL / 128, MROWS / 128);  // (24, 32)
    dim3 gProj(DMODEL / 128, MROWS / 128);     // (8, 32)
    dim3 gFF1(DFF / 128, MROWS / 128);         // (32, 32)
    dim3 gAttn(SEQ / 128, NHEAD, BATCH);       // (8, 16, 4)
    dim3 tT(32, 8);

    cudaEvent_t eFork = EV();
    cudaEventRecord(eFork, 0);
    cudaStreamWaitEvent(s2, eFork, 0);

    posenc_kernel<<<(SEQ * DMODEL + 255) / 256, 256>>>(x, gx, xh);

    cudaEvent_t e_qkv_done = nullptr, e_wo_done = nullptr,
                e_ff1_done = nullptr, e_ff2_done = nullptr;

    for (int l = 0; l < NLAYER; ++l) {
        const float* wq = Wq + (size_t)l * DMODEL * DMODEL;
        const float* wk = Wk + (size_t)l * DMODEL * DMODEL;
        const float* wv = Wv + (size_t)l * DMODEL * DMODEL;
        const float* wo = Wo + (size_t)l * DMODEL * DMODEL;

        if (e_qkv_done) cudaStreamWaitEvent(s2, e_qkv_done, 0);
        split_wT_kernel<<<dim3(32,32), tT, 0, s2>>>(wq, wqkvh,               wqkvl,               DMODEL, DMODEL);
        split_wT_kernel<<<dim3(32,32), tT, 0, s2>>>(wk, wqkvh + 1024*1024,   wqkvl + 1024*1024,   DMODEL, DMODEL);
        split_wT_kernel<<<dim3(32,32), tT, 0, s2>>>(wv, wqkvh + 2*1024*1024, wqkvl + 2*1024*1024, DMODEL, DMODEL);
        cudaEvent_t e_sqkv = EV(); cudaEventRecord(e_sqkv, s2);

        if (e_wo_done) cudaStreamWaitEvent(s2, e_wo_done, 0);
        split_wT_kernel<<<dim3(32,32), tT, 0, s2>>>(wo, woh, wol, DMODEL, DMODEL);
        cudaEvent_t e_so = EV(); cudaEventRecord(e_so, s2);

        if (e_ff1_done) cudaStreamWaitEvent(s2, e_ff1_done, 0);
        split_wT_kernel<<<dim3(DFF/32, DMODEL/32), tT, 0, s2>>>(
            W1 + (size_t)l * DMODEL * DFF, w1h, w1l, DMODEL, DFF);
        cudaEvent_t e_s1 = EV(); cudaEventRecord(e_s1, s2);

        if (e_ff2_done) cudaStreamWaitEvent(s2, e_ff2_done, 0);
        split_wT_kernel<<<dim3(DMODEL/32, DFF/32), tT, 0, s2>>>(
            W2 + (size_t)l * DFF * DMODEL, w2h, w2l, DFF, DMODEL);
        cudaEvent_t e_s2e = EV(); cudaEventRecord(e_s2e, s2);

        cudaStreamWaitEvent(0, e_sqkv, 0);
        mma_gemm_qkv_kernel<<<gQKV, 256, GSMEM>>>(xh, wqkvh, wqkvl,
            bq + (size_t)l * DMODEL, bk + (size_t)l * DMODEL, bv + (size_t)l * DMODEL,
            qhi, qlo, khi, klo, vhi, vlo, qscale);
        e_qkv_done = EV(); cudaEventRecord(e_qkv_done, 0);

        attn_mma_kernel<<<gAttn, 256, ATTN_SMEM>>>(qhi, qlo, khi, klo, vhi, vlo,
                                                   mask, oh);

        cudaStreamWaitEvent(0, e_so, 0);
        mma_gemm_kernel<<<gProj, 256, GSMEM>>>(oh, woh, wol,
            bo + (size_t)l * DMODEL, gy, nullptr,
            MROWS, DMODEL, DMODEL, 1.0f, 0, 0);
        e_wo_done = EV(); cudaEventRecord(e_wo_done, 0);

        add_ln_kernel<<<MROWS / 8, 256>>>(gx, gy,
            lng + (size_t)(2 * l) * DMODEL, lnb + (size_t)(2 * l) * DMODEL,
            gx, xh);

        cudaStreamWaitEvent(0, e_s1, 0);
        mma_gemm_kernel<<<gFF1, 256, GSMEM>>>(xh, w1h, w1l,
            b1 + (size_t)l * DFF, nullptr, hh,
            MROWS, DFF, DMODEL, 1.0f, 1, 1);
        e_ff1_done = EV(); cudaEventRecord(e_ff1_done, 0);

        cudaStreamWaitEvent(0, e_s2e, 0);
        mma_gemm_kernel<<<gProj, 256, GSMEM>>>(hh, w2h, w2l,
            b2 + (size_t)l * DMODEL, gy, nullptr,
            MROWS, DMODEL, DFF, 1.0f, 0, 0);
        e_ff2_done = EV(); cudaEventRecord(e_ff2_done, 0);

        float* ln_out = (l == NLAYER - 1) ? out : gx;
        add_ln_kernel<<<MROWS / 8, 256>>>(gx, gy,
            lng + (size_t)(2 * l + 1) * DMODEL, lnb + (size_t)(2 * l + 1) * DMODEL,
            ln_out, xh);
    }

    cudaEvent_t eJoin = EV();
    cudaEventRecord(eJoin, s2);
    cudaStreamWaitEvent(0, eJoin, 0);
#undef EV
}

// round 15
// speedup vs baseline: 1.4689x; 1.0623x over previous
#include <cuda_runtime.h>
#include <cuda_bf16.h>
#include <cuda_fp16.h>
#include <math.h>
#include <stdint.h>

// Problem constants
#define NLAYER 6
#define NHEAD  16
#define DMODEL 1024
#define DHEAD  64
#define DFF    4096
#define BATCH  4
#define SEQ    1024
#define MROWS  (BATCH*SEQ)
#define NEG_INF_F (-100000000.0f)

// ---------------------------------------------------------------------------
// Scratch (static device globals; no allocation anywhere)
// ---------------------------------------------------------------------------
__device__ float g_x[MROWS*DMODEL];
__device__ float g_y[MROWS*DMODEL];
__device__ __half g_xh[MROWS*DMODEL];           // activation, single fp16
__device__ __half g_oh[MROWS*DMODEL];           // attention out, single fp16
__device__ __half g_hh[MROWS*DFF];              // ffn hidden, single fp16
// attention operands: Q single fp16; K/V fp16 hi/lo
__device__ __half g_qh[MROWS*DMODEL];
__device__ __half g_khi[MROWS*DMODEL], g_klo[MROWS*DMODEL];
__device__ __half g_vhi[MROWS*DMODEL], g_vlo[MROWS*DMODEL];
// weights: fp16 hi/lo split (~22 bits effective)
__device__ __half g_wqkv_hi[3*DMODEL*DMODEL], g_wqkv_lo[3*DMODEL*DMODEL];
__device__ __half g_wo_hi[DMODEL*DMODEL],     g_wo_lo[DMODEL*DMODEL];
__device__ __half g_w1_hi[DMODEL*DFF],        g_w1_lo[DMODEL*DFF];
__device__ __half g_w2_hi[DFF*DMODEL],        g_w2_lo[DFF*DMODEL];

// ---------------------------------------------------------------------------
// PTX helpers
// ---------------------------------------------------------------------------
__device__ __forceinline__ uint32_t smem_u32(const void* p) {
    uint32_t a;
    asm("{ .reg .u64 t; cvta.to.shared.u64 t, %1; cvt.u32.u64 %0, t; }" : "=r"(a) : "l"(p));
    return a;
}
__device__ __forceinline__ void cp_async16(uint32_t dst, const void* src) {
    asm volatile("cp.async.cg.shared.global [%0], [%1], 16;" :: "r"(dst), "l"(src) : "memory");
}
#define CP_COMMIT() asm volatile("cp.async.commit_group;" ::: "memory")

__device__ __forceinline__ void ldsm_x4(uint32_t& r0, uint32_t& r1, uint32_t& r2,
                                        uint32_t& r3, uint32_t addr) {
    asm volatile("ldmatrix.sync.aligned.m8n8.x4.shared.b16 {%0,%1,%2,%3}, [%4];"
                 : "=r"(r0), "=r"(r1), "=r"(r2), "=r"(r3) : "r"(addr));
}
__device__ __forceinline__ void ldsm_x4_t(uint32_t& r0, uint32_t& r1, uint32_t& r2,
                                          uint32_t& r3, uint32_t addr) {
    asm volatile("ldmatrix.sync.aligned.m8n8.x4.trans.shared.b16 {%0,%1,%2,%3}, [%4];"
                 : "=r"(r0), "=r"(r1), "=r"(r2), "=r"(r3) : "r"(addr));
}
__device__ __forceinline__ void mma_fp16(float* c, const uint32_t* a, const uint32_t* b) {
    asm volatile(
        "mma.sync.aligned.m16n8k16.row.col.f32.f16.f16.f32 "
        "{%0,%1,%2,%3}, {%4,%5,%6,%7}, {%8,%9}, {%0,%1,%2,%3};"
        : "+f"(c[0]), "+f"(c[1]), "+f"(c[2]), "+f"(c[3])
        : "r"(a[0]), "r"(a[1]), "r"(a[2]), "r"(a[3]), "r"(b[0]), "r"(b[1]));
}
__device__ __forceinline__ uint32_t pack_h2(float x, float y) {
    __half2 h = __floats2half2_rn(x, y);
    return *(uint32_t*)&h;
}
// fp16 hi/lo pack
__device__ __forceinline__ void pack_split_h(float x, float y, uint32_t& hi, uint32_t& lo) {
    __half hx = __float2half_rn(x), hy = __float2half_rn(y);
    __half2 H; H.x = hx; H.y = hy;
    __half2 L;
    L.x = __float2half_rn(x - __half2float(hx));
    L.y = __float2half_rn(y - __half2float(hy));
    hi = *(uint32_t*)&H; lo = *(uint32_t*)&L;
}

// Swizzle for 64B-row tiles (GEMM: 32 x b16/row)
__device__ __forceinline__ uint32_t swz(int row, int c) {
    return (uint32_t)(((row >> 1) << 7) |
                      ((((((row & 1) << 2) | c)) ^ ((row >> 1) & 7)) << 4));
}
// Swizzle for 128B-row tiles (attention: 64 x b16/row)
__device__ __forceinline__ uint32_t swz128(int row, int c) {
    return (uint32_t)((row << 7) | (((c ^ (row & 7))) << 4));
}

// GEMM smem geometry: 128x128 tile, BK=32, 3 tiles (A, Bhi, Blo), TRIPLE buffered
#define T_TILE 8192
#define STAGEB (3*T_TILE)            // 24576
#define GSMEM  (3*STAGEB)            // 73728 (x2 CTAs = 144KB/SM)

// Attention smem: Q single (16KB) + K/V hi/lo double-buffered (2x32KB) + mask
#define AQ_TILE 16384                // 128 rows x 64 fp16
#define AKV_STAGE 32768              // Khi,Klo,Vhi,Vlo @ 8KB each
#define ATTN_SMEM (AQ_TILE + 2*AKV_STAGE + 512)   // 82432 (x2 = 161KB/SM)

// ---------------------------------------------------------------------------
// Positional encoding (fp64) + fused fp16 round of the result
// ---------------------------------------------------------------------------
__global__ void posenc_kernel(const float* __restrict__ x, float* __restrict__ out,
                              __half* __restrict__ oh)
{
    int idx = blockIdx.x * blockDim.x + threadIdx.x;
    if (idx >= SEQ * DMODEL) return;
    int d = idx & (DMODEL - 1);
    int s = idx >> 10;
    int t = (d < DMODEL/2) ? d : d - DMODEL/2;
    const double log_inc = log(10000.0) / (double)(DMODEL/2 - 1);
    double arg = (double)s * exp(-(double)t * log_inc);
    float sig = (float)((d < DMODEL/2) ? sin(arg) : cos(arg));
#pragma unroll
    for (int b = 0; b < BATCH; ++b) {
        size_t off = (size_t)b * SEQ * DMODEL + idx;
        float v = x[off] + sig;
        out[off] = v;
        oh[off] = __float2half_rn(v);
    }
}

// ---------------------------------------------------------------------------
// W [K,N] fp32 -> transposed fp16 split: hiT, loT [N,K]
// ---------------------------------------------------------------------------
__global__ __launch_bounds__(256) void split_wT_kernel(
    const float* __restrict__ W, __half* __restrict__ hiT,
    __half* __restrict__ loT, int K, int N)
{
    __shared__ float t[32][33];
    int nx = blockIdx.x * 32;
    int ky = blockIdx.y * 32;
    int tx = threadIdx.x, ty = threadIdx.y;   // (32, 8)
#pragma unroll
    for (int i = 0; i < 4; ++i)
        t[ty + 8*i][tx] = W[(size_t)(ky + ty + 8*i) * N + nx + tx];
    __syncthreads();
#pragma unroll
    for (int i = 0; i < 4; ++i) {
        float v = t[tx][ty + 8*i];
        __half h = __float2half_rn(v);
        size_t o = (size_t)(nx + ty + 8*i) * K + ky + tx;
        hiT[o] = h;
        loT[o] = __float2half_rn(v - __half2float(h));
    }
}

// --- chunk loader: 3 tiles (A, Bhi, Blo) x 512 16B chunks / 256 thr = 6 ---
#define LOAD_CHUNK(k0, buf)                                                     \
    {                                                                           \
        _Pragma("unroll")                                                       \
        for (int i = 0; i < 6; ++i) {                                           \
            int t = tid + i * 256;                                              \
            int tile = t >> 9;                                                  \
            int w = t & 511;                                                    \
            int row = w >> 2;                                                   \
            int c = w & 3;                                                      \
            const __half* src =                                                 \
                (tile == 0) ? A : (tile == 1) ? Bhi : Blo;                      \
            int gr = ((tile == 0) ? m0 : n0) + row;                             \
            cp_async16((buf) + (uint32_t)tile * T_TILE + swz(row, c),           \
                       src + (size_t)gr * K + (k0) + c * 8);                    \
        }                                                                       \
        CP_COMMIT();                                                            \
    }

// --- MMA body (2-pass fp16: A*Bhi + A*Blo), 8 warps each 32x64 ---
#define MMA_BODY(buf)                                                            \
    {                                                                            \
        const uint32_t Aa = buf;                                                 \
        const uint32_t Bh = buf + T_TILE;                                        \
        const uint32_t Bl = buf + 2 * T_TILE;                                    \
        _Pragma("unroll")                                                        \
        for (int kk = 0; kk < 2; ++kk) {                                         \
            uint32_t a_f[2][4];                                                  \
            _Pragma("unroll")                                                    \
            for (int mi = 0; mi < 2; ++mi) {                                     \
                uint32_t off = swz(a_r + mi * 16, kk * 2 + a_h);                 \
                ldsm_x4(a_f[mi][0], a_f[mi][1], a_f[mi][2], a_f[mi][3], Aa + off); \
            }                                                                    \
            uint32_t bf[8][2];                                                   \
            _Pragma("unroll")                                                    \
            for (int nt = 0; nt < 4; ++nt) {                                     \
                uint32_t off = swz(b_r + nt * 16, kk * 2 + b_h);                 \
                uint32_t q0, q1, q2, q3;                                         \
                ldsm_x4(q0, q1, q2, q3, Bh + off);                               \
                bf[nt*2][0] = q0; bf[nt*2][1] = q1;                              \
                bf[nt*2+1][0] = q2; bf[nt*2+1][1] = q3;                          \
            }                                                                    \
            _Pragma("unroll")                                                    \
            for (int mi = 0; mi < 2; ++mi)                                       \
                _Pragma("unroll")                                                \
                for (int ni = 0; ni < 8; ++ni)                                   \
                    mma_fp16(acc[mi][ni], a_f[mi], bf[ni]);                      \
            _Pragma("unroll")                                                    \
            for (int nt = 0; nt < 4; ++nt) {                                     \
                uint32_t off = swz(b_r + nt * 16, kk * 2 + b_h);                 \
                uint32_t q0, q1, q2, q3;                                         \
                ldsm_x4(q0, q1, q2, q3, Bl + off);                               \
                bf[nt*2][0] = q0; bf[nt*2][1] = q1;                              \
                bf[nt*2+1][0] = q2; bf[nt*2+1][1] = q3;                          \
            }                                                                    \
            _Pragma("unroll")                                                    \
            for (int mi = 0; mi < 2; ++mi)                                       \
                _Pragma("unroll")                                                \
                for (int ni = 0; ni < 8; ++ni)                                   \
                    mma_fp16(acc[mi][ni], a_f[mi], bf[ni]);                      \
        }                                                                        \
    }

// --- 3-stage K-loop, single barrier per iteration ---
#define K_LOOP()                                                                 \
    LOAD_CHUNK(0, sb);                                                           \
    LOAD_CHUNK(32, sb + STAGEB);                                                 \
    for (int ch = 0; ch < nch; ++ch) {                                           \
        if (ch + 1 < nch) {                                                      \
            asm volatile("cp.async.wait_group 1;" ::: "memory");                 \
        } else {                                                                 \
            asm volatile("cp.async.wait_group 0;" ::: "memory");                 \
        }                                                                        \
        __syncthreads();                                                         \
        if (ch + 2 < nch) {                                                      \
            LOAD_CHUNK((ch + 2) * 32, sb + (uint32_t)((ch + 2) % 3) * STAGEB);   \
        }                                                                        \
        MMA_BODY(sb + (uint32_t)(ch % 3) * STAGEB)                               \
    }

// ---------------------------------------------------------------------------
// fp16 2-pass GEMM (Wo / FF1 / FF2): 128x128 tile, 256 thr, 2 CTA/SM.
// outmode 0: fp32 C. outmode 1: single fp16 Ch.
// ---------------------------------------------------------------------------
__global__ __launch_bounds__(256, 2) void mma_gemm_kernel(
    const __half* __restrict__ A,
    const __half* __restrict__ Bhi, const __half* __restrict__ Blo,
    const float* __restrict__ bias, float* __restrict__ C,
    __half* __restrict__ Ch,
    int M, int N, int K, float alpha, int relu, int outmode)
{
    extern __shared__ char smem[];
    const uint32_t sb = smem_u32(smem);
    const int tid = threadIdx.x;
    const int wid = tid >> 5, lane = tid & 31;
    const int m0 = blockIdx.y * 128, n0 = blockIdx.x * 128;
    const int wm = (wid & 3) * 32;
    const int wn = (wid >> 2) * 64;

    float acc[2][8][4];
#pragma unroll
    for (int mi = 0; mi < 2; ++mi)
#pragma unroll
        for (int ni = 0; ni < 8; ++ni)
#pragma unroll
            for (int r = 0; r < 4; ++r) acc[mi][ni][r] = 0.0f;

    const int nch = K >> 5;
    const int a_r = wm + (lane & 15);
    const int a_h = lane >> 4;
    const int b_r = wn + ((lane >> 4) << 3) + (lane & 7);
    const int b_h = (lane >> 3) & 1;

    K_LOOP()

    const int grp = lane >> 2, qid = lane & 3;
#pragma unroll
    for (int mi = 0; mi < 2; ++mi) {
        const int row0 = m0 + wm + mi * 16 + grp;
#pragma unroll
        for (int ni = 0; ni < 8; ++ni) {
            const int col = n0 + wn + ni * 8 + qid * 2;
            float2 b2 = *(const float2*)(bias + col);
            float2 u, v;
            u.x = (acc[mi][ni][0] + b2.x) * alpha;
            u.y = (acc[mi][ni][1] + b2.y) * alpha;
            v.x = (acc[mi][ni][2] + b2.x) * alpha;
            v.y = (acc[mi][ni][3] + b2.y) * alpha;
            if (relu) {
                u.x = fmaxf(u.x, 0.f); u.y = fmaxf(u.y, 0.f);
                v.x = fmaxf(v.x, 0.f); v.y = fmaxf(v.y, 0.f);
            }
            if (outmode == 0) {
                *(float2*)(C + (size_t)row0 * N + col) = u;
                *(float2*)(C + (size_t)(row0 + 8) * N + col) = v;
            } else {
                *(uint32_t*)(Ch + (size_t)row0 * N + col) = pack_h2(u.x, u.y);
                *(uint32_t*)(Ch + (size_t)(row0 + 8) * N + col) = pack_h2(v.x, v.y);
            }
        }
    }
}

// ---------------------------------------------------------------------------
// Batched QKV GEMM (fp16 2-pass): B packed [3072, 1024]. grid (24, 32).
// Epilogue: Q single fp16 (scaled); K,V fp16 hi/lo.
// ---------------------------------------------------------------------------
__global__ __launch_bounds__(256, 2) void mma_gemm_qkv_kernel(
    const __half* __restrict__ A,
    const __half* __restrict__ Bhi, const __half* __restrict__ Blo,
    const float* __restrict__ bq, const float* __restrict__ bk,
    const float* __restrict__ bv,
    __half* __restrict__ Qh,
    __half* __restrict__ Khi, __half* __restrict__ Klo,
    __half* __restrict__ Vhi, __half* __restrict__ Vlo,
    float qscale)
{
    extern __shared__ char smem[];
    const uint32_t sb = smem_u32(smem);
    const int tid = threadIdx.x;
    const int wid = tid >> 5, lane = tid & 31;
    const int m0 = blockIdx.y * 128, n0 = blockIdx.x * 128;
    const int K = DMODEL;
    const int wm = (wid & 3) * 32;
    const int wn = (wid >> 2) * 64;

    float acc[2][8][4];
#pragma unroll
    for (int mi = 0; mi < 2; ++mi)
#pragma unroll
        for (int ni = 0; ni < 8; ++ni)
#pragma unroll
            for (int r = 0; r < 4; ++r) acc[mi][ni][r] = 0.0f;

    const int nch = K >> 5;
    const int a_r = wm + (lane & 15);
    const int a_h = lane >> 4;
    const int b_r = wn + ((lane >> 4) << 3) + (lane & 7);
    const int b_h = (lane >> 3) & 1;

    K_LOOP()

    const int mid = n0 >> 10;
    const float* bsel = (mid == 0) ? bq : (mid == 1) ? bk : bv;
    const int cb = mid << 10;

    const int grp = lane >> 2, qid = lane & 3;
#pragma unroll
    for (int mi = 0; mi < 2; ++mi) {
        const int row0 = m0 + wm + mi * 16 + grp;
#pragma unroll
        for (int ni = 0; ni < 8; ++ni) {
            const int col = n0 + wn + ni * 8 + qid * 2 - cb;
            float2 b2 = *(const float2*)(bsel + col);
            float2 u, v;
            u.x = acc[mi][ni][0] + b2.x;
            u.y = acc[mi][ni][1] + b2.y;
            v.x = acc[mi][ni][2] + b2.x;
            v.y = acc[mi][ni][3] + b2.y;
            size_t o0 = (size_t)row0 * DMODEL + col;
            size_t o1 = (size_t)(row0 + 8) * DMODEL + col;
            if (mid == 0) {
                *(uint32_t*)(Qh + o0) = pack_h2(u.x * qscale, u.y * qscale);
                *(uint32_t*)(Qh + o1) = pack_h2(v.x * qscale, v.y * qscale);
            } else {
                __half* hisel = (mid == 1) ? Khi : Vhi;
                __half* losel = (mid == 1) ? Klo : Vlo;
                uint32_t hi, lo;
                pack_split_h(u.x, u.y, hi, lo);
                *(uint32_t*)(hisel + o0) = hi;
                *(uint32_t*)(losel + o0) = lo;
                pack_split_h(v.x, v.y, hi, lo);
                *(uint32_t*)(hisel + o1) = hi;
                *(uint32_t*)(losel + o1) = lo;
            }
        }
    }
}

// ---------------------------------------------------------------------------
// MMA flash attention (fp16 2-pass): Q single, K/V hi/lo, P single.
// 8 warps, 128 q-rows per CTA, double-buffered K/V, 2 CTAs/SM.
// ---------------------------------------------------------------------------
__global__ __launch_bounds__(256, 2) void attn_mma_kernel(
    const __half* __restrict__ Qg,
    const __half* __restrict__ Khi, const __half* __restrict__ Klo,
    const __half* __restrict__ Vhi, const __half* __restrict__ Vlo,
    const float* __restrict__ mask,
    __half* __restrict__ Oh)
{
    extern __shared__ char sm[];
    const uint32_t sb = smem_u32(sm);
    const uint32_t Qt = sb;
    const uint32_t KV0 = sb + AQ_TILE;
    float* msk = (float*)(sm + AQ_TILE + 2 * AKV_STAGE);

    const int tid = threadIdx.x, wid = tid >> 5, lane = tid & 31;
    const int b = blockIdx.z, h = blockIdx.y, q0 = blockIdx.x * 128;
    const int g = lane >> 2, qd = lane & 3;

    // Load Q tile: 128 rows x 8 chunks = 1024 chunks / 256 = 4 each
#pragma unroll
    for (int i = 0; i < 4; ++i) {
        int t = tid + i * 256;
        int r = t >> 3, c = t & 7;
        const __half* src = Qg
            + (size_t)(b * SEQ + q0 + r) * DMODEL + h * DHEAD + c * 8;
        cp_async16(Qt + swz128(r, c), src);
    }
    CP_COMMIT();

    float m_i[2] = {-INFINITY, -INFINITY}, l_i[2] = {0.f, 0.f};
    float oacc[8][4];
#pragma unroll
    for (int ni = 0; ni < 8; ++ni)
#pragma unroll
        for (int r = 0; r < 4; ++r) oacc[ni][r] = 0.f;

    const int a_r = wid * 16 + (lane & 15);
    const int a_c = lane >> 4;
    const int b_r = (lane & 7) + ((lane >> 4) << 3);
    const int b_c = (lane >> 3) & 1;
    const int v_ro = ((lane >> 3) & 1) * 8 + (lane & 7);
    const int v_co = lane >> 4;

#define LOAD_KV(kt, stg)                                                        \
    {                                                                           \
        const uint32_t sbase = KV0 + (uint32_t)(stg) * AKV_STAGE;               \
        _Pragma("unroll")                                                       \
        for (int i = 0; i < 8; ++i) {                                           \
            int t = tid + i * 256;                                              \
            int tt = t >> 9;                                                    \
            int w = t & 511;                                                    \
            int r = w >> 3, c = w & 7;                                          \
            const __half* src =                                                 \
                ((tt == 0) ? Khi : (tt == 1) ? Klo : (tt == 2) ? Vhi : Vlo)     \
                + (size_t)(b * SEQ + (kt) + r) * DMODEL + h * DHEAD + c * 8;    \
            cp_async16(sbase + (uint32_t)tt * 8192 + swz128(r, c), src);        \
        }                                                                       \
        if (tid < 64)                                                           \
            msk[(stg) * 64 + tid] =                                             \
                (1.0f - mask[b * SEQ + (kt) + tid]) * NEG_INF_F;                \
        CP_COMMIT();                                                            \
    }

    LOAD_KV(0, 0);

    for (int kt = 0; kt < SEQ; kt += 64) {
        const int stg = (kt >> 6) & 1;
        const uint32_t Kh = KV0 + (uint32_t)stg * AKV_STAGE;
        const uint32_t Kl = Kh + 8192;
        const uint32_t Vh = Kh + 16384;
        const uint32_t Vl = Kh + 24576;
        const float* mrow = msk + stg * 64;

        if (kt + 64 < SEQ) {
            LOAD_KV(kt + 64, stg ^ 1);
            asm volatile("cp.async.wait_group 1;" ::: "memory");
        } else {
            asm volatile("cp.async.wait_group 0;" ::: "memory");
        }
        __syncthreads();

        // ---- S = Q (Khi + Klo) : 2-pass fp16 ----
        float sacc[8][4];
#pragma unroll
        for (int ni = 0; ni < 8; ++ni)
#pragma unroll
            for (int r = 0; r < 4; ++r) sacc[ni][r] = 0.f;

#pragma unroll
        for (int kk = 0; kk < 4; ++kk) {
            uint32_t qf[4];
            uint32_t offA = swz128(a_r, kk * 2 + a_c);
            ldsm_x4(qf[0], qf[1], qf[2], qf[3], Qt + offA);
#pragma unroll
            for (int nt = 0; nt < 4; ++nt) {
                uint32_t off = swz128(b_r + nt * 16, kk * 2 + b_c);
                uint32_t f[4];
                ldsm_x4(f[0], f[1], f[2], f[3], Kh + off);
                mma_fp16(sacc[nt*2],   qf, f);
                mma_fp16(sacc[nt*2+1], qf, f + 2);
                ldsm_x4(f[0], f[1], f[2], f[3], Kl + off);
                mma_fp16(sacc[nt*2],   qf, f);
                mma_fp16(sacc[nt*2+1], qf, f + 2);
            }
        }

        // additive mask
#pragma unroll
        for (int ni = 0; ni < 8; ++ni) {
            float ma = mrow[ni * 8 + qd * 2], mb = mrow[ni * 8 + qd * 2 + 1];
            sacc[ni][0] += ma; sacc[ni][1] += mb;
            sacc[ni][2] += ma; sacc[ni][3] += mb;
        }

        // ---- streaming softmax ----
#pragma unroll
        for (int hf = 0; hf < 2; ++hf) {
            float mx = -INFINITY;
#pragma unroll
            for (int ni = 0; ni < 8; ++ni)
                mx = fmaxf(mx, fmaxf(sacc[ni][hf*2], sacc[ni][hf*2+1]));
            mx = fmaxf(mx, __shfl_xor_sync(0xffffffffu, mx, 1));
            mx = fmaxf(mx, __shfl_xor_sync(0xffffffffu, mx, 2));
            float mnew = fmaxf(m_i[hf], mx);
            float rs = 0.f;
#pragma unroll
            for (int ni = 0; ni < 8; ++ni) {
                float e0 = __expf(sacc[ni][hf*2]   - mnew);
                float e1 = __expf(sacc[ni][hf*2+1] - mnew);
                sacc[ni][hf*2] = e0; sacc[ni][hf*2+1] = e1;
                rs += e0 + e1;
            }
            rs += __shfl_xor_sync(0xffffffffu, rs, 1);
            rs += __shfl_xor_sync(0xffffffffu, rs, 2);
            float sc = __expf(m_i[hf] - mnew);
            l_i[hf] = l_i[hf] * sc + rs;
            m_i[hf] = mnew;
#pragma unroll
            for (int ni = 0; ni < 8; ++ni) {
                oacc[ni][hf*2]   *= sc;
                oacc[ni][hf*2+1] *= sc;
            }
        }

        // ---- O += P (Vhi + Vlo) : 2-pass fp16, P single ----
#pragma unroll
        for (int kk = 0; kk < 4; ++kk) {
            uint32_t ph[4];
            ph[0] = pack_h2(sacc[2*kk][0],   sacc[2*kk][1]);
            ph[1] = pack_h2(sacc[2*kk][2],   sacc[2*kk][3]);
            ph[2] = pack_h2(sacc[2*kk+1][0], sacc[2*kk+1][1]);
            ph[3] = pack_h2(sacc[2*kk+1][2], sacc[2*kk+1][3]);
#pragma unroll
            for (int nt = 0; nt < 4; ++nt) {
                uint32_t off = swz128(kk * 16 + v_ro, nt * 2 + v_co);
                uint32_t f[4];
                ldsm_x4_t(f[0], f[1], f[2], f[3], Vh + off);
                mma_fp16(oacc[nt*2],   ph, f);
                mma_fp16(oacc[nt*2+1], ph, f + 2);
                ldsm_x4_t(f[0], f[1], f[2], f[3], Vl + off);
                mma_fp16(oacc[nt*2],   ph, f);
                mma_fp16(oacc[nt*2+1], ph, f + 2);
            }
        }
        __syncthreads();
    }

    // ---- O /= l; write single fp16 ----
#pragma unroll
    for (int hf = 0; hf < 2; ++hf) {
        float inv = 1.0f / l_i[hf];
        int row = q0 + wid * 16 + g + hf * 8;
#pragma unroll
        for (int ni = 0; ni < 8; ++ni) {
            float x0 = oacc[ni][hf*2] * inv, x1 = oacc[ni][hf*2+1] * inv;
            size_t off = (size_t)(b * SEQ + row) * DMODEL + h * DHEAD + ni * 8 + qd * 2;
            *(uint32_t*)(Oh + off) = pack_h2(x0, x1);
        }
    }
#undef LOAD_KV
}

// ---------------------------------------------------------------------------
// Fused residual + LayerNorm: warp-per-row; writes fp32 out + single fp16 xh.
// ---------------------------------------------------------------------------
__global__ __launch_bounds__(256) void add_ln_kernel(
    const float* __restrict__ x, const float* __restrict__ y,
    const float* __restrict__ g, const float* __restrict__ beta,
    float* __restrict__ out, __half* __restrict__ oh)
{
    const int warp = threadIdx.x >> 5, lane = threadIdx.x & 31;
    const int row = blockIdx.x * 8 + warp;
    const size_t base = (size_t)row * DMODEL;

    float v[32];
    float s = 0.f;
#pragma unroll
    for (int i = 0; i < 8; ++i) {
        int col = i * 128 + lane * 4;
        float4 xv = *(const float4*)(x + base + col);
        float4 yv = *(const float4*)(y + base + col);
        v[4*i+0] = xv.x + yv.x;
        v[4*i+1] = xv.y + yv.y;
        v[4*i+2] = xv.z + yv.z;
        v[4*i+3] = xv.w + yv.w;
        s += v[4*i+0] + v[4*i+1] + v[4*i+2] + v[4*i+3];
    }
#pragma unroll
    for (int o = 16; o > 0; o >>= 1) s += __shfl_xor_sync(0xffffffffu, s, o);
    const float mean = s * (1.0f / DMODEL);

    float s2 = 0.f;
#pragma unroll
    for (int i = 0; i < 32; ++i) {
        float d = v[i] - mean;
        s2 += d * d;
    }
#pragma unroll
    for (int o = 16; o > 0; o >>= 1) s2 += __shfl_xor_sync(0xffffffffu, s2, o);
    const float rstd = rsqrtf(s2 * (1.0f / DMODEL) + 1e-5f);

#pragma unroll
    for (int i = 0; i < 8; ++i) {
        int col = i * 128 + lane * 4;
        float4 gv = *(const float4*)(g + col);
        float4 bv = *(const float4*)(beta + col);
        float4 o4;
        o4.x = (v[4*i+0] - mean) * rstd * gv.x + bv.x;
        o4.y = (v[4*i+1] - mean) * rstd * gv.y + bv.y;
        o4.z = (v[4*i+2] - mean) * rstd * gv.z + bv.z;
        o4.w = (v[4*i+3] - mean) * rstd * gv.w + bv.w;
        *(float4*)(out + base + col) = o4;
        *(uint32_t*)(oh + base + col)     = pack_h2(o4.x, o4.y);
        *(uint32_t*)(oh + base + col + 2) = pack_h2(o4.z, o4.w);
    }
}

// ---------------------------------------------------------------------------
// Launch (dual-stream: main = stream 0, s2 = weight splits)
// ---------------------------------------------------------------------------
extern "C" void kernel_launch(void* const* d_in, const int* in_sizes, int n_in,
                              void* d_out, int out_size)
{
    (void)in_sizes; (void)n_in; (void)out_size;

    const float* x    = (const float*)d_in[0];
    const float* mask = (const float*)d_in[1];
    const float* Wq   = (const float*)d_in[2];
    const float* bq   = (const float*)d_in[3];
    const float* Wk   = (const float*)d_in[4];
    const float* bk   = (const float*)d_in[5];
    const float* Wv   = (const float*)d_in[6];
    const float* bv   = (const float*)d_in[7];
    const float* Wo   = (const float*)d_in[8];
    const float* bo   = (const float*)d_in[9];
    const float* W1   = (const float*)d_in[10];
    const float* b1   = (const float*)d_in[11];
    const float* W2   = (const float*)d_in[12];
    const float* b2   = (const float*)d_in[13];
    const float* lng  = (const float*)d_in[14];
    const float* lnb  = (const float*)d_in[15];
    float* out = (float*)d_out;

    float *gx, *gy;
    __half *xh, *oh, *hh, *qh, *khi, *klo, *vhi, *vlo;
    __half *wqkvh, *wqkvl, *woh, *wol, *w1h, *w1l, *w2h, *w2l;
    cudaGetSymbolAddress((void**)&gx,  g_x);
    cudaGetSymbolAddress((void**)&gy,  g_y);
    cudaGetSymbolAddress((void**)&xh,  g_xh);
    cudaGetSymbolAddress((void**)&oh,  g_oh);
    cudaGetSymbolAddress((void**)&hh,  g_hh);
    cudaGetSymbolAddress((void**)&qh,  g_qh);
    cudaGetSymbolAddress((void**)&khi, g_khi);
    cudaGetSymbolAddress((void**)&klo, g_klo);
    cudaGetSymbolAddress((void**)&vhi, g_vhi);
    cudaGetSymbolAddress((void**)&vlo, g_vlo);
    cudaGetSymbolAddress((void**)&wqkvh, g_wqkv_hi);
    cudaGetSymbolAddress((void**)&wqkvl, g_wqkv_lo);
    cudaGetSymbolAddress((void**)&woh, g_wo_hi);
    cudaGetSymbolAddress((void**)&wol, g_wo_lo);
    cudaGetSymbolAddress((void**)&w1h, g_w1_hi);
    cudaGetSymbolAddress((void**)&w1l, g_w1_lo);
    cudaGetSymbolAddress((void**)&w2h, g_w2_hi);
    cudaGetSymbolAddress((void**)&w2l, g_w2_lo);

    static cudaStream_t s2 = nullptr;
    static cudaEvent_t evpool[64];
    static int attr_set = 0;
    if (!attr_set) {
        cudaFuncSetAttribute(mma_gemm_kernel,
                             cudaFuncAttributeMaxDynamicSharedMemorySize, GSMEM);
        cudaFuncSetAttribute(mma_gemm_qkv_kernel,
                             cudaFuncAttributeMaxDynamicSharedMemorySize, GSMEM);
        cudaFuncSetAttribute(attn_mma_kernel,
                             cudaFuncAttributeMaxDynamicSharedMemorySize, ATTN_SMEM);
        cudaStreamCreateWithFlags(&s2, cudaStreamNonBlocking);
        for (int i = 0; i < 64; ++i)
            cudaEventCreateWithFlags(&evpool[i], cudaEventDisableTiming);
        attr_set = 1;
    }
    int evn = 0;
#define EV() (evpool[evn++])

    const float qscale = 0.125f;
    dim3 gQKV(3 * DMODEL / 128, MROWS / 128);  // (24, 32)
    dim3 gProj(DMODEL / 128, MROWS / 128);     // (8, 32)
    dim3 gFF1(DFF / 128, MROWS / 128);         // (32, 32)
    dim3 gAttn(SEQ / 128, NHEAD, BATCH);       // (8, 16, 4)
    dim3 tT(32, 8);

    cudaEvent_t eFork = EV();
    cudaEventRecord(eFork, 0);
    cudaStreamWaitEvent(s2, eFork, 0);

    posenc_kernel<<<(SEQ * DMODEL + 255) / 256, 256>>>(x, gx, xh);

    cudaEvent_t e_qkv_done = nullptr, e_wo_done = nullptr,
                e_ff1_done = nullptr, e_ff2_done = nullptr;

    for (int l = 0; l < NLAYER; ++l) {
        const float* wq = Wq + (size_t)l * DMODEL * DMODEL;
        const float* wk = Wk + (size_t)l * DMODEL * DMODEL;
        const float* wv = Wv + (size_t)l * DMODEL * DMODEL;
        const float* wo = Wo + (size_t)l * DMODEL * DMODEL;

        if (e_qkv_done) cudaStreamWaitEvent(s2, e_qkv_done, 0);
        split_wT_kernel<<<dim3(32,32), tT, 0, s2>>>(wq, wqkvh,               wqkvl,               DMODEL, DMODEL);
        split_wT_kernel<<<dim3(32,32), tT, 0, s2>>>(wk, wqkvh + 1024*1024,   wqkvl + 1024*1024,   DMODEL, DMODEL);
        split_wT_kernel<<<dim3(32,32), tT, 0, s2>>>(wv, wqkvh + 2*1024*1024, wqkvl + 2*1024*1024, DMODEL, DMODEL);
        cudaEvent_t e_sqkv = EV(); cudaEventRecord(e_sqkv, s2);

        if (e_wo_done) cudaStreamWaitEvent(s2, e_wo_done, 0);
        split_wT_kernel<<<dim3(32,32), tT, 0, s2>>>(wo, woh, wol, DMODEL, DMODEL);
        cudaEvent_t e_so = EV(); cudaEventRecord(e_so, s2);

        if (e_ff1_done) cudaStreamWaitEvent(s2, e_ff1_done, 0);
        split_wT_kernel<<<dim3(DFF/32, DMODEL/32), tT, 0, s2>>>(
            W1 + (size_t)l * DMODEL * DFF, w1h, w1l, DMODEL, DFF);
        cudaEvent_t e_s1 = EV(); cudaEventRecord(e_s1, s2);

        if (e_ff2_done) cudaStreamWaitEvent(s2, e_ff2_done, 0);
        split_wT_kernel<<<dim3(DMODEL/32, DFF/32), tT, 0, s2>>>(
            W2 + (size_t)l * DFF * DMODEL, w2h, w2l, DFF, DMODEL);
        cudaEvent_t e_s2e = EV(); cudaEventRecord(e_s2e, s2);

        cudaStreamWaitEvent(0, e_sqkv, 0);
        mma_gemm_qkv_kernel<<<gQKV, 256, GSMEM>>>(xh, wqkvh, wqkvl,
            bq + (size_t)l * DMODEL, bk + (size_t)l * DMODEL, bv + (size_t)l * DMODEL,
            qh, khi, klo, vhi, vlo, qscale);
        e_qkv_done = EV(); cudaEventRecord(e_qkv_done, 0);

        attn_mma_kernel<<<gAttn, 256, ATTN_SMEM>>>(qh, khi, klo, vhi, vlo,
                                                   mask, oh);

        cudaStreamWaitEvent(0, e_so, 0);
        mma_gemm_kernel<<<gProj, 256, GSMEM>>>(oh, woh, wol,
            bo + (size_t)l * DMODEL, gy, nullptr,
            MROWS, DMODEL, DMODEL, 1.0f, 0, 0);
        e_wo_done = EV(); cudaEventRecord(e_wo_done, 0);

        add_ln_kernel<<<MROWS / 8, 256>>>(gx, gy,
            lng + (size_t)(2 * l) * DMODEL, lnb + (size_t)(2 * l) * DMODEL,
            gx, xh);

        cudaStreamWaitEvent(0, e_s1, 0);
        mma_gemm_kernel<<<gFF1, 256, GSMEM>>>(xh, w1h, w1l,
            b1 + (size_t)l * DFF, nullptr, hh,
            MROWS, DFF, DMODEL, 1.0f, 1, 1);
        e_ff1_done = EV(); cudaEventRecord(e_ff1_done, 0);

        cudaStreamWaitEvent(0, e_s2e, 0);
        mma_gemm_kernel<<<gProj, 256, GSMEM>>>(hh, w2h, w2l,
            b2 + (size_t)l * DMODEL, gy, nullptr,
            MROWS, DMODEL, DFF, 1.0f, 0, 0);
        e_ff2_done = EV(); cudaEventRecord(e_ff2_done, 0);

        float* ln_out = (l == NLAYER - 1) ? out : gx;
        add_ln_kernel<<<MROWS / 8, 256>>>(gx, gy,
            lng + (size_t)(2 * l + 1) * DMODEL, lnb + (size_t)(2 * l + 1) * DMODEL,
            ln_out, xh);
    }

    cudaEvent_t eJoin = EV();
    cudaEventRecord(eJoin, s2);
    cudaStreamWaitEvent(0, eJoin, 0);
#undef EV
}

// round 16
// speedup vs baseline: 2.1143x; 1.4393x over previous
#include <cuda_runtime.h>
#include <cuda_bf16.h>
#include <cuda_fp16.h>
#include <math.h>
#include <stdint.h>

// Problem constants
#define NLAYER 6
#define NHEAD  16
#define DMODEL 1024
#define DHEAD  64
#define DFF    4096
#define BATCH  4
#define SEQ    1024
#define MROWS  (BATCH*SEQ)
#define NEG_INF_F (-100000000.0f)

// ---------------------------------------------------------------------------
// Scratch (static device globals; no allocation anywhere)
// ---------------------------------------------------------------------------
__device__ float g_x[MROWS*DMODEL];
__device__ float g_y[MROWS*DMODEL];
__device__ __half g_xh[MROWS*DMODEL];           // activation, single fp16
__device__ __half g_oh[MROWS*DMODEL];           // attention out, single fp16
__device__ __half g_hh[MROWS*DFF];              // ffn hidden, single fp16
// attention operands: Q single fp16; K/V fp16 hi/lo (proven error-free path)
__device__ __half g_qh[MROWS*DMODEL];
__device__ __half g_khi[MROWS*DMODEL], g_klo[MROWS*DMODEL];
__device__ __half g_vhi[MROWS*DMODEL], g_vlo[MROWS*DMODEL];
// weights: single fp16 (transposed)
__device__ __half g_wqkv[3*DMODEL*DMODEL];
__device__ __half g_wo[DMODEL*DMODEL];
__device__ __half g_w1[DMODEL*DFF];
__device__ __half g_w2[DFF*DMODEL];

// ---------------------------------------------------------------------------
// PTX helpers
// ---------------------------------------------------------------------------
__device__ __forceinline__ uint32_t smem_u32(const void* p) {
    uint32_t a;
    asm("{ .reg .u64 t; cvta.to.shared.u64 t, %1; cvt.u32.u64 %0, t; }" : "=r"(a) : "l"(p));
    return a;
}
__device__ __forceinline__ void cp_async16(uint32_t dst, const void* src) {
    asm volatile("cp.async.cg.shared.global [%0], [%1], 16;" :: "r"(dst), "l"(src) : "memory");
}
#define CP_COMMIT() asm volatile("cp.async.commit_group;" ::: "memory")

__device__ __forceinline__ void ldsm_x4(uint32_t& r0, uint32_t& r1, uint32_t& r2,
                                        uint32_t& r3, uint32_t addr) {
    asm volatile("ldmatrix.sync.aligned.m8n8.x4.shared.b16 {%0,%1,%2,%3}, [%4];"
                 : "=r"(r0), "=r"(r1), "=r"(r2), "=r"(r3) : "r"(addr));
}
__device__ __forceinline__ void ldsm_x4_t(uint32_t& r0, uint32_t& r1, uint32_t& r2,
                                          uint32_t& r3, uint32_t addr) {
    asm volatile("ldmatrix.sync.aligned.m8n8.x4.trans.shared.b16 {%0,%1,%2,%3}, [%4];"
                 : "=r"(r0), "=r"(r1), "=r"(r2), "=r"(r3) : "r"(addr));
}
__device__ __forceinline__ void mma_fp16(float* c, const uint32_t* a, const uint32_t* b) {
    asm volatile(
        "mma.sync.aligned.m16n8k16.row.col.f32.f16.f16.f32 "
        "{%0,%1,%2,%3}, {%4,%5,%6,%7}, {%8,%9}, {%0,%1,%2,%3};"
        : "+f"(c[0]), "+f"(c[1]), "+f"(c[2]), "+f"(c[3])
        : "r"(a[0]), "r"(a[1]), "r"(a[2]), "r"(a[3]), "r"(b[0]), "r"(b[1]));
}
__device__ __forceinline__ uint32_t pack_h2(float x, float y) {
    __half2 h = __floats2half2_rn(x, y);
    return *(uint32_t*)&h;
}
__device__ __forceinline__ void pack_split_h(float x, float y, uint32_t& hi, uint32_t& lo) {
    __half hx = __float2half_rn(x), hy = __float2half_rn(y);
    __half2 H; H.x = hx; H.y = hy;
    __half2 L;
    L.x = __float2half_rn(x - __half2float(hx));
    L.y = __float2half_rn(y - __half2float(hy));
    hi = *(uint32_t*)&H; lo = *(uint32_t*)&L;
}

// Swizzle for 64B-row tiles (GEMM: 32 x b16/row)
__device__ __forceinline__ uint32_t swz(int row, int c) {
    return (uint32_t)(((row >> 1) << 7) |
                      ((((((row & 1) << 2) | c)) ^ ((row >> 1) & 7)) << 4));
}
// Swizzle for 128B-row tiles (attention: 64 x b16/row)
__device__ __forceinline__ uint32_t swz128(int row, int c) {
    return (uint32_t)((row << 7) | (((c ^ (row & 7))) << 4));
}

// GEMM smem geometry: 128x128 tile, BK=32, 2 tiles (A, B), TRIPLE buffered
#define T_TILE 8192
#define STAGEB (2*T_TILE)            // 16384
#define GSMEM  (3*STAGEB)            // 49152 (x2 CTAs = 96KB/SM)

// Attention smem: Q single (16KB) + K/V hi/lo double-buffered (2x32KB) + mask
#define AQ_TILE 16384
#define AKV_STAGE 32768
#define ATTN_SMEM (AQ_TILE + 2*AKV_STAGE + 512)   // 82432

// ---------------------------------------------------------------------------
// Positional encoding (fp64) + fused fp16 round of the result
// ---------------------------------------------------------------------------
__global__ void posenc_kernel(const float* __restrict__ x, float* __restrict__ out,
                              __half* __restrict__ oh)
{
    int idx = blockIdx.x * blockDim.x + threadIdx.x;
    if (idx >= SEQ * DMODEL) return;
    int d = idx & (DMODEL - 1);
    int s = idx >> 10;
    int t = (d < DMODEL/2) ? d : d - DMODEL/2;
    const double log_inc = log(10000.0) / (double)(DMODEL/2 - 1);
    double arg = (double)s * exp(-(double)t * log_inc);
    float sig = (float)((d < DMODEL/2) ? sin(arg) : cos(arg));
#pragma unroll
    for (int b = 0; b < BATCH; ++b) {
        size_t off = (size_t)b * SEQ * DMODEL + idx;
        float v = x[off] + sig;
        out[off] = v;
        oh[off] = __float2half_rn(v);
    }
}

// ---------------------------------------------------------------------------
// W [K,N] fp32 -> transposed single fp16: wT [N,K]
// ---------------------------------------------------------------------------
__global__ __launch_bounds__(256) void convert_wT_kernel(
    const float* __restrict__ W, __half* __restrict__ wT, int K, int N)
{
    __shared__ float t[32][33];
    int nx = blockIdx.x * 32;
    int ky = blockIdx.y * 32;
    int tx = threadIdx.x, ty = threadIdx.y;   // (32, 8)
#pragma unroll
    for (int i = 0; i < 4; ++i)
        t[ty + 8*i][tx] = W[(size_t)(ky + ty + 8*i) * N + nx + tx];
    __syncthreads();
#pragma unroll
    for (int i = 0; i < 4; ++i)
        wT[(size_t)(nx + ty + 8*i) * K + ky + tx] = __float2half_rn(t[tx][ty + 8*i]);
}

// --- chunk loader: 2 tiles (A, B) x 512 16B chunks / 256 thr = 4 ---
#define LOAD_CHUNK(k0, buf)                                                     \
    {                                                                           \
        _Pragma("unroll")                                                       \
        for (int i = 0; i < 4; ++i) {                                           \
            int t = tid + i * 256;                                              \
            int tile = t >> 9;                                                  \
            int w = t & 511;                                                    \
            int row = w >> 2;                                                   \
            int c = w & 3;                                                      \
            const __half* src = tile ? B : A;                                   \
            int gr = (tile ? n0 : m0) + row;                                    \
            cp_async16((buf) + (uint32_t)tile * T_TILE + swz(row, c),           \
                       src + (size_t)gr * K + (k0) + c * 8);                    \
        }                                                                       \
        CP_COMMIT();                                                            \
    }

// --- MMA body (single-pass fp16: A*B), 8 warps each 32x64 ---
#define MMA_BODY(buf)                                                            \
    {                                                                            \
        const uint32_t Aa = buf;                                                 \
        const uint32_t Bb = buf + T_TILE;                                        \
        _Pragma("unroll")                                                        \
        for (int kk = 0; kk < 2; ++kk) {                                         \
            uint32_t a_f[2][4];                                                  \
            _Pragma("unroll")                                                    \
            for (int mi = 0; mi < 2; ++mi) {                                     \
                uint32_t off = swz(a_r + mi * 16, kk * 2 + a_h);                 \
                ldsm_x4(a_f[mi][0], a_f[mi][1], a_f[mi][2], a_f[mi][3], Aa + off); \
            }                                                                    \
            uint32_t bf[8][2];                                                   \
            _Pragma("unroll")                                                    \
            for (int nt = 0; nt < 4; ++nt) {                                     \
                uint32_t off = swz(b_r + nt * 16, kk * 2 + b_h);                 \
                uint32_t q0, q1, q2, q3;                                         \
                ldsm_x4(q0, q1, q2, q3, Bb + off);                               \
                bf[nt*2][0] = q0; bf[nt*2][1] = q1;                              \
                bf[nt*2+1][0] = q2; bf[nt*2+1][1] = q3;                          \
            }                                                                    \
            _Pragma("unroll")                                                    \
            for (int mi = 0; mi < 2; ++mi)                                       \
                _Pragma("unroll")                                                \
                for (int ni = 0; ni < 8; ++ni)                                   \
                    mma_fp16(acc[mi][ni], a_f[mi], bf[ni]);                      \
        }                                                                        \
    }

// --- 3-stage K-loop, single barrier per iteration ---
#define K_LOOP()                                                                 \
    LOAD_CHUNK(0, sb);                                                           \
    LOAD_CHUNK(32, sb + STAGEB);                                                 \
    for (int ch = 0; ch < nch; ++ch) {                                           \
        if (ch + 1 < nch) {                                                      \
            asm volatile("cp.async.wait_group 1;" ::: "memory");                 \
        } else {                                                                 \
            asm volatile("cp.async.wait_group 0;" ::: "memory");                 \
        }                                                                        \
        __syncthreads();                                                         \
        if (ch + 2 < nch) {                                                      \
            LOAD_CHUNK((ch + 2) * 32, sb + (uint32_t)((ch + 2) % 3) * STAGEB);   \
        }                                                                        \
        MMA_BODY(sb + (uint32_t)(ch % 3) * STAGEB)                               \
    }

// ---------------------------------------------------------------------------
// fp16 single-pass GEMM (Wo / FF1 / FF2): 128x128 tile, 256 thr, 2 CTA/SM.
// outmode 0: fp32 C. outmode 1: single fp16 Ch.
// ---------------------------------------------------------------------------
__global__ __launch_bounds__(256, 2) void mma_gemm_kernel(
    const __half* __restrict__ A, const __half* __restrict__ B,
    const float* __restrict__ bias, float* __restrict__ C,
    __half* __restrict__ Ch,
    int M, int N, int K, float alpha, int relu, int outmode)
{
    extern __shared__ char smem[];
    const uint32_t sb = smem_u32(smem);
    const int tid = threadIdx.x;
    const int wid = tid >> 5, lane = tid & 31;
    const int m0 = blockIdx.y * 128, n0 = blockIdx.x * 128;
    const int wm = (wid & 3) * 32;
    const int wn = (wid >> 2) * 64;

    float acc[2][8][4];
#pragma unroll
    for (int mi = 0; mi < 2; ++mi)
#pragma unroll
        for (int ni = 0; ni < 8; ++ni)
#pragma unroll
            for (int r = 0; r < 4; ++r) acc[mi][ni][r] = 0.0f;

    const int nch = K >> 5;
    const int a_r = wm + (lane & 15);
    const int a_h = lane >> 4;
    const int b_r = wn + ((lane >> 4) << 3) + (lane & 7);
    const int b_h = (lane >> 3) & 1;

    K_LOOP()

    const int grp = lane >> 2, qid = lane & 3;
#pragma unroll
    for (int mi = 0; mi < 2; ++mi) {
        const int row0 = m0 + wm + mi * 16 + grp;
#pragma unroll
        for (int ni = 0; ni < 8; ++ni) {
            const int col = n0 + wn + ni * 8 + qid * 2;
            float2 b2 = *(const float2*)(bias + col);
            float2 u, v;
            u.x = (acc[mi][ni][0] + b2.x) * alpha;
            u.y = (acc[mi][ni][1] + b2.y) * alpha;
            v.x = (acc[mi][ni][2] + b2.x) * alpha;
            v.y = (acc[mi][ni][3] + b2.y) * alpha;
            if (relu) {
                u.x = fmaxf(u.x, 0.f); u.y = fmaxf(u.y, 0.f);
                v.x = fmaxf(v.x, 0.f); v.y = fmaxf(v.y, 0.f);
            }
            if (outmode == 0) {
                *(float2*)(C + (size_t)row0 * N + col) = u;
                *(float2*)(C + (size_t)(row0 + 8) * N + col) = v;
            } else {
                *(uint32_t*)(Ch + (size_t)row0 * N + col) = pack_h2(u.x, u.y);
                *(uint32_t*)(Ch + (size_t)(row0 + 8) * N + col) = pack_h2(v.x, v.y);
            }
        }
    }
}

// ---------------------------------------------------------------------------
// Batched QKV GEMM (fp16 single-pass): B packed [3072, 1024]. grid (24, 32).
// Epilogue: Q single fp16 (scaled); K,V fp16 hi/lo for attention.
// ---------------------------------------------------------------------------
__global__ __launch_bounds__(256, 2) void mma_gemm_qkv_kernel(
    const __half* __restrict__ A, const __half* __restrict__ B,
    const float* __restrict__ bq, const float* __restrict__ bk,
    const float* __restrict__ bv,
    __half* __restrict__ Qh,
    __half* __restrict__ Khi, __half* __restrict__ Klo,
    __half* __restrict__ Vhi, __half* __restrict__ Vlo,
    float qscale)
{
    extern __shared__ char smem[];
    const uint32_t sb = smem_u32(smem);
    const int tid = threadIdx.x;
    const int wid = tid >> 5, lane = tid & 31;
    const int m0 = blockIdx.y * 128, n0 = blockIdx.x * 128;
    const int K = DMODEL;
    const int wm = (wid & 3) * 32;
    const int wn = (wid >> 2) * 64;

    float acc[2][8][4];
#pragma unroll
    for (int mi = 0; mi < 2; ++mi)
#pragma unroll
        for (int ni = 0; ni < 8; ++ni)
#pragma unroll
            for (int r = 0; r < 4; ++r) acc[mi][ni][r] = 0.0f;

    const int nch = K >> 5;
    const int a_r = wm + (lane & 15);
    const int a_h = lane >> 4;
    const int b_r = wn + ((lane >> 4) << 3) + (lane & 7);
    const int b_h = (lane >> 3) & 1;

    K_LOOP()

    const int mid = n0 >> 10;
    const float* bsel = (mid == 0) ? bq : (mid == 1) ? bk : bv;
    const int cb = mid << 10;

    const int grp = lane >> 2, qid = lane & 3;
#pragma unroll
    for (int mi = 0; mi < 2; ++mi) {
        const int row0 = m0 + wm + mi * 16 + grp;
#pragma unroll
        for (int ni = 0; ni < 8; ++ni) {
            const int col = n0 + wn + ni * 8 + qid * 2 - cb;
            float2 b2 = *(const float2*)(bsel + col);
            float2 u, v;
            u.x = acc[mi][ni][0] + b2.x;
            u.y = acc[mi][ni][1] + b2.y;
            v.x = acc[mi][ni][2] + b2.x;
            v.y = acc[mi][ni][3] + b2.y;
            size_t o0 = (size_t)row0 * DMODEL + col;
            size_t o1 = (size_t)(row0 + 8) * DMODEL + col;
            if (mid == 0) {
                *(uint32_t*)(Qh + o0) = pack_h2(u.x * qscale, u.y * qscale);
                *(uint32_t*)(Qh + o1) = pack_h2(v.x * qscale, v.y * qscale);
            } else {
                __half* hisel = (mid == 1) ? Khi : Vhi;
                __half* losel = (mid == 1) ? Klo : Vlo;
                uint32_t hi, lo;
                pack_split_h(u.x, u.y, hi, lo);
                *(uint32_t*)(hisel + o0) = hi;
                *(uint32_t*)(losel + o0) = lo;
                pack_split_h(v.x, v.y, hi, lo);
                *(uint32_t*)(hisel + o1) = hi;
                *(uint32_t*)(losel + o1) = lo;
            }
        }
    }
}

// ---------------------------------------------------------------------------
// MMA flash attention (fp16 2-pass K/V, Q/P single) — unchanged from R15
// ---------------------------------------------------------------------------
__global__ __launch_bounds__(256, 2) void attn_mma_kernel(
    const __half* __restrict__ Qg,
    const __half* __restrict__ Khi, const __half* __restrict__ Klo,
    const __half* __restrict__ Vhi, const __half* __restrict__ Vlo,
    const float* __restrict__ mask,
    __half* __restrict__ Oh)
{
    extern __shared__ char sm[];
    const uint32_t sb = smem_u32(sm);
    const uint32_t Qt = sb;
    const uint32_t KV0 = sb + AQ_TILE;
    float* msk = (float*)(sm + AQ_TILE + 2 * AKV_STAGE);

    const int tid = threadIdx.x, wid = tid >> 5, lane = tid & 31;
    const int b = blockIdx.z, h = blockIdx.y, q0 = blockIdx.x * 128;
    const int g = lane >> 2, qd = lane & 3;

#pragma unroll
    for (int i = 0; i < 4; ++i) {
        int t = tid + i * 256;
        int r = t >> 3, c = t & 7;
        const __half* src = Qg
            + (size_t)(b * SEQ + q0 + r) * DMODEL + h * DHEAD + c * 8;
        cp_async16(Qt + swz128(r, c), src);
    }
    CP_COMMIT();

    float m_i[2] = {-INFINITY, -INFINITY}, l_i[2] = {0.f, 0.f};
    float oacc[8][4];
#pragma unroll
    for (int ni = 0; ni < 8; ++ni)
#pragma unroll
        for (int r = 0; r < 4; ++r) oacc[ni][r] = 0.f;

    const int a_r = wid * 16 + (lane & 15);
    const int a_c = lane >> 4;
    const int b_r = (lane & 7) + ((lane >> 4) << 3);
    const int b_c = (lane >> 3) & 1;
    const int v_ro = ((lane >> 3) & 1) * 8 + (lane & 7);
    const int v_co = lane >> 4;

#define LOAD_KV(kt, stg)                                                        \
    {                                                                           \
        const uint32_t sbase = KV0 + (uint32_t)(stg) * AKV_STAGE;               \
        _Pragma("unroll")                                                       \
        for (int i = 0; i < 8; ++i) {                                           \
            int t = tid + i * 256;                                              \
            int tt = t >> 9;                                                    \
            int w = t & 511;                                                    \
            int r = w >> 3, c = w & 7;                                          \
            const __half* src =                                                 \
                ((tt == 0) ? Khi : (tt == 1) ? Klo : (tt == 2) ? Vhi : Vlo)     \
                + (size_t)(b * SEQ + (kt) + r) * DMODEL + h * DHEAD + c * 8;    \
            cp_async16(sbase + (uint32_t)tt * 8192 + swz128(r, c), src);        \
        }                                                                       \
        if (tid < 64)                                                           \
            msk[(stg) * 64 + tid] =                                             \
                (1.0f - mask[b * SEQ + (kt) + tid]) * NEG_INF_F;                \
        CP_COMMIT();                                                            \
    }

    LOAD_KV(0, 0);

    for (int kt = 0; kt < SEQ; kt += 64) {
        const int stg = (kt >> 6) & 1;
        const uint32_t Kh = KV0 + (uint32_t)stg * AKV_STAGE;
        const uint32_t Kl = Kh + 8192;
        const uint32_t Vh = Kh + 16384;
        const uint32_t Vl = Kh + 24576;
        const float* mrow = msk + stg * 64;

        if (kt + 64 < SEQ) {
            LOAD_KV(kt + 64, stg ^ 1);
            asm volatile("cp.async.wait_group 1;" ::: "memory");
        } else {
            asm volatile("cp.async.wait_group 0;" ::: "memory");
        }
        __syncthreads();

        float sacc[8][4];
#pragma unroll
        for (int ni = 0; ni < 8; ++ni)
#pragma unroll
            for (int r = 0; r < 4; ++r) sacc[ni][r] = 0.f;

#pragma unroll
        for (int kk = 0; kk < 4; ++kk) {
            uint32_t qf[4];
            uint32_t offA = swz128(a_r, kk * 2 + a_c);
            ldsm_x4(qf[0], qf[1], qf[2], qf[3], Qt + offA);
#pragma unroll
            for (int nt = 0; nt < 4; ++nt) {
                uint32_t off = swz128(b_r + nt * 16, kk * 2 + b_c);
                uint32_t f[4];
                ldsm_x4(f[0], f[1], f[2], f[3], Kh + off);
                mma_fp16(sacc[nt*2],   qf, f);
                mma_fp16(sacc[nt*2+1], qf, f + 2);
                ldsm_x4(f[0], f[1], f[2], f[3], Kl + off);
                mma_fp16(sacc[nt*2],   qf, f);
                mma_fp16(sacc[nt*2+1], qf, f + 2);
            }
        }

#pragma unroll
        for (int ni = 0; ni < 8; ++ni) {
            float ma = mrow[ni * 8 + qd * 2], mb = mrow[ni * 8 + qd * 2 + 1];
            sacc[ni][0] += ma; sacc[ni][1] += mb;
            sacc[ni][2] += ma; sacc[ni][3] += mb;
        }

#pragma unroll
        for (int hf = 0; hf < 2; ++hf) {
            float mx = -INFINITY;
#pragma unroll
            for (int ni = 0; ni < 8; ++ni)
                mx = fmaxf(mx, fmaxf(sacc[ni][hf*2], sacc[ni][hf*2+1]));
            mx = fmaxf(mx, __shfl_xor_sync(0xffffffffu, mx, 1));
            mx = fmaxf(mx, __shfl_xor_sync(0xffffffffu, mx, 2));
            float mnew = fmaxf(m_i[hf], mx);
            float rs = 0.f;
#pragma unroll
            for (int ni = 0; ni < 8; ++ni) {
                float e0 = __expf(sacc[ni][hf*2]   - mnew);
                float e1 = __expf(sacc[ni][hf*2+1] - mnew);
                sacc[ni][hf*2] = e0; sacc[ni][hf*2+1] = e1;
                rs += e0 + e1;
            }
            rs += __shfl_xor_sync(0xffffffffu, rs, 1);
            rs += __shfl_xor_sync(0xffffffffu, rs, 2);
            float sc = __expf(m_i[hf] - mnew);
            l_i[hf] = l_i[hf] * sc + rs;
            m_i[hf] = mnew;
#pragma unroll
            for (int ni = 0; ni < 8; ++ni) {
                oacc[ni][hf*2]   *= sc;
                oacc[ni][hf*2+1] *= sc;
            }
        }

#pragma unroll
        for (int kk = 0; kk < 4; ++kk) {
            uint32_t ph[4];
            ph[0] = pack_h2(sacc[2*kk][0],   sacc[2*kk][1]);
            ph[1] = pack_h2(sacc[2*kk][2],   sacc[2*kk][3]);
            ph[2] = pack_h2(sacc[2*kk+1][0], sacc[2*kk+1][1]);
            ph[3] = pack_h2(sacc[2*kk+1][2], sacc[2*kk+1][3]);
#pragma unroll
            for (int nt = 0; nt < 4; ++nt) {
                uint32_t off = swz128(kk * 16 + v_ro, nt * 2 + v_co);
                uint32_t f[4];
                ldsm_x4_t(f[0], f[1], f[2], f[3], Vh + off);
                mma_fp16(oacc[nt*2],   ph, f);
                mma_fp16(oacc[nt*2+1], ph, f + 2);
                ldsm_x4_t(f[0], f[1], f[2], f[3], Vl + off);
                mma_fp16(oacc[nt*2],   ph, f);
                mma_fp16(oacc[nt*2+1], ph, f + 2);
            }
        }
        __syncthreads();
    }

#pragma unroll
    for (int hf = 0; hf < 2; ++hf) {
        float inv = 1.0f / l_i[hf];
        int row = q0 + wid * 16 + g + hf * 8;
#pragma unroll
        for (int ni = 0; ni < 8; ++ni) {
            float x0 = oacc[ni][hf*2] * inv, x1 = oacc[ni][hf*2+1] * inv;
            size_t off = (size_t)(b * SEQ + row) * DMODEL + h * DHEAD + ni * 8 + qd * 2;
            *(uint32_t*)(Oh + off) = pack_h2(x0, x1);
        }
    }
#undef LOAD_KV
}

// ---------------------------------------------------------------------------
// Fused residual + LayerNorm: warp-per-row; writes fp32 out + single fp16 xh.
// ---------------------------------------------------------------------------
__global__ __launch_bounds__(256) void add_ln_kernel(
    const float* __restrict__ x, const float* __restrict__ y,
    const float* __restrict__ g, const float* __restrict__ beta,
    float* __restrict__ out, __half* __restrict__ oh)
{
    const int warp = threadIdx.x >> 5, lane = threadIdx.x & 31;
    const int row = blockIdx.x * 8 + warp;
    const size_t base = (size_t)row * DMODEL;

    float v[32];
    float s = 0.f;
#pragma unroll
    for (int i = 0; i < 8; ++i) {
        int col = i * 128 + lane * 4;
        float4 xv = *(const float4*)(x + base + col);
        float4 yv = *(const float4*)(y + base + col);
        v[4*i+0] = xv.x + yv.x;
        v[4*i+1] = xv.y + yv.y;
        v[4*i+2] = xv.z + yv.z;
        v[4*i+3] = xv.w + yv.w;
        s += v[4*i+0] + v[4*i+1] + v[4*i+2] + v[4*i+3];
    }
#pragma unroll
    for (int o = 16; o > 0; o >>= 1) s += __shfl_xor_sync(0xffffffffu, s, o);
    const float mean = s * (1.0f / DMODEL);

    float s2 = 0.f;
#pragma unroll
    for (int i = 0; i < 32; ++i) {
        float d = v[i] - mean;
        s2 += d * d;
    }
#pragma unroll
    for (int o = 16; o > 0; o >>= 1) s2 += __shfl_xor_sync(0xffffffffu, s2, o);
    const float rstd = rsqrtf(s2 * (1.0f / DMODEL) + 1e-5f);

#pragma unroll
    for (int i = 0; i < 8; ++i) {
        int col = i * 128 + lane * 4;
        float4 gv = *(const float4*)(g + col);
        float4 bv = *(const float4*)(beta + col);
        float4 o4;
        o4.x = (v[4*i+0] - mean) * rstd * gv.x + bv.x;
        o4.y = (v[4*i+1] - mean) * rstd * gv.y + bv.y;
        o4.z = (v[4*i+2] - mean) * rstd * gv.z + bv.z;
        o4.w = (v[4*i+3] - mean) * rstd * gv.w + bv.w;
        *(float4*)(out + base + col) = o4;
        *(uint32_t*)(oh + base + col)     = pack_h2(o4.x, o4.y);
        *(uint32_t*)(oh + base + col + 2) = pack_h2(o4.z, o4.w);
    }
}

// ---------------------------------------------------------------------------
// Launch (dual-stream: main = stream 0, s2 = weight converts)
// ---------------------------------------------------------------------------
extern "C" void kernel_launch(void* const* d_in, const int* in_sizes, int n_in,
                              void* d_out, int out_size)
{
    (void)in_sizes; (void)n_in; (void)out_size;

    const float* x    = (const float*)d_in[0];
    const float* mask = (const float*)d_in[1];
    const float* Wq   = (const float*)d_in[2];
    const float* bq   = (const float*)d_in[3];
    const float* Wk   = (const float*)d_in[4];
    const float* bk   = (const float*)d_in[5];
    const float* Wv   = (const float*)d_in[6];
    const float* bv   = (const float*)d_in[7];
    const float* Wo   = (const float*)d_in[8];
    const float* bo   = (const float*)d_in[9];
    const float* W1   = (const float*)d_in[10];
    const float* b1   = (const float*)d_in[11];
    const float* W2   = (const float*)d_in[12];
    const float* b2   = (const float*)d_in[13];
    const float* lng  = (const float*)d_in[14];
    const float* lnb  = (const float*)d_in[15];
    float* out = (float*)d_out;

    float *gx, *gy;
    __half *xh, *oh, *hh, *qh, *khi, *klo, *vhi, *vlo;
    __half *wqkv, *wo_, *w1_, *w2_;
    cudaGetSymbolAddress((void**)&gx,  g_x);
    cudaGetSymbolAddress((void**)&gy,  g_y);
    cudaGetSymbolAddress((void**)&xh,  g_xh);
    cudaGetSymbolAddress((void**)&oh,  g_oh);
    cudaGetSymbolAddress((void**)&hh,  g_hh);
    cudaGetSymbolAddress((void**)&qh,  g_qh);
    cudaGetSymbolAddress((void**)&khi, g_khi);
    cudaGetSymbolAddress((void**)&klo, g_klo);
    cudaGetSymbolAddress((void**)&vhi, g_vhi);
    cudaGetSymbolAddress((void**)&vlo, g_vlo);
    cudaGetSymbolAddress((void**)&wqkv, g_wqkv);
    cudaGetSymbolAddress((void**)&wo_, g_wo);
    cudaGetSymbolAddress((void**)&w1_, g_w1);
    cudaGetSymbolAddress((void**)&w2_, g_w2);

    static cudaStream_t s2 = nullptr;
    static cudaEvent_t evpool[64];
    static int attr_set = 0;
    if (!attr_set) {
        cudaFuncSetAttribute(mma_gemm_kernel,
                             cudaFuncAttributeMaxDynamicSharedMemorySize, GSMEM);
        cudaFuncSetAttribute(mma_gemm_qkv_kernel,
                             cudaFuncAttributeMaxDynamicSharedMemorySize, GSMEM);
        cudaFuncSetAttribute(attn_mma_kernel,
                             cudaFuncAttributeMaxDynamicSharedMemorySize, ATTN_SMEM);
        cudaStreamCreateWithFlags(&s2, cudaStreamNonBlocking);
        for (int i = 0; i < 64; ++i)
            cudaEventCreateWithFlags(&evpool[i], cudaEventDisableTiming);
        attr_set = 1;
    }
    int evn = 0;
#define EV() (evpool[evn++])

    const float qscale = 0.125f;
    dim3 gQKV(3 * DMODEL / 128, MROWS / 128);  // (24, 32)
    dim3 gProj(DMODEL / 128, MROWS / 128);     // (8, 32)
    dim3 gFF1(DFF / 128, MROWS / 128);         // (32, 32)
    dim3 gAttn(SEQ / 128, NHEAD, BATCH);       // (8, 16, 4)
    dim3 tT(32, 8);

    cudaEvent_t eFork = EV();
    cudaEventRecord(eFork, 0);
    cudaStreamWaitEvent(s2, eFork, 0);

    posenc_kernel<<<(SEQ * DMODEL + 255) / 256, 256>>>(x, gx, xh);

    cudaEvent_t e_qkv_done = nullptr, e_wo_done = nullptr,
                e_ff1_done = nullptr, e_ff2_done = nullptr;

    for (int l = 0; l < NLAYER; ++l) {
        const float* wq = Wq + (size_t)l * DMODEL * DMODEL;
        const float* wk = Wk + (size_t)l * DMODEL * DMODEL;
        const float* wv = Wv + (size_t)l * DMODEL * DMODEL;
        const float* wo = Wo + (size_t)l * DMODEL * DMODEL;

        if (e_qkv_done) cudaStreamWaitEvent(s2, e_qkv_done, 0);
        convert_wT_kernel<<<dim3(32,32), tT, 0, s2>>>(wq, wqkv,               DMODEL, DMODEL);
        convert_wT_kernel<<<dim3(32,32), tT, 0, s2>>>(wk, wqkv + 1024*1024,   DMODEL, DMODEL);
        convert_wT_kernel<<<dim3(32,32), tT, 0, s2>>>(wv, wqkv + 2*1024*1024, DMODEL, DMODEL);
        cudaEvent_t e_sqkv = EV(); cudaEventRecord(e_sqkv, s2);

        if (e_wo_done) cudaStreamWaitEvent(s2, e_wo_done, 0);
        convert_wT_kernel<<<dim3(32,32), tT, 0, s2>>>(wo, wo_, DMODEL, DMODEL);
        cudaEvent_t e_so = EV(); cudaEventRecord(e_so, s2);

        if (e_ff1_done) cudaStreamWaitEvent(s2, e_ff1_done, 0);
        convert_wT_kernel<<<dim3(DFF/32, DMODEL/32), tT, 0, s2>>>(
            W1 + (size_t)l * DMODEL * DFF, w1_, DMODEL, DFF);
        cudaEvent_t e_s1 = EV(); cudaEventRecord(e_s1, s2);

        if (e_ff2_done) cudaStreamWaitEvent(s2, e_ff2_done, 0);
        convert_wT_kernel<<<dim3(DMODEL/32, DFF/32), tT, 0, s2>>>(
            W2 + (size_t)l * DFF * DMODEL, w2_, DFF, DMODEL);
        cudaEvent_t e_s2e = EV(); cudaEventRecord(e_s2e, s2);

        cudaStreamWaitEvent(0, e_sqkv, 0);
        mma_gemm_qkv_kernel<<<gQKV, 256, GSMEM>>>(xh, wqkv,
            bq + (size_t)l * DMODEL, bk + (size_t)l * DMODEL, bv + (size_t)l * DMODEL,
            qh, khi, klo, vhi, vlo, qscale);
        e_qkv_done = EV(); cudaEventRecord(e_qkv_done, 0);

        attn_mma_kernel<<<gAttn, 256, ATTN_SMEM>>>(qh, khi, klo, vhi, vlo,
                                                   mask, oh);

        cudaStreamWaitEvent(0, e_so, 0);
        mma_gemm_kernel<<<gProj, 256, GSMEM>>>(oh, wo_,
            bo + (size_t)l * DMODEL, gy, nullptr,
            MROWS, DMODEL, DMODEL, 1.0f, 0, 0);
        e_wo_done = EV(); cudaEventRecord(e_wo_done, 0);

        add_ln_kernel<<<MROWS / 8, 256>>>(gx, gy,
            lng + (size_t)(2 * l) * DMODEL, lnb + (size_t)(2 * l) * DMODEL,
            gx, xh);

        cudaStreamWaitEvent(0, e_s1, 0);
        mma_gemm_kernel<<<gFF1, 256, GSMEM>>>(xh, w1_,
            b1 + (size_t)l * DFF, nullptr, hh,
            MROWS, DFF, DMODEL, 1.0f, 1, 1);
        e_ff1_done = EV(); cudaEventRecord(e_ff1_done, 0);

        cudaStreamWaitEvent(0, e_s2e, 0);
        mma_gemm_kernel<<<gProj, 256, GSMEM>>>(hh, w2_,
            b2 + (size_t)l * DMODEL, gy, nullptr,
            MROWS, DMODEL, DFF, 1.0f, 0, 0);
        e_ff2_done = EV(); cudaEventRecord(e_ff2_done, 0);

        float* ln_out = (l == NLAYER - 1) ? out : gx;
        add_ln_kernel<<<MROWS / 8, 256>>>(gx, gy,
            lng + (size_t)(2 * l + 1) * DMODEL, lnb + (size_t)(2 * l + 1) * DMODEL,
            ln_out, xh);
    }

    cudaEvent_t eJoin = EV();
    cudaEventRecord(eJoin, s2);
    cudaStreamWaitEvent(0, eJoin, 0);
#undef EV
}

// round 17
// speedup vs baseline: 2.3264x; 1.1003x over previous
#include <cuda_runtime.h>
#include <cuda_bf16.h>
#include <cuda_fp16.h>
#include <math.h>
#include <stdint.h>

// Problem constants
#define NLAYER 6
#define NHEAD  16
#define DMODEL 1024
#define DHEAD  64
#define DFF    4096
#define BATCH  4
#define SEQ    1024
#define MROWS  (BATCH*SEQ)
#define NEG_INF_F (-100000000.0f)

// ---------------------------------------------------------------------------
// Scratch (static device globals; no allocation anywhere)
// ---------------------------------------------------------------------------
__device__ float g_x[MROWS*DMODEL];
__device__ float g_y[MROWS*DMODEL];
__device__ __half g_xh[MROWS*DMODEL];           // activation, single fp16
__device__ __half g_oh[MROWS*DMODEL];           // attention out, single fp16
__device__ __half g_hh[MROWS*DFF];              // ffn hidden, single fp16
// attention operands: all single fp16
__device__ __half g_qh[MROWS*DMODEL];
__device__ __half g_kh[MROWS*DMODEL];
__device__ __half g_vh[MROWS*DMODEL];
// weights: single fp16 (transposed)
__device__ __half g_wqkv[3*DMODEL*DMODEL];
__device__ __half g_wo[DMODEL*DMODEL];
__device__ __half g_w1[DMODEL*DFF];
__device__ __half g_w2[DFF*DMODEL];

// ---------------------------------------------------------------------------
// PTX helpers
// ---------------------------------------------------------------------------
__device__ __forceinline__ uint32_t smem_u32(const void* p) {
    uint32_t a;
    asm("{ .reg .u64 t; cvta.to.shared.u64 t, %1; cvt.u32.u64 %0, t; }" : "=r"(a) : "l"(p));
    return a;
}
__device__ __forceinline__ void cp_async16(uint32_t dst, const void* src) {
    asm volatile("cp.async.cg.shared.global [%0], [%1], 16;" :: "r"(dst), "l"(src) : "memory");
}
#define CP_COMMIT() asm volatile("cp.async.commit_group;" ::: "memory")

__device__ __forceinline__ void ldsm_x4(uint32_t& r0, uint32_t& r1, uint32_t& r2,
                                        uint32_t& r3, uint32_t addr) {
    asm volatile("ldmatrix.sync.aligned.m8n8.x4.shared.b16 {%0,%1,%2,%3}, [%4];"
                 : "=r"(r0), "=r"(r1), "=r"(r2), "=r"(r3) : "r"(addr));
}
__device__ __forceinline__ void ldsm_x4_t(uint32_t& r0, uint32_t& r1, uint32_t& r2,
                                          uint32_t& r3, uint32_t addr) {
    asm volatile("ldmatrix.sync.aligned.m8n8.x4.trans.shared.b16 {%0,%1,%2,%3}, [%4];"
                 : "=r"(r0), "=r"(r1), "=r"(r2), "=r"(r3) : "r"(addr));
}
__device__ __forceinline__ void mma_fp16(float* c, const uint32_t* a, const uint32_t* b) {
    asm volatile(
        "mma.sync.aligned.m16n8k16.row.col.f32.f16.f16.f32 "
        "{%0,%1,%2,%3}, {%4,%5,%6,%7}, {%8,%9}, {%0,%1,%2,%3};"
        : "+f"(c[0]), "+f"(c[1]), "+f"(c[2]), "+f"(c[3])
        : "r"(a[0]), "r"(a[1]), "r"(a[2]), "r"(a[3]), "r"(b[0]), "r"(b[1]));
}
__device__ __forceinline__ uint32_t pack_h2(float x, float y) {
    __half2 h = __floats2half2_rn(x, y);
    return *(uint32_t*)&h;
}

// Swizzle for 64B-row tiles (GEMM: 32 x b16/row)
__device__ __forceinline__ uint32_t swz(int row, int c) {
    return (uint32_t)(((row >> 1) << 7) |
                      ((((((row & 1) << 2) | c)) ^ ((row >> 1) & 7)) << 4));
}
// Swizzle for 128B-row tiles (attention: 64 x b16/row)
__device__ __forceinline__ uint32_t swz128(int row, int c) {
    return (uint32_t)((row << 7) | (((c ^ (row & 7))) << 4));
}

// GEMM smem geometry: 128x128 tile, BK=32, 2 tiles (A, B), TRIPLE buffered
#define T_TILE 8192
#define STAGEB (2*T_TILE)            // 16384
#define GSMEM  (3*STAGEB)            // 49152 (x2 CTAs = 96KB/SM)

// Attention smem: Q single (16KB) + K/V single double-buffered (2x16KB) + mask
#define AQ_TILE 16384
#define AKV_STAGE 16384              // K 8KB + V 8KB
#define ATTN_SMEM (AQ_TILE + 2*AKV_STAGE + 512)   // 49664

// ---------------------------------------------------------------------------
// Positional encoding (fp64) + fused fp16 round of the result
// ---------------------------------------------------------------------------
__global__ void posenc_kernel(const float* __restrict__ x, float* __restrict__ out,
                              __half* __restrict__ oh)
{
    int idx = blockIdx.x * blockDim.x + threadIdx.x;
    if (idx >= SEQ * DMODEL) return;
    int d = idx & (DMODEL - 1);
    int s = idx >> 10;
    int t = (d < DMODEL/2) ? d : d - DMODEL/2;
    const double log_inc = log(10000.0) / (double)(DMODEL/2 - 1);
    double arg = (double)s * exp(-(double)t * log_inc);
    float sig = (float)((d < DMODEL/2) ? sin(arg) : cos(arg));
#pragma unroll
    for (int b = 0; b < BATCH; ++b) {
        size_t off = (size_t)b * SEQ * DMODEL + idx;
        float v = x[off] + sig;
        out[off] = v;
        oh[off] = __float2half_rn(v);
    }
}

// ---------------------------------------------------------------------------
// W [K,N] fp32 -> transposed single fp16: wT [N,K]
// ---------------------------------------------------------------------------
__global__ __launch_bounds__(256) void convert_wT_kernel(
    const float* __restrict__ W, __half* __restrict__ wT, int K, int N)
{
    __shared__ float t[32][33];
    int nx = blockIdx.x * 32;
    int ky = blockIdx.y * 32;
    int tx = threadIdx.x, ty = threadIdx.y;   // (32, 8)
#pragma unroll
    for (int i = 0; i < 4; ++i)
        t[ty + 8*i][tx] = W[(size_t)(ky + ty + 8*i) * N + nx + tx];
    __syncthreads();
#pragma unroll
    for (int i = 0; i < 4; ++i)
        wT[(size_t)(nx + ty + 8*i) * K + ky + tx] = __float2half_rn(t[tx][ty + 8*i]);
}

// --- chunk loader: 2 tiles (A, B) x 512 16B chunks / 256 thr = 4 ---
#define LOAD_CHUNK(k0, buf)                                                     \
    {                                                                           \
        _Pragma("unroll")                                                       \
        for (int i = 0; i < 4; ++i) {                                           \
            int t = tid + i * 256;                                              \
            int tile = t >> 9;                                                  \
            int w = t & 511;                                                    \
            int row = w >> 2;                                                   \
            int c = w & 3;                                                      \
            const __half* src = tile ? B : A;                                   \
            int gr = (tile ? n0 : m0) + row;                                    \
            cp_async16((buf) + (uint32_t)tile * T_TILE + swz(row, c),           \
                       src + (size_t)gr * K + (k0) + c * 8);                    \
        }                                                                       \
        CP_COMMIT();                                                            \
    }

// --- MMA body (single-pass fp16: A*B), 8 warps each 32x64 ---
#define MMA_BODY(buf)                                                            \
    {                                                                            \
        const uint32_t Aa = buf;                                                 \
        const uint32_t Bb = buf + T_TILE;                                        \
        _Pragma("unroll")                                                        \
        for (int kk = 0; kk < 2; ++kk) {                                         \
            uint32_t a_f[2][4];                                                  \
            _Pragma("unroll")                                                    \
            for (int mi = 0; mi < 2; ++mi) {                                     \
                uint32_t off = swz(a_r + mi * 16, kk * 2 + a_h);                 \
                ldsm_x4(a_f[mi][0], a_f[mi][1], a_f[mi][2], a_f[mi][3], Aa + off); \
            }                                                                    \
            uint32_t bf[8][2];                                                   \
            _Pragma("unroll")                                                    \
            for (int nt = 0; nt < 4; ++nt) {                                     \
                uint32_t off = swz(b_r + nt * 16, kk * 2 + b_h);                 \
                uint32_t q0, q1, q2, q3;                                         \
                ldsm_x4(q0, q1, q2, q3, Bb + off);                               \
                bf[nt*2][0] = q0; bf[nt*2][1] = q1;                              \
                bf[nt*2+1][0] = q2; bf[nt*2+1][1] = q3;                          \
            }                                                                    \
            _Pragma("unroll")                                                    \
            for (int mi = 0; mi < 2; ++mi)                                       \
                _Pragma("unroll")                                                \
                for (int ni = 0; ni < 8; ++ni)                                   \
                    mma_fp16(acc[mi][ni], a_f[mi], bf[ni]);                      \
        }                                                                        \
    }

// --- 3-stage K-loop, single barrier per iteration ---
#define K_LOOP()                                                                 \
    LOAD_CHUNK(0, sb);                                                           \
    LOAD_CHUNK(32, sb + STAGEB);                                                 \
    for (int ch = 0; ch < nch; ++ch) {                                           \
        if (ch + 1 < nch) {                                                      \
            asm volatile("cp.async.wait_group 1;" ::: "memory");                 \
        } else {                                                                 \
            asm volatile("cp.async.wait_group 0;" ::: "memory");                 \
        }                                                                        \
        __syncthreads();                                                         \
        if (ch + 2 < nch) {                                                      \
            LOAD_CHUNK((ch + 2) * 32, sb + (uint32_t)((ch + 2) % 3) * STAGEB);   \
        }                                                                        \
        MMA_BODY(sb + (uint32_t)(ch % 3) * STAGEB)                               \
    }

// ---------------------------------------------------------------------------
// fp16 single-pass GEMM (Wo / FF1 / FF2): 128x128 tile, 256 thr, 2 CTA/SM.
// outmode 0: fp32 C. outmode 1: single fp16 Ch.
// ---------------------------------------------------------------------------
__global__ __launch_bounds__(256, 2) void mma_gemm_kernel(
    const __half* __restrict__ A, const __half* __restrict__ B,
    const float* __restrict__ bias, float* __restrict__ C,
    __half* __restrict__ Ch,
    int M, int N, int K, float alpha, int relu, int outmode)
{
    extern __shared__ char smem[];
    const uint32_t sb = smem_u32(smem);
    const int tid = threadIdx.x;
    const int wid = tid >> 5, lane = tid & 31;
    const int m0 = blockIdx.y * 128, n0 = blockIdx.x * 128;
    const int wm = (wid & 3) * 32;
    const int wn = (wid >> 2) * 64;

    float acc[2][8][4];
#pragma unroll
    for (int mi = 0; mi < 2; ++mi)
#pragma unroll
        for (int ni = 0; ni < 8; ++ni)
#pragma unroll
            for (int r = 0; r < 4; ++r) acc[mi][ni][r] = 0.0f;

    const int nch = K >> 5;
    const int a_r = wm + (lane & 15);
    const int a_h = lane >> 4;
    const int b_r = wn + ((lane >> 4) << 3) + (lane & 7);
    const int b_h = (lane >> 3) & 1;

    K_LOOP()

    const int grp = lane >> 2, qid = lane & 3;
#pragma unroll
    for (int mi = 0; mi < 2; ++mi) {
        const int row0 = m0 + wm + mi * 16 + grp;
#pragma unroll
        for (int ni = 0; ni < 8; ++ni) {
            const int col = n0 + wn + ni * 8 + qid * 2;
            float2 b2 = *(const float2*)(bias + col);
            float2 u, v;
            u.x = (acc[mi][ni][0] + b2.x) * alpha;
            u.y = (acc[mi][ni][1] + b2.y) * alpha;
            v.x = (acc[mi][ni][2] + b2.x) * alpha;
            v.y = (acc[mi][ni][3] + b2.y) * alpha;
            if (relu) {
                u.x = fmaxf(u.x, 0.f); u.y = fmaxf(u.y, 0.f);
                v.x = fmaxf(v.x, 0.f); v.y = fmaxf(v.y, 0.f);
            }
            if (outmode == 0) {
                *(float2*)(C + (size_t)row0 * N + col) = u;
                *(float2*)(C + (size_t)(row0 + 8) * N + col) = v;
            } else {
                *(uint32_t*)(Ch + (size_t)row0 * N + col) = pack_h2(u.x, u.y);
                *(uint32_t*)(Ch + (size_t)(row0 + 8) * N + col) = pack_h2(v.x, v.y);
            }
        }
    }
}

// ---------------------------------------------------------------------------
// Batched QKV GEMM (fp16 single-pass): B packed [3072, 1024]. grid (24, 32).
// Epilogue: all outputs single fp16; Q scaled by qscale.
// ---------------------------------------------------------------------------
__global__ __launch_bounds__(256, 2) void mma_gemm_qkv_kernel(
    const __half* __restrict__ A, const __half* __restrict__ B,
    const float* __restrict__ bq, const float* __restrict__ bk,
    const float* __restrict__ bv,
    __half* __restrict__ Qh, __half* __restrict__ Kh, __half* __restrict__ Vh,
    float qscale)
{
    extern __shared__ char smem[];
    const uint32_t sb = smem_u32(smem);
    const int tid = threadIdx.x;
    const int wid = tid >> 5, lane = tid & 31;
    const int m0 = blockIdx.y * 128, n0 = blockIdx.x * 128;
    const int K = DMODEL;
    const int wm = (wid & 3) * 32;
    const int wn = (wid >> 2) * 64;

    float acc[2][8][4];
#pragma unroll
    for (int mi = 0; mi < 2; ++mi)
#pragma unroll
        for (int ni = 0; ni < 8; ++ni)
#pragma unroll
            for (int r = 0; r < 4; ++r) acc[mi][ni][r] = 0.0f;

    const int nch = K >> 5;
    const int a_r = wm + (lane & 15);
    const int a_h = lane >> 4;
    const int b_r = wn + ((lane >> 4) << 3) + (lane & 7);
    const int b_h = (lane >> 3) & 1;

    K_LOOP()

    const int mid = n0 >> 10;
    const float* bsel = (mid == 0) ? bq : (mid == 1) ? bk : bv;
    __half* osel = (mid == 0) ? Qh : (mid == 1) ? Kh : Vh;
    const float asel = (mid == 0) ? qscale : 1.0f;
    const int cb = mid << 10;

    const int grp = lane >> 2, qid = lane & 3;
#pragma unroll
    for (int mi = 0; mi < 2; ++mi) {
        const int row0 = m0 + wm + mi * 16 + grp;
#pragma unroll
        for (int ni = 0; ni < 8; ++ni) {
            const int col = n0 + wn + ni * 8 + qid * 2 - cb;
            float2 b2 = *(const float2*)(bsel + col);
            *(uint32_t*)(osel + (size_t)row0 * DMODEL + col) =
                pack_h2((acc[mi][ni][0] + b2.x) * asel, (acc[mi][ni][1] + b2.y) * asel);
            *(uint32_t*)(osel + (size_t)(row0 + 8) * DMODEL + col) =
                pack_h2((acc[mi][ni][2] + b2.x) * asel, (acc[mi][ni][3] + b2.y) * asel);
        }
    }
}

// ---------------------------------------------------------------------------
// MMA flash attention (all single fp16): Q, K, V, P single-pass.
// 8 warps, 128 q-rows per CTA, double-buffered K/V, 2 CTAs/SM.
// ---------------------------------------------------------------------------
__global__ __launch_bounds__(256, 2) void attn_mma_kernel(
    const __half* __restrict__ Qg,
    const __half* __restrict__ Kg, const __half* __restrict__ Vg,
    const float* __restrict__ mask,
    __half* __restrict__ Oh)
{
    extern __shared__ char sm[];
    const uint32_t sb = smem_u32(sm);
    const uint32_t Qt = sb;
    const uint32_t KV0 = sb + AQ_TILE;
    float* msk = (float*)(sm + AQ_TILE + 2 * AKV_STAGE);

    const int tid = threadIdx.x, wid = tid >> 5, lane = tid & 31;
    const int b = blockIdx.z, h = blockIdx.y, q0 = blockIdx.x * 128;
    const int g = lane >> 2, qd = lane & 3;

    // Load Q tile: 1024 chunks / 256 = 4 each
#pragma unroll
    for (int i = 0; i < 4; ++i) {
        int t = tid + i * 256;
        int r = t >> 3, c = t & 7;
        const __half* src = Qg
            + (size_t)(b * SEQ + q0 + r) * DMODEL + h * DHEAD + c * 8;
        cp_async16(Qt + swz128(r, c), src);
    }
    CP_COMMIT();

    float m_i[2] = {-INFINITY, -INFINITY}, l_i[2] = {0.f, 0.f};
    float oacc[8][4];
#pragma unroll
    for (int ni = 0; ni < 8; ++ni)
#pragma unroll
        for (int r = 0; r < 4; ++r) oacc[ni][r] = 0.f;

    const int a_r = wid * 16 + (lane & 15);
    const int a_c = lane >> 4;
    const int b_r = (lane & 7) + ((lane >> 4) << 3);
    const int b_c = (lane >> 3) & 1;
    const int v_ro = ((lane >> 3) & 1) * 8 + (lane & 7);
    const int v_co = lane >> 4;

    // K/V stage loader: 2 tiles x 512 chunks / 256 = 4 each
#define LOAD_KV(kt, stg)                                                        \
    {                                                                           \
        const uint32_t sbase = KV0 + (uint32_t)(stg) * AKV_STAGE;               \
        _Pragma("unroll")                                                       \
        for (int i = 0; i < 4; ++i) {                                           \
            int t = tid + i * 256;                                              \
            int tt = t >> 9;                                                    \
            int w = t & 511;                                                    \
            int r = w >> 3, c = w & 7;                                          \
            const __half* src = (tt ? Vg : Kg)                                  \
                + (size_t)(b * SEQ + (kt) + r) * DMODEL + h * DHEAD + c * 8;    \
            cp_async16(sbase + (uint32_t)tt * 8192 + swz128(r, c), src);        \
        }                                                                       \
        if (tid < 64)                                                           \
            msk[(stg) * 64 + tid] =                                             \
                (1.0f - mask[b * SEQ + (kt) + tid]) * NEG_INF_F;                \
        CP_COMMIT();                                                            \
    }

    LOAD_KV(0, 0);

    for (int kt = 0; kt < SEQ; kt += 64) {
        const int stg = (kt >> 6) & 1;
        const uint32_t Kt = KV0 + (uint32_t)stg * AKV_STAGE;
        const uint32_t Vt = Kt + 8192;
        const float* mrow = msk + stg * 64;

        if (kt + 64 < SEQ) {
            LOAD_KV(kt + 64, stg ^ 1);
            asm volatile("cp.async.wait_group 1;" ::: "memory");
        } else {
            asm volatile("cp.async.wait_group 0;" ::: "memory");
        }
        __syncthreads();

        // ---- S = Q K^T : single-pass fp16 ----
        float sacc[8][4];
#pragma unroll
        for (int ni = 0; ni < 8; ++ni)
#pragma unroll
            for (int r = 0; r < 4; ++r) sacc[ni][r] = 0.f;

#pragma unroll
        for (int kk = 0; kk < 4; ++kk) {
            uint32_t qf[4];
            uint32_t offA = swz128(a_r, kk * 2 + a_c);
            ldsm_x4(qf[0], qf[1], qf[2], qf[3], Qt + offA);
#pragma unroll
            for (int nt = 0; nt < 4; ++nt) {
                uint32_t off = swz128(b_r + nt * 16, kk * 2 + b_c);
                uint32_t f[4];
                ldsm_x4(f[0], f[1], f[2], f[3], Kt + off);
                mma_fp16(sacc[nt*2],   qf, f);
                mma_fp16(sacc[nt*2+1], qf, f + 2);
            }
        }

        // additive mask
#pragma unroll
        for (int ni = 0; ni < 8; ++ni) {
            float ma = mrow[ni * 8 + qd * 2], mb = mrow[ni * 8 + qd * 2 + 1];
            sacc[ni][0] += ma; sacc[ni][1] += mb;
            sacc[ni][2] += ma; sacc[ni][3] += mb;
        }

        // ---- streaming softmax ----
#pragma unroll
        for (int hf = 0; hf < 2; ++hf) {
            float mx = -INFINITY;
#pragma unroll
            for (int ni = 0; ni < 8; ++ni)
                mx = fmaxf(mx, fmaxf(sacc[ni][hf*2], sacc[ni][hf*2+1]));
            mx = fmaxf(mx, __shfl_xor_sync(0xffffffffu, mx, 1));
            mx = fmaxf(mx, __shfl_xor_sync(0xffffffffu, mx, 2));
            float mnew = fmaxf(m_i[hf], mx);
            float rs = 0.f;
#pragma unroll
            for (int ni = 0; ni < 8; ++ni) {
                float e0 = __expf(sacc[ni][hf*2]   - mnew);
                float e1 = __expf(sacc[ni][hf*2+1] - mnew);
                sacc[ni][hf*2] = e0; sacc[ni][hf*2+1] = e1;
                rs += e0 + e1;
            }
            rs += __shfl_xor_sync(0xffffffffu, rs, 1);
            rs += __shfl_xor_sync(0xffffffffu, rs, 2);
            float sc = __expf(m_i[hf] - mnew);
            l_i[hf] = l_i[hf] * sc + rs;
            m_i[hf] = mnew;
#pragma unroll
            for (int ni = 0; ni < 8; ++ni) {
                oacc[ni][hf*2]   *= sc;
                oacc[ni][hf*2+1] *= sc;
            }
        }

        // ---- O += P V : single-pass fp16 ----
#pragma unroll
        for (int kk = 0; kk < 4; ++kk) {
            uint32_t ph[4];
            ph[0] = pack_h2(sacc[2*kk][0],   sacc[2*kk][1]);
            ph[1] = pack_h2(sacc[2*kk][2],   sacc[2*kk][3]);
            ph[2] = pack_h2(sacc[2*kk+1][0], sacc[2*kk+1][1]);
            ph[3] = pack_h2(sacc[2*kk+1][2], sacc[2*kk+1][3]);
#pragma unroll
            for (int nt = 0; nt < 4; ++nt) {
                uint32_t off = swz128(kk * 16 + v_ro, nt * 2 + v_co);
                uint32_t f[4];
                ldsm_x4_t(f[0], f[1], f[2], f[3], Vt + off);
                mma_fp16(oacc[nt*2],   ph, f);
                mma_fp16(oacc[nt*2+1], ph, f + 2);
            }
        }
        __syncthreads();
    }

    // ---- O /= l; write single fp16 ----
#pragma unroll
    for (int hf = 0; hf < 2; ++hf) {
        float inv = 1.0f / l_i[hf];
        int row = q0 + wid * 16 + g + hf * 8;
#pragma unroll
        for (int ni = 0; ni < 8; ++ni) {
            float x0 = oacc[ni][hf*2] * inv, x1 = oacc[ni][hf*2+1] * inv;
            size_t off = (size_t)(b * SEQ + row) * DMODEL + h * DHEAD + ni * 8 + qd * 2;
            *(uint32_t*)(Oh + off) = pack_h2(x0, x1);
        }
    }
#undef LOAD_KV
}

// ---------------------------------------------------------------------------
// Fused residual + LayerNorm: warp-per-row; writes fp32 out + single fp16 xh.
// ---------------------------------------------------------------------------
__global__ __launch_bounds__(256) void add_ln_kernel(
    const float* __restrict__ x, const float* __restrict__ y,
    const float* __restrict__ g, const float* __restrict__ beta,
    float* __restrict__ out, __half* __restrict__ oh)
{
    const int warp = threadIdx.x >> 5, lane = threadIdx.x & 31;
    const int row = blockIdx.x * 8 + warp;
    const size_t base = (size_t)row * DMODEL;

    float v[32];
    float s = 0.f;
#pragma unroll
    for (int i = 0; i < 8; ++i) {
        int col = i * 128 + lane * 4;
        float4 xv = *(const float4*)(x + base + col);
        float4 yv = *(const float4*)(y + base + col);
        v[4*i+0] = xv.x + yv.x;
        v[4*i+1] = xv.y + yv.y;
        v[4*i+2] = xv.z + yv.z;
        v[4*i+3] = xv.w + yv.w;
        s += v[4*i+0] + v[4*i+1] + v[4*i+2] + v[4*i+3];
    }
#pragma unroll
    for (int o = 16; o > 0; o >>= 1) s += __shfl_xor_sync(0xffffffffu, s, o);
    const float mean = s * (1.0f / DMODEL);

    float s2 = 0.f;
#pragma unroll
    for (int i = 0; i < 32; ++i) {
        float d = v[i] - mean;
        s2 += d * d;
    }
#pragma unroll
    for (int o = 16; o > 0; o >>= 1) s2 += __shfl_xor_sync(0xffffffffu, s2, o);
    const float rstd = rsqrtf(s2 * (1.0f / DMODEL) + 1e-5f);

#pragma unroll
    for (int i = 0; i < 8; ++i) {
        int col = i * 128 + lane * 4;
        float4 gv = *(const float4*)(g + col);
        float4 bv = *(const float4*)(beta + col);
        float4 o4;
        o4.x = (v[4*i+0] - mean) * rstd * gv.x + bv.x;
        o4.y = (v[4*i+1] - mean) * rstd * gv.y + bv.y;
        o4.z = (v[4*i+2] - mean) * rstd * gv.z + bv.z;
        o4.w = (v[4*i+3] - mean) * rstd * gv.w + bv.w;
        *(float4*)(out + base + col) = o4;
        *(uint32_t*)(oh + base + col)     = pack_h2(o4.x, o4.y);
        *(uint32_t*)(oh + base + col + 2) = pack_h2(o4.z, o4.w);
    }
}

// ---------------------------------------------------------------------------
// Launch (dual-stream: main = stream 0, s2 = weight converts)
// ---------------------------------------------------------------------------
extern "C" void kernel_launch(void* const* d_in, const int* in_sizes, int n_in,
                              void* d_out, int out_size)
{
    (void)in_sizes; (void)n_in; (void)out_size;

    const float* x    = (const float*)d_in[0];
    const float* mask = (const float*)d_in[1];
    const float* Wq   = (const float*)d_in[2];
    const float* bq   = (const float*)d_in[3];
    const float* Wk   = (const float*)d_in[4];
    const float* bk   = (const float*)d_in[5];
    const float* Wv   = (const float*)d_in[6];
    const float* bv   = (const float*)d_in[7];
    const float* Wo   = (const float*)d_in[8];
    const float* bo   = (const float*)d_in[9];
    const float* W1   = (const float*)d_in[10];
    const float* b1   = (const float*)d_in[11];
    const float* W2   = (const float*)d_in[12];
    const float* b2   = (const float*)d_in[13];
    const float* lng  = (const float*)d_in[14];
    const float* lnb  = (const float*)d_in[15];
    float* out = (float*)d_out;

    float *gx, *gy;
    __half *xh, *oh, *hh, *qh, *kh, *vh;
    __half *wqkv, *wo_, *w1_, *w2_;
    cudaGetSymbolAddress((void**)&gx,  g_x);
    cudaGetSymbolAddress((void**)&gy,  g_y);
    cudaGetSymbolAddress((void**)&xh,  g_xh);
    cudaGetSymbolAddress((void**)&oh,  g_oh);
    cudaGetSymbolAddress((void**)&hh,  g_hh);
    cudaGetSymbolAddress((void**)&qh,  g_qh);
    cudaGetSymbolAddress((void**)&kh,  g_kh);
    cudaGetSymbolAddress((void**)&vh,  g_vh);
    cudaGetSymbolAddress((void**)&wqkv, g_wqkv);
    cudaGetSymbolAddress((void**)&wo_, g_wo);
    cudaGetSymbolAddress((void**)&w1_, g_w1);
    cudaGetSymbolAddress((void**)&w2_, g_w2);

    static cudaStream_t s2 = nullptr;
    static cudaEvent_t evpool[64];
    static int attr_set = 0;
    if (!attr_set) {
        cudaFuncSetAttribute(mma_gemm_kernel,
                             cudaFuncAttributeMaxDynamicSharedMemorySize, GSMEM);
        cudaFuncSetAttribute(mma_gemm_qkv_kernel,
                             cudaFuncAttributeMaxDynamicSharedMemorySize, GSMEM);
        cudaFuncSetAttribute(attn_mma_kernel,
                             cudaFuncAttributeMaxDynamicSharedMemorySize, ATTN_SMEM);
        cudaStreamCreateWithFlags(&s2, cudaStreamNonBlocking);
        for (int i = 0; i < 64; ++i)
            cudaEventCreateWithFlags(&evpool[i], cudaEventDisableTiming);
        attr_set = 1;
    }
    int evn = 0;
#define EV() (evpool[evn++])

    const float qscale = 0.125f;
    dim3 gQKV(3 * DMODEL / 128, MROWS / 128);  // (24, 32)
    dim3 gProj(DMODEL / 128, MROWS / 128);     // (8, 32)
    dim3 gFF1(DFF / 128, MROWS / 128);         // (32, 32)
    dim3 gAttn(SEQ / 128, NHEAD, BATCH);       // (8, 16, 4)
    dim3 tT(32, 8);

    cudaEvent_t eFork = EV();
    cudaEventRecord(eFork, 0);
    cudaStreamWaitEvent(s2, eFork, 0);

    posenc_kernel<<<(SEQ * DMODEL + 255) / 256, 256>>>(x, gx, xh);

    cudaEvent_t e_qkv_done = nullptr, e_wo_done = nullptr,
                e_ff1_done = nullptr, e_ff2_done = nullptr;

    for (int l = 0; l < NLAYER; ++l) {
        const float* wq = Wq + (size_t)l * DMODEL * DMODEL;
        const float* wk = Wk + (size_t)l * DMODEL * DMODEL;
        const float* wv = Wv + (size_t)l * DMODEL * DMODEL;
        const float* wo = Wo + (size_t)l * DMODEL * DMODEL;

        if (e_qkv_done) cudaStreamWaitEvent(s2, e_qkv_done, 0);
        convert_wT_kernel<<<dim3(32,32), tT, 0, s2>>>(wq, wqkv,               DMODEL, DMODEL);
        convert_wT_kernel<<<dim3(32,32), tT, 0, s2>>>(wk, wqkv + 1024*1024,   DMODEL, DMODEL);
        convert_wT_kernel<<<dim3(32,32), tT, 0, s2>>>(wv, wqkv + 2*1024*1024, DMODEL, DMODEL);
        cudaEvent_t e_sqkv = EV(); cudaEventRecord(e_sqkv, s2);

        if (e_wo_done) cudaStreamWaitEvent(s2, e_wo_done, 0);
        convert_wT_kernel<<<dim3(32,32), tT, 0, s2>>>(wo, wo_, DMODEL, DMODEL);
        cudaEvent_t e_so = EV(); cudaEventRecord(e_so, s2);

        if (e_ff1_done) cudaStreamWaitEvent(s2, e_ff1_done, 0);
        convert_wT_kernel<<<dim3(DFF/32, DMODEL/32), tT, 0, s2>>>(
            W1 + (size_t)l * DMODEL * DFF, w1_, DMODEL, DFF);
        cudaEvent_t e_s1 = EV(); cudaEventRecord(e_s1, s2);

        if (e_ff2_done) cudaStreamWaitEvent(s2, e_ff2_done, 0);
        convert_wT_kernel<<<dim3(DMODEL/32, DFF/32), tT, 0, s2>>>(
            W2 + (size_t)l * DFF * DMODEL, w2_, DFF, DMODEL);
        cudaEvent_t e_s2e = EV(); cudaEventRecord(e_s2e, s2);

        cudaStreamWaitEvent(0, e_sqkv, 0);
        mma_gemm_qkv_kernel<<<gQKV, 256, GSMEM>>>(xh, wqkv,
            bq + (size_t)l * DMODEL, bk + (size_t)l * DMODEL, bv + (size_t)l * DMODEL,
            qh, kh, vh, qscale);
        e_qkv_done = EV(); cudaEventRecord(e_qkv_done, 0);

        attn_mma_kernel<<<gAttn, 256, ATTN_SMEM>>>(qh, kh, vh, mask, oh);

        cudaStreamWaitEvent(0, e_so, 0);
        mma_gemm_kernel<<<gProj, 256, GSMEM>>>(oh, wo_,
            bo + (size_t)l * DMODEL, gy, nullptr,
            MROWS, DMODEL, DMODEL, 1.0f, 0, 0);
        e_wo_done = EV(); cudaEventRecord(e_wo_done, 0);

        add_ln_kernel<<<MROWS / 8, 256>>>(gx, gy,
            lng + (size_t)(2 * l) * DMODEL, lnb + (size_t)(2 * l) * DMODEL,
            gx, xh);

        cudaStreamWaitEvent(0, e_s1, 0);
        mma_gemm_kernel<<<gFF1, 256, GSMEM>>>(xh, w1_,
            b1 + (size_t)l * DFF, nullptr, hh,
            MROWS, DFF, DMODEL, 1.0f, 1, 1);
        e_ff1_done = EV(); cudaEventRecord(e_ff1_done, 0);

        cudaStreamWaitEvent(0, e_s2e, 0);
        mma_gemm_kernel<<<gProj, 256, GSMEM>>>(hh, w2_,
            b2 + (size_t)l * DMODEL, gy, nullptr,
            MROWS, DMODEL, DFF, 1.0f, 0, 0);
        e_ff2_done = EV(); cudaEventRecord(e_ff2_done, 0);

        float* ln_out = (l == NLAYER - 1) ? out : gx;
        add_ln_kernel<<<MROWS / 8, 256>>>(gx, gy,
            lng + (size_t)(2 * l + 1) * DMODEL, lnb + (size_t)(2 * l + 1) * DMODEL,
            ln_out, xh);
    }

    cudaEvent_t eJoin = EV();
    cudaEventRecord(eJoin, s2);
    cudaStreamWaitEvent(0, eJoin, 0);
#undef EV
}